// round 3
// baseline (speedup 1.0000x reference)
#include <cuda_runtime.h>
#include <math.h>

#define NN     4096
#define BB     8
#define NPG    512
#define KK     30
#define NPAIR  15
#define NBASIS 32
#define EDIM   35      // NBASIS + 3
#define HH     256
#define X2H    512
#define TT     128
#define LL     5
#define RADIUS 1.5f

// ---------------- static scratch (no allocations allowed) ----------------
__device__ __align__(16) float d_tfeat[BB * TT];
__device__ __align__(16) float d_tproj[LL * BB * HH];
__device__ __align__(16) float d_h[NN * HH];
__device__ __align__(16) float d_aggr[NN * X2H];
__device__ __align__(16) float d_z1[NN * HH];
__device__ __align__(16) float d_z[NN * HH];
// pair-interleaved edge attrs: [(i*15+p)*36 + m] -> {e(2p,m), e(2p+1,m)}
__device__ __align__(16) float d_epair[NN * NPAIR * 36 * 2];
__device__ int   d_nbr[NN * KK];
__device__ int   d_cnt[NN];
__device__ __align__(16) float d_sumz[BB * HH];
__device__ __align__(16) float d_sumq[BB * HH];

__device__ __forceinline__ float silu_f(float v) { return v / (1.f + expf(-v)); }

// ---------------- packed fp32x2 helpers (Blackwell FFMA2) ----------------
__device__ __forceinline__ unsigned long long pack2(float lo, float hi) {
    unsigned long long r;
    asm("mov.b64 %0, {%1, %2};" : "=l"(r) : "f"(lo), "f"(hi));
    return r;
}
__device__ __forceinline__ void unpack2(unsigned long long v, float& lo, float& hi) {
    asm("mov.b64 {%0, %1}, %2;" : "=f"(lo), "=f"(hi) : "l"(v));
}
__device__ __forceinline__ unsigned long long ffma2(unsigned long long a,
                                                    unsigned long long b,
                                                    unsigned long long c) {
    unsigned long long d;
    asm("fma.rn.f32x2 %0, %1, %2, %3;" : "=l"(d) : "l"(a), "l"(b), "l"(c));
    return d;
}

// ---------------- time embedding: GFP + Linear + SiLU -> t_feat [B,T] ----
__global__ void k_temb(const float* __restrict__ tin, const float* __restrict__ wgfp,
                       const float* __restrict__ wt, const float* __restrict__ bt) {
    __shared__ float ss[64], sc[64];
    int t = threadIdx.x; // 128 threads
    for (int b = 0; b < BB; b++) {
        if (t < 64) {
            float xp = 6.283185307179586f * tin[b] * wgfp[t];
            ss[t] = sinf(xp);
            sc[t] = cosf(xp);
        }
        __syncthreads();
        float acc = bt[t];
        #pragma unroll 8
        for (int h = 0; h < 64; h++) {
            acc = fmaf(ss[h], wt[h * TT + t], acc);
            acc = fmaf(sc[h], wt[(64 + h) * TT + t], acc);
        }
        d_tfeat[b * TT + t] = silu_f(acc);
        __syncthreads();
    }
}

// ---------------- per-layer time projection -------------------------------
__global__ void k_tproj(const float* __restrict__ Wt, const float* __restrict__ bt) {
    int l = blockIdx.x / BB, b = blockIdx.x % BB;
    int c = threadIdx.x; // 256
    __shared__ float tf[TT];
    if (c < TT) tf[c] = d_tfeat[b * TT + c];
    __syncthreads();
    float acc = bt[l * HH + c];
    const float* w = Wt + (size_t)l * TT * HH;
    #pragma unroll 8
    for (int k = 0; k < TT; k++) acc = fmaf(tf[k], w[k * HH + c], acc);
    d_tproj[(l * BB + b) * HH + c] = acc;
}

// ---------------- h0 = coords @ W_in + b_in -------------------------------
__global__ void k_hin(const float* __restrict__ coords, const float* __restrict__ Win,
                      const float* __restrict__ bin) {
    int i = blockIdx.x;
    int c = threadIdx.x;
    float x0 = coords[i * 3 + 0], x1 = coords[i * 3 + 1], x2 = coords[i * 3 + 2];
    float v = fmaf(x0, Win[c], fmaf(x1, Win[HH + c], fmaf(x2, Win[2 * HH + c], bin[c])));
    d_h[(size_t)i * HH + c] = v;
}

// ---------------- radius graph: K nearest within R, warp per node ---------
__global__ void __launch_bounds__(128) k_nbr(const float* __restrict__ coords) {
    __shared__ float sx[NPG], sy[NPG], sz[NPG];
    __shared__ float sd[4][NPG];
    int t = threadIdx.x;
    int base = blockIdx.x * 4;
    int g = base >> 9;
    int goff = g << 9;
    for (int j = t; j < NPG; j += 128) {
        sx[j] = coords[(goff + j) * 3 + 0];
        sy[j] = coords[(goff + j) * 3 + 1];
        sz[j] = coords[(goff + j) * 3 + 2];
    }
    __syncthreads();
    int w = t >> 5, lane = t & 31;
    int il = (base & 511) + w;
    int ig = goff + il;
    float xi = sx[il], yi = sy[il], zi = sz[il];
    float sqi = xi * xi + yi * yi + zi * zi;
    for (int j = lane; j < NPG; j += 32) {
        float xj = sx[j], yj = sy[j], zj = sz[j];
        float dot = xi * xj + yi * yj + zi * zj;
        float sqj = xj * xj + yj * yj + zj * zj;
        float d2 = sqi + sqj - 2.f * dot;
        float d = sqrtf(fmaxf(d2, 1e-12f));
        sd[w][j] = (j != il && d < RADIUS) ? d : INFINITY;
    }
    __syncwarp();
    int cc = 0;
    for (int k = 0; k < KK; k++) {
        float best = INFINITY;
        int bi = -1;
        for (int j = lane; j < NPG; j += 32) {
            float v = sd[w][j];
            if (v < best) { best = v; bi = j; }
        }
        #pragma unroll
        for (int off = 16; off; off >>= 1) {
            float ov = __shfl_down_sync(0xffffffffu, best, off);
            int oi = __shfl_down_sync(0xffffffffu, bi, off);
            if (ov < best || (ov == best && (unsigned)oi < (unsigned)bi)) { best = ov; bi = oi; }
        }
        best = __shfl_sync(0xffffffffu, best, 0);
        bi = __shfl_sync(0xffffffffu, bi, 0);
        if (!(best < INFINITY)) break;
        if (lane == 0) {
            d_nbr[ig * KK + k] = goff + bi;
            sd[w][bi] = INFINITY;
        }
        cc = k + 1;
        __syncwarp();
    }
    if (lane == 0) d_cnt[ig] = cc;
}

// ---------------- edge attributes (pair-interleaved layout) ---------------
__global__ void k_eattr(const float* __restrict__ coords) {
    int e = blockIdx.x * blockDim.x + threadIdx.x;
    if (e >= NN * KK) return;
    int i = e / KK, k = e % KK;
    float* o = d_epair + (size_t)(i * NPAIR + (k >> 1)) * 72 + (k & 1);
    if (k >= d_cnt[i]) {
        #pragma unroll
        for (int m = 0; m < 36; m++) o[2 * m] = 0.f;
        return;
    }
    int s = d_nbr[e];
    float ex = coords[s * 3 + 0] - coords[i * 3 + 0];
    float ey = coords[s * 3 + 1] - coords[i * 3 + 1];
    float ez = coords[s * 3 + 2] - coords[i * 3 + 2];
    float d2 = ex * ex + ey * ey + ez * ez;
    float el = sqrtf(fmaxf(d2, 1e-12f));
    float inv = 1.f / el;
    const float step = RADIUS / 33.f;
    const float istep = 33.f / RADIUS;
    #pragma unroll
    for (int m = 0; m < NBASIS; m++) {
        float dd = (el - (float)(m + 1) * step) * istep;
        o[2 * m] = expf(-dd * dd) * (1.f / 1.12f);
    }
    o[2 * 32] = ex * inv;
    o[2 * 33] = ey * inv;
    o[2 * 34] = ez * inv;
    o[2 * 35] = 0.f;
}

// ---------------- GINE message + aggregate (FFMA2, edge pairs) ------------
// One block per node, 512 threads (one column each). Columns >=256 use the
// per-graph-constant tproj value (no gather).
__global__ void __launch_bounds__(512) k_edge(const float* __restrict__ We,
                                              const float* __restrict__ be, int l) {
    int i = blockIdx.x;
    int g = i >> 9;
    int t = threadIdx.x;
    __shared__ __align__(16) float2 sea[NPAIR * 36];
    __shared__ int snbr[KK];
    int count = d_cnt[i];
    // stage pair-interleaved edge attrs (contiguous copy)
    const float2* src2 = (const float2*)(d_epair + (size_t)i * NPAIR * 72);
    for (int idx = t; idx < NPAIR * 36; idx += 512) sea[idx] = src2[idx];
    if (t < KK) snbr[t] = (t < count) ? d_nbr[i * KK + t] : i;
    // weights: duplicated packed pairs, register resident
    unsigned long long w[36];
    #pragma unroll
    for (int m = 0; m < EDIM; m++) {
        float wv = We[m * X2H + t];
        w[m] = pack2(wv, wv);
    }
    w[35] = 0ull;
    float bv = be[t];
    unsigned long long b2 = pack2(bv, bv);
    float tp = (t >= HH) ? d_tproj[(l * BB + g) * HH + (t - HH)] : 0.f;
    __syncthreads();

    float a = 0.f;
    int npair = (count + 1) >> 1;
    for (int p = 0; p < npair; p++) {
        // gather x[src] (only lower half gathers; upper half uses constant tp)
        int k0 = 2 * p, k1 = 2 * p + 1;
        float xs0, xs1;
        if (t < HH) {
            xs0 = d_h[(size_t)snbr[k0] * HH + t];
            xs1 = d_h[(size_t)snbr[k1] * HH + t];
        } else {
            xs0 = tp; xs1 = tp;
        }
        unsigned long long acc = b2;
        const ulonglong2* sp2 = (const ulonglong2*)(sea + p * 36);
        #pragma unroll
        for (int q = 0; q < 18; q++) {
            ulonglong2 e2 = sp2[q];
            acc = ffma2(e2.x, w[2 * q], acc);
            acc = ffma2(e2.y, w[2 * q + 1], acc);
        }
        float m0, m1;
        unpack2(acc, m0, m1);
        a += fmaxf(xs0 + m0, 0.f);
        if (k1 < count) a += fmaxf(xs1 + m1, 0.f);
    }
    d_aggr[(size_t)i * X2H + t] = a;
}

// ---------------- GEMM (FFMA2): 128x64 tile, 256 thr, 8x4 microtile -------
// MODE0: z1 = silu(((1+eps)*[h|tproj] + aggr) @ W1 + b1)   K=512
// MODE1: z  = z1 @ W2 + b2                                  K=256
template <int MODE>
__global__ void __launch_bounds__(256) k_gemm(const float* __restrict__ Bw,
                                              const float* __restrict__ bias,
                                              const float* __restrict__ epsp, int l) {
    const int Kd = (MODE == 0) ? X2H : HH;
    __shared__ __align__(16) float2 As[16][128];  // duplicated pairs
    __shared__ __align__(16) float Bs[16][68];    // padded
    __shared__ float stp[HH];
    int t = threadIdx.x;
    int n0 = blockIdx.x * 64, m0 = blockIdx.y * 128;
    int g = m0 >> 9;
    int ty = t >> 4, tx = t & 15;                 // ty 0..15 (rows*8), tx 0..15 (cols*4)
    float ep = (MODE == 0) ? (1.f + epsp[l]) : 0.f;
    if (MODE == 0 && t < HH) stp[t] = d_tproj[(l * BB + g) * HH + t];

    unsigned long long acc[8][2];
    #pragma unroll
    for (int r = 0; r < 8; r++) { acc[r][0] = 0ull; acc[r][1] = 0ull; }

    for (int k0 = 0; k0 < Kd; k0 += 16) {
        __syncthreads();
        // stage A (2 float4 per thread), duplicated into pairs
        #pragma unroll
        for (int it = 0; it < 2; it++) {
            int idx = t + it * 256;
            int row = idx >> 2, kq = idx & 3;
            int grow = m0 + row;
            int kg = k0 + kq * 4;
            float4 xv;
            if (MODE == 0) {
                float4 ag = *(const float4*)(d_aggr + (size_t)grow * X2H + kg);
                float4 hx;
                if (kg < HH) hx = *(const float4*)(d_h + (size_t)grow * HH + kg);
                else         hx = *(const float4*)(stp + (kg - HH));
                xv.x = fmaf(ep, hx.x, ag.x);
                xv.y = fmaf(ep, hx.y, ag.y);
                xv.z = fmaf(ep, hx.z, ag.z);
                xv.w = fmaf(ep, hx.w, ag.w);
            } else {
                xv = *(const float4*)(d_z1 + (size_t)grow * HH + kg);
            }
            As[kq * 4 + 0][row] = make_float2(xv.x, xv.x);
            As[kq * 4 + 1][row] = make_float2(xv.y, xv.y);
            As[kq * 4 + 2][row] = make_float2(xv.z, xv.z);
            As[kq * 4 + 3][row] = make_float2(xv.w, xv.w);
        }
        // stage B (1 float4 per thread)
        {
            int kr = t >> 4, nc = (t & 15) * 4;
            *(float4*)&Bs[kr][nc] = *(const float4*)(Bw + (size_t)(k0 + kr) * HH + n0 + nc);
        }
        __syncthreads();
        #pragma unroll
        for (int kk = 0; kk < 16; kk++) {
            const ulonglong2* ap = (const ulonglong2*)&As[kk][ty * 8];
            ulonglong2 b2 = *(const ulonglong2*)&Bs[kk][tx * 4];
            #pragma unroll
            for (int ih = 0; ih < 4; ih++) {
                ulonglong2 av = ap[ih];
                acc[2 * ih + 0][0] = ffma2(av.x, b2.x, acc[2 * ih + 0][0]);
                acc[2 * ih + 0][1] = ffma2(av.x, b2.y, acc[2 * ih + 0][1]);
                acc[2 * ih + 1][0] = ffma2(av.y, b2.x, acc[2 * ih + 1][0]);
                acc[2 * ih + 1][1] = ffma2(av.y, b2.y, acc[2 * ih + 1][1]);
            }
        }
    }
    float4 bs4 = *(const float4*)(bias + n0 + tx * 4);
    float* C = (MODE == 0) ? d_z1 : d_z;
    #pragma unroll
    for (int r = 0; r < 8; r++) {
        float v0, v1, v2, v3;
        unpack2(acc[r][0], v0, v1);
        unpack2(acc[r][1], v2, v3);
        v0 += bs4.x; v1 += bs4.y; v2 += bs4.z; v3 += bs4.w;
        if (MODE == 0) { v0 = silu_f(v0); v1 = silu_f(v1); v2 = silu_f(v2); v3 = silu_f(v3); }
        int row = m0 + ty * 8 + r;
        *(float4*)(C + (size_t)row * HH + n0 + tx * 4) = make_float4(v0, v1, v2, v3);
    }
}

// ---------------- GraphNorm stats: sum + sumsq in one pass ----------------
__global__ void k_gstat() {
    int g = blockIdx.x, chunk = blockIdx.y;
    int t = threadIdx.x;
    int cl = t & 31, seg = t >> 5;
    int c = chunk * 32 + cl;
    int base = g * NPG + seg * 64;
    float s = 0.f, s2 = 0.f;
    for (int n = 0; n < 64; n++) {
        float v = d_z[(size_t)(base + n) * HH + c];
        s += v;
        s2 = fmaf(v, v, s2);
    }
    __shared__ float r1[8][32], r2[8][32];
    r1[seg][cl] = s;
    r2[seg][cl] = s2;
    __syncthreads();
    if (seg == 0) {
        float t1 = 0.f, t2 = 0.f;
        #pragma unroll
        for (int q = 0; q < 8; q++) { t1 += r1[q][cl]; t2 += r2[q][cl]; }
        d_sumz[g * HH + c] = t1;
        d_sumq[g * HH + c] = t2;
    }
}

__global__ void k_gfin(const float* __restrict__ gw, const float* __restrict__ gb,
                       const float* __restrict__ gms) {
    int nb = blockIdx.x * 64;
    int g = nb >> 9;
    int c = threadIdx.x;
    float mean = d_sumz[g * HH + c] * (1.f / 512.f);
    float ez2  = d_sumq[g * HH + c] * (1.f / 512.f);
    float mm = mean * gms[c];
    float var = ez2 - 2.f * mm * mean + mm * mm;
    float inv = 1.f / sqrtf(var + 1e-5f);
    float w = gw[c], b = gb[c];
    for (int n = 0; n < 64; n++) {
        size_t id = (size_t)(nb + n) * HH + c;
        float cc = d_z[id] - mm;
        float zn = fmaf(w * cc, inv, b);
        float hv = zn + d_h[id];
        d_h[id] = silu_f(hv);
    }
}

// ---------------- output head: out = h @ W_out + b_out -------------------
__global__ void k_out(const float* __restrict__ Wout, const float* __restrict__ bout,
                      float* __restrict__ out) {
    __shared__ float sw[HH * 3];
    int t = threadIdx.x;
    for (int idx = t; idx < HH * 3; idx += 256) sw[idx] = Wout[idx];
    __syncthreads();
    int w = t >> 5, lane = t & 31;
    int i = blockIdx.x * 8 + w;
    float a0 = 0.f, a1 = 0.f, a2 = 0.f;
    for (int c = lane; c < HH; c += 32) {
        float hv = d_h[(size_t)i * HH + c];
        a0 = fmaf(hv, sw[c * 3 + 0], a0);
        a1 = fmaf(hv, sw[c * 3 + 1], a1);
        a2 = fmaf(hv, sw[c * 3 + 2], a2);
    }
    #pragma unroll
    for (int off = 16; off; off >>= 1) {
        a0 += __shfl_down_sync(0xffffffffu, a0, off);
        a1 += __shfl_down_sync(0xffffffffu, a1, off);
        a2 += __shfl_down_sync(0xffffffffu, a2, off);
    }
    if (lane == 0) {
        out[i * 3 + 0] = a0 + bout[0];
        out[i * 3 + 1] = a1 + bout[1];
        out[i * 3 + 2] = a2 + bout[2];
    }
}

// -------------------------------------------------------------------------
extern "C" void kernel_launch(void* const* d_in, const int* in_sizes, int n_in,
                              void* d_out, int out_size) {
    const float* coords = (const float*)d_in[0];
    const float* tin  = (const float*)d_in[2];
    const float* Wgfp = (const float*)d_in[3];
    const float* Wt_  = (const float*)d_in[4];
    const float* bt_  = (const float*)d_in[5];
    const float* Win  = (const float*)d_in[6];
    const float* bin  = (const float*)d_in[7];
    const float* W1   = (const float*)d_in[8];
    const float* b1   = (const float*)d_in[9];
    const float* W2   = (const float*)d_in[10];
    const float* b2   = (const float*)d_in[11];
    const float* We   = (const float*)d_in[12];
    const float* be   = (const float*)d_in[13];
    const float* eps  = (const float*)d_in[14];
    const float* gnw  = (const float*)d_in[15];
    const float* gnb  = (const float*)d_in[16];
    const float* gnms = (const float*)d_in[17];
    const float* Wtl  = (const float*)d_in[18];
    const float* btl  = (const float*)d_in[19];
    const float* Wout = (const float*)d_in[20];
    const float* bout = (const float*)d_in[21];
    float* out = (float*)d_out;

    k_temb<<<1, 128>>>(tin, Wgfp, Wt_, bt_);
    k_tproj<<<LL * BB, 256>>>(Wtl, btl);
    k_hin<<<NN, 256>>>(coords, Win, bin);
    k_nbr<<<NN / 4, 128>>>(coords);
    k_eattr<<<(NN * KK + 127) / 128, 128>>>(coords);

    for (int l = 0; l < LL; l++) {
        k_edge<<<NN, 512>>>(We + (size_t)l * EDIM * X2H, be + l * X2H, l);
        k_gemm<0><<<dim3(4, 32), 256>>>(W1 + (size_t)l * X2H * HH, b1 + l * HH, eps, l);
        k_gemm<1><<<dim3(4, 32), 256>>>(W2 + (size_t)l * HH * HH, b2 + l * HH, eps, l);
        k_gstat<<<dim3(BB, 8), 256>>>();
        k_gfin<<<64, 256>>>(gnw + l * HH, gnb + l * HH, gnms + l * HH);
    }
    k_out<<<NN / 8, 256>>>(Wout, bout, out);
}

// round 4
// speedup vs baseline: 1.1679x; 1.1679x over previous
#include <cuda_runtime.h>
#include <math.h>

#define NN     4096
#define BB     8
#define NPG    512
#define KK     30
#define NBASIS 32
#define EDIM   35      // NBASIS + 3
#define KPAD   40      // padded K for mma (5 steps of 8)
#define HH     256
#define X2H    512
#define TT     128
#define LL     5
#define RADIUS 1.5f

// ---------------- static scratch (no allocations allowed) ----------------
__device__ __align__(16) float d_tfeat[BB * TT];
__device__ __align__(16) float d_tproj[LL * BB * HH];
__device__ __align__(16) float d_h[NN * HH];
__device__ __align__(16) float d_aggr[NN * X2H];
__device__ __align__(16) float d_z1[NN * HH];
__device__ __align__(16) float d_z[NN * HH];
__device__ __align__(16) float d_eattr[NN * KK * 36];   // [edge][36], zeroed if invalid
__device__ int   d_nbr[NN * KK];
__device__ int   d_cnt[NN];
__device__ __align__(16) float d_sumz[BB * HH];
__device__ __align__(16) float d_sumq[BB * HH];

__device__ __forceinline__ float silu_f(float v) { return v / (1.f + expf(-v)); }

// ---------------- tf32 helpers ----------------
__device__ __forceinline__ float to_tf32(float a) {
    unsigned u;
    asm("cvt.rna.tf32.f32 %0, %1;" : "=r"(u) : "f"(a));
    return __uint_as_float(u);
}
__device__ __forceinline__ void mma_tf32(float* c, float4 a, float b0, float b1) {
    asm volatile(
        "mma.sync.aligned.m16n8k8.row.col.f32.tf32.tf32.f32 "
        "{%0,%1,%2,%3}, {%4,%5,%6,%7}, {%8,%9}, {%0,%1,%2,%3};"
        : "+f"(c[0]), "+f"(c[1]), "+f"(c[2]), "+f"(c[3])
        : "r"(__float_as_uint(a.x)), "r"(__float_as_uint(a.y)),
          "r"(__float_as_uint(a.z)), "r"(__float_as_uint(a.w)),
          "r"(__float_as_uint(b0)), "r"(__float_as_uint(b1)));
}

// ---------------- time embedding ----------------
__global__ void k_temb(const float* __restrict__ tin, const float* __restrict__ wgfp,
                       const float* __restrict__ wt, const float* __restrict__ bt) {
    __shared__ float ss[64], sc[64];
    int t = threadIdx.x; // 128
    for (int b = 0; b < BB; b++) {
        if (t < 64) {
            float xp = 6.283185307179586f * tin[b] * wgfp[t];
            ss[t] = sinf(xp);
            sc[t] = cosf(xp);
        }
        __syncthreads();
        float acc = bt[t];
        #pragma unroll 8
        for (int h = 0; h < 64; h++) {
            acc = fmaf(ss[h], wt[h * TT + t], acc);
            acc = fmaf(sc[h], wt[(64 + h) * TT + t], acc);
        }
        d_tfeat[b * TT + t] = silu_f(acc);
        __syncthreads();
    }
}

__global__ void k_tproj(const float* __restrict__ Wt, const float* __restrict__ bt) {
    int l = blockIdx.x / BB, b = blockIdx.x % BB;
    int c = threadIdx.x; // 256
    __shared__ float tf[TT];
    if (c < TT) tf[c] = d_tfeat[b * TT + c];
    __syncthreads();
    float acc = bt[l * HH + c];
    const float* w = Wt + (size_t)l * TT * HH;
    #pragma unroll 8
    for (int k = 0; k < TT; k++) acc = fmaf(tf[k], w[k * HH + c], acc);
    d_tproj[(l * BB + b) * HH + c] = acc;
}

__global__ void k_hin(const float* __restrict__ coords, const float* __restrict__ Win,
                      const float* __restrict__ bin) {
    int i = blockIdx.x;
    int c = threadIdx.x;
    float x0 = coords[i * 3 + 0], x1 = coords[i * 3 + 1], x2 = coords[i * 3 + 2];
    float v = fmaf(x0, Win[c], fmaf(x1, Win[HH + c], fmaf(x2, Win[2 * HH + c], bin[c])));
    d_h[(size_t)i * HH + c] = v;
}

// ---------------- radius graph ----------------
__global__ void __launch_bounds__(128) k_nbr(const float* __restrict__ coords) {
    __shared__ float sx[NPG], sy[NPG], sz[NPG];
    __shared__ float sd[4][NPG];
    int t = threadIdx.x;
    int base = blockIdx.x * 4;
    int goff = (base >> 9) << 9;
    for (int j = t; j < NPG; j += 128) {
        sx[j] = coords[(goff + j) * 3 + 0];
        sy[j] = coords[(goff + j) * 3 + 1];
        sz[j] = coords[(goff + j) * 3 + 2];
    }
    __syncthreads();
    int w = t >> 5, lane = t & 31;
    int il = (base & 511) + w;
    int ig = goff + il;
    float xi = sx[il], yi = sy[il], zi = sz[il];
    float sqi = xi * xi + yi * yi + zi * zi;
    for (int j = lane; j < NPG; j += 32) {
        float xj = sx[j], yj = sy[j], zj = sz[j];
        float dot = xi * xj + yi * yj + zi * zj;
        float sqj = xj * xj + yj * yj + zj * zj;
        float d2 = sqi + sqj - 2.f * dot;
        float d = sqrtf(fmaxf(d2, 1e-12f));
        sd[w][j] = (j != il && d < RADIUS) ? d : INFINITY;
    }
    __syncwarp();
    int cc = 0;
    for (int k = 0; k < KK; k++) {
        float best = INFINITY;
        int bi = -1;
        for (int j = lane; j < NPG; j += 32) {
            float v = sd[w][j];
            if (v < best) { best = v; bi = j; }
        }
        #pragma unroll
        for (int off = 16; off; off >>= 1) {
            float ov = __shfl_down_sync(0xffffffffu, best, off);
            int oi = __shfl_down_sync(0xffffffffu, bi, off);
            if (ov < best || (ov == best && (unsigned)oi < (unsigned)bi)) { best = ov; bi = oi; }
        }
        best = __shfl_sync(0xffffffffu, best, 0);
        bi = __shfl_sync(0xffffffffu, bi, 0);
        if (!(best < INFINITY)) break;
        if (lane == 0) {
            d_nbr[ig * KK + k] = goff + bi;
            sd[w][bi] = INFINITY;
        }
        cc = k + 1;
        __syncwarp();
    }
    if (lane == 0) d_cnt[ig] = cc;
}

// ---------------- edge attributes (zero rows for invalid edges) -----------
__global__ void k_eattr(const float* __restrict__ coords) {
    int e = blockIdx.x * blockDim.x + threadIdx.x;
    if (e >= NN * KK) return;
    int i = e / KK, k = e % KK;
    float* o = d_eattr + (size_t)e * 36;
    if (k >= d_cnt[i]) {
        #pragma unroll
        for (int m = 0; m < 36; m++) o[m] = 0.f;
        return;
    }
    int s = d_nbr[e];
    float ex = coords[s * 3 + 0] - coords[i * 3 + 0];
    float ey = coords[s * 3 + 1] - coords[i * 3 + 1];
    float ez = coords[s * 3 + 2] - coords[i * 3 + 2];
    float d2 = ex * ex + ey * ey + ez * ez;
    float el = sqrtf(fmaxf(d2, 1e-12f));
    float inv = 1.f / el;
    const float step = RADIUS / 33.f;
    const float istep = 33.f / RADIUS;
    #pragma unroll
    for (int m = 0; m < NBASIS; m++) {
        float dd = (el - (float)(m + 1) * step) * istep;
        o[m] = expf(-dd * dd) * (1.f / 1.12f);
    }
    o[32] = ex * inv;
    o[33] = ey * inv;
    o[34] = ez * inv;
    o[35] = 0.f;
}

// ---------------- k_edge: tensor-core (3xTF32) GINE message+aggregate -----
// Block = 4 nodes (128 edge rows, rows 32n+k, k<30 valid). 8 warps, 256 thr.
// Fragment-order smem for A (eattr, hi/lo) and per-chunk B (We, hi/lo).
// smem float offsets:
#define OFF_AFH 0
#define OFF_AFL 5120
#define OFF_BFH 10240
#define OFF_BFL 15360
#define OFF_PART 20480   // 8*128
#define OFF_STP  21504   // 256
#define OFF_SBE  21760   // 512
#define SMEM_EDGE_FLOATS 22272

__global__ void __launch_bounds__(256) k_edge(const float* __restrict__ We,
                                              const float* __restrict__ be, int l) {
    extern __shared__ float sm[];
    float* Afh = sm + OFF_AFH;
    float* Afl = sm + OFF_AFL;
    float* Bfh = sm + OFF_BFH;
    float* Bfl = sm + OFF_BFL;
    float* part = sm + OFF_PART;
    float* stp = sm + OFF_STP;
    float* sbe = sm + OFF_SBE;
    __shared__ int ssrc[4][32];
    __shared__ int scnt[4];

    int t = threadIdx.x;
    int w = t >> 5, lane = t & 31;
    int i0 = blockIdx.x * 4;
    int g = i0 >> 9;

    // stage small tables
    if (t < 128) {
        int n = t >> 5, k = t & 31;
        int c = d_cnt[i0 + n];
        if (k == 0) scnt[n] = c;
        ssrc[n][k] = (k < c) ? d_nbr[(i0 + n) * KK + k] : (i0 + n);
    }
    stp[t] = d_tproj[(l * BB + g) * HH + t];  // t<256
    for (int c = t; c < X2H; c += 256) sbe[c] = be[c];

    // stage A fragments (eattr rows for this block), hi/lo split
    // linear idx = ((w*5+ks)*32 + lane)*4 + r ; A elem: row=16w+8*(r&1)+lane/4,
    // col = ks*8 + lane%4 + 4*(r>>1)
    for (int idx = t; idx < 5120; idx += 256) {
        int r = idx & 3;
        int lidx = (idx >> 2) & 31;
        int ks = (idx >> 7) % 5;
        int ww = idx / 640;
        int row = 16 * ww + 8 * (r & 1) + (lidx >> 2);
        int col = ks * 8 + (lidx & 3) + 4 * (r >> 1);
        int n = row >> 5, k = row & 31;
        float a = 0.f;
        if (k < KK && col < EDIM)
            a = d_eattr[(size_t)((i0 + n) * KK + k) * 36 + col];
        float hi = to_tf32(a);
        Afh[idx] = hi;
        Afl[idx] = to_tf32(a - hi);
    }
    __syncthreads();

    int node = w >> 1;                 // node this warp reduces for
    int kbase = (w & 1) * 16;         // k-range half
    int cnt_n = scnt[node];

    for (int cc = 0; cc < 4; cc++) {
        // stage B fragments for col chunk cc: idx = ((ks*8+tp)*32+lane)*4+r
        // t = 2*tp + (r>>1), breg = r&1 ; k-row = ks*8 + lane%4 + 4*breg,
        // col = t*8 + lane/4 (+128*cc)
        for (int idx = t; idx < 5120; idx += 256) {
            int r = idx & 3;
            int lidx = (idx >> 2) & 31;
            int tp = (idx >> 7) & 7;
            int ks = idx >> 10;
            int tile = 2 * tp + (r >> 1);
            int krow = ks * 8 + (lidx & 3) + 4 * (r & 1);
            int gcol = cc * 128 + tile * 8 + (lidx >> 2);
            float b = (krow < EDIM) ? We[krow * X2H + gcol] : 0.f;
            float hi = to_tf32(b);
            Bfh[idx] = hi;
            Bfl[idx] = to_tf32(b - hi);
        }
        __syncthreads();

        float acc[16][4];
        #pragma unroll
        for (int q = 0; q < 16; q++) {
            acc[q][0] = 0.f; acc[q][1] = 0.f; acc[q][2] = 0.f; acc[q][3] = 0.f;
        }
        #pragma unroll
        for (int ks = 0; ks < 5; ks++) {
            float4 ah = *(const float4*)&Afh[((w * 5 + ks) * 32 + lane) * 4];
            float4 al = *(const float4*)&Afl[((w * 5 + ks) * 32 + lane) * 4];
            #pragma unroll
            for (int tp = 0; tp < 8; tp++) {
                float4 bh = *(const float4*)&Bfh[((ks * 8 + tp) * 32 + lane) * 4];
                float4 bl = *(const float4*)&Bfl[((ks * 8 + tp) * 32 + lane) * 4];
                mma_tf32(acc[2 * tp + 0], ah, bh.x, bh.y);
                mma_tf32(acc[2 * tp + 0], al, bh.x, bh.y);
                mma_tf32(acc[2 * tp + 0], ah, bl.x, bl.y);
                mma_tf32(acc[2 * tp + 1], ah, bh.z, bh.w);
                mma_tf32(acc[2 * tp + 1], al, bh.z, bh.w);
                mma_tf32(acc[2 * tp + 1], ah, bl.z, bl.w);
            }
        }

        // epilogue: + be + x[src], relu, mask, reduce rows -> part[w][col]
        int k0 = kbase + (lane >> 2);
        int k1 = k0 + 8;
        bool v0 = k0 < cnt_n, v1 = k1 < cnt_n;
        int s0 = ssrc[node][k0 & 31], s1 = ssrc[node][k1 & 31];
        #pragma unroll
        for (int tile = 0; tile < 16; tile++) {
            int colb = tile * 8 + 2 * (lane & 3);
            int gcol = cc * 128 + colb;
            float2 be2 = *(const float2*)&sbe[gcol];
            float2 x0, x1;
            if (cc < 2) {
                x0 = *(const float2*)(d_h + (size_t)s0 * HH + gcol);
                x1 = *(const float2*)(d_h + (size_t)s1 * HH + gcol);
            } else {
                float2 tv = *(const float2*)&stp[gcol - HH];
                x0 = tv; x1 = tv;
            }
            float m00 = v0 ? fmaxf(acc[tile][0] + be2.x + x0.x, 0.f) : 0.f;
            float m01 = v0 ? fmaxf(acc[tile][1] + be2.y + x0.y, 0.f) : 0.f;
            float m10 = v1 ? fmaxf(acc[tile][2] + be2.x + x1.x, 0.f) : 0.f;
            float m11 = v1 ? fmaxf(acc[tile][3] + be2.y + x1.y, 0.f) : 0.f;
            float sA = m00 + m10;
            float sB = m01 + m11;
            #pragma unroll
            for (int off = 16; off >= 4; off >>= 1) {
                sA += __shfl_down_sync(0xffffffffu, sA, off);
                sB += __shfl_down_sync(0xffffffffu, sB, off);
            }
            if (lane < 4) {
                part[w * 128 + tile * 8 + 2 * lane] = sA;
                part[w * 128 + tile * 8 + 2 * lane + 1] = sB;
            }
        }
        __syncthreads();
        // combine warp halves -> aggr
        for (int q = t; q < 512; q += 256) {
            int n = q >> 7, c = q & 127;
            float s = part[(2 * n) * 128 + c] + part[(2 * n + 1) * 128 + c];
            d_aggr[(size_t)(i0 + n) * X2H + cc * 128 + c] = s;
        }
        __syncthreads();
    }
}

// ---------------- GEMM (R2-proven 64x64 FFMA tiles) -----------------------
// MODE0: z1 = silu(((1+eps)*[h|tproj] + aggr) @ W1 + b1)   K=512
// MODE1: z  = z1 @ W2 + b2                                  K=256
template <int MODE>
__global__ void __launch_bounds__(256) k_gemm(const float* __restrict__ Bw,
                                              const float* __restrict__ bias,
                                              const float* __restrict__ epsp, int l) {
    const int Kd = (MODE == 0) ? X2H : HH;
    const int Nd = HH;
    __shared__ float As[16][64];
    __shared__ float Bs[16][64];
    __shared__ float stp[HH];
    int t = threadIdx.x;
    int m0 = blockIdx.y * 64, n0 = blockIdx.x * 64;
    int g = m0 >> 9;
    int ty = t >> 4, tx = t & 15;
    int ar = t >> 2, akc = (t & 3) * 4;
    int br = t >> 4, bnc = (t & 15) * 4;
    float ep = (MODE == 0) ? (1.f + epsp[l]) : 0.f;
    if (MODE == 0 && t < HH) stp[t] = d_tproj[(l * BB + g) * HH + t];
    __syncthreads();
    float acc[4][4];
    #pragma unroll
    for (int i = 0; i < 4; i++)
        #pragma unroll
        for (int j = 0; j < 4; j++) acc[i][j] = 0.f;
    for (int k0 = 0; k0 < Kd; k0 += 16) {
        int kg = k0 + akc;
        float4 av;
        if (MODE == 0) {
            float4 g4 = *(const float4*)(d_aggr + (size_t)(m0 + ar) * X2H + kg);
            float4 hx;
            if (kg < HH) hx = *(const float4*)(d_h + (size_t)(m0 + ar) * HH + kg);
            else         hx = *(const float4*)(stp + (kg - HH));
            av.x = fmaf(ep, hx.x, g4.x);
            av.y = fmaf(ep, hx.y, g4.y);
            av.z = fmaf(ep, hx.z, g4.z);
            av.w = fmaf(ep, hx.w, g4.w);
        } else {
            av = *(const float4*)(d_z1 + (size_t)(m0 + ar) * HH + kg);
        }
        As[akc + 0][ar] = av.x;
        As[akc + 1][ar] = av.y;
        As[akc + 2][ar] = av.z;
        As[akc + 3][ar] = av.w;
        *(float4*)&Bs[br][bnc] = *(const float4*)(Bw + (size_t)(k0 + br) * Nd + n0 + bnc);
        __syncthreads();
        #pragma unroll
        for (int kk = 0; kk < 16; kk++) {
            float4 a4 = *(const float4*)&As[kk][ty * 4];
            float4 b4 = *(const float4*)&Bs[kk][tx * 4];
            acc[0][0] = fmaf(a4.x, b4.x, acc[0][0]); acc[0][1] = fmaf(a4.x, b4.y, acc[0][1]);
            acc[0][2] = fmaf(a4.x, b4.z, acc[0][2]); acc[0][3] = fmaf(a4.x, b4.w, acc[0][3]);
            acc[1][0] = fmaf(a4.y, b4.x, acc[1][0]); acc[1][1] = fmaf(a4.y, b4.y, acc[1][1]);
            acc[1][2] = fmaf(a4.y, b4.z, acc[1][2]); acc[1][3] = fmaf(a4.y, b4.w, acc[1][3]);
            acc[2][0] = fmaf(a4.z, b4.x, acc[2][0]); acc[2][1] = fmaf(a4.z, b4.y, acc[2][1]);
            acc[2][2] = fmaf(a4.z, b4.z, acc[2][2]); acc[2][3] = fmaf(a4.z, b4.w, acc[2][3]);
            acc[3][0] = fmaf(a4.w, b4.x, acc[3][0]); acc[3][1] = fmaf(a4.w, b4.y, acc[3][1]);
            acc[3][2] = fmaf(a4.w, b4.z, acc[3][2]); acc[3][3] = fmaf(a4.w, b4.w, acc[3][3]);
        }
        __syncthreads();
    }
    float* C = (MODE == 0) ? d_z1 : d_z;
    #pragma unroll
    for (int i = 0; i < 4; i++) {
        int row = m0 + ty * 4 + i;
        #pragma unroll
        for (int j = 0; j < 4; j++) {
            int col = n0 + tx * 4 + j;
            float v = acc[i][j] + bias[col];
            if (MODE == 0) v = silu_f(v);
            C[(size_t)row * Nd + col] = v;
        }
    }
}

// ---------------- GraphNorm stats: sum + sumsq in one pass ----------------
__global__ void k_gstat() {
    int g = blockIdx.x, chunk = blockIdx.y;
    int t = threadIdx.x;
    int cl = t & 31, seg = t >> 5;
    int c = chunk * 32 + cl;
    int base = g * NPG + seg * 64;
    float s = 0.f, s2 = 0.f;
    for (int n = 0; n < 64; n++) {
        float v = d_z[(size_t)(base + n) * HH + c];
        s += v;
        s2 = fmaf(v, v, s2);
    }
    __shared__ float r1[8][32], r2[8][32];
    r1[seg][cl] = s;
    r2[seg][cl] = s2;
    __syncthreads();
    if (seg == 0) {
        float t1 = 0.f, t2 = 0.f;
        #pragma unroll
        for (int q = 0; q < 8; q++) { t1 += r1[q][cl]; t2 += r2[q][cl]; }
        d_sumz[g * HH + c] = t1;
        d_sumq[g * HH + c] = t2;
    }
}

__global__ void k_gfin(const float* __restrict__ gw, const float* __restrict__ gb,
                       const float* __restrict__ gms) {
    int nb = blockIdx.x * 64;
    int g = nb >> 9;
    int c = threadIdx.x;
    float mean = d_sumz[g * HH + c] * (1.f / 512.f);
    float ez2  = d_sumq[g * HH + c] * (1.f / 512.f);
    float mm = mean * gms[c];
    float var = ez2 - 2.f * mm * mean + mm * mm;
    float inv = 1.f / sqrtf(var + 1e-5f);
    float w = gw[c], b = gb[c];
    for (int n = 0; n < 64; n++) {
        size_t id = (size_t)(nb + n) * HH + c;
        float cc = d_z[id] - mm;
        float zn = fmaf(w * cc, inv, b);
        float hv = zn + d_h[id];
        d_h[id] = silu_f(hv);
    }
}

// ---------------- output head ----------------
__global__ void k_out(const float* __restrict__ Wout, const float* __restrict__ bout,
                      float* __restrict__ out) {
    __shared__ float sw[HH * 3];
    int t = threadIdx.x;
    for (int idx = t; idx < HH * 3; idx += 256) sw[idx] = Wout[idx];
    __syncthreads();
    int w = t >> 5, lane = t & 31;
    int i = blockIdx.x * 8 + w;
    float a0 = 0.f, a1 = 0.f, a2 = 0.f;
    for (int c = lane; c < HH; c += 32) {
        float hv = d_h[(size_t)i * HH + c];
        a0 = fmaf(hv, sw[c * 3 + 0], a0);
        a1 = fmaf(hv, sw[c * 3 + 1], a1);
        a2 = fmaf(hv, sw[c * 3 + 2], a2);
    }
    #pragma unroll
    for (int off = 16; off; off >>= 1) {
        a0 += __shfl_down_sync(0xffffffffu, a0, off);
        a1 += __shfl_down_sync(0xffffffffu, a1, off);
        a2 += __shfl_down_sync(0xffffffffu, a2, off);
    }
    if (lane == 0) {
        out[i * 3 + 0] = a0 + bout[0];
        out[i * 3 + 1] = a1 + bout[1];
        out[i * 3 + 2] = a2 + bout[2];
    }
}

// -------------------------------------------------------------------------
extern "C" void kernel_launch(void* const* d_in, const int* in_sizes, int n_in,
                              void* d_out, int out_size) {
    const float* coords = (const float*)d_in[0];
    const float* tin  = (const float*)d_in[2];
    const float* Wgfp = (const float*)d_in[3];
    const float* Wt_  = (const float*)d_in[4];
    const float* bt_  = (const float*)d_in[5];
    const float* Win  = (const float*)d_in[6];
    const float* bin  = (const float*)d_in[7];
    const float* W1   = (const float*)d_in[8];
    const float* b1   = (const float*)d_in[9];
    const float* W2   = (const float*)d_in[10];
    const float* b2   = (const float*)d_in[11];
    const float* We   = (const float*)d_in[12];
    const float* be   = (const float*)d_in[13];
    const float* eps  = (const float*)d_in[14];
    const float* gnw  = (const float*)d_in[15];
    const float* gnb  = (const float*)d_in[16];
    const float* gnms = (const float*)d_in[17];
    const float* Wtl  = (const float*)d_in[18];
    const float* btl  = (const float*)d_in[19];
    const float* Wout = (const float*)d_in[20];
    const float* bout = (const float*)d_in[21];
    float* out = (float*)d_out;

    const int smem_edge = SMEM_EDGE_FLOATS * 4;
    cudaFuncSetAttribute(k_edge, cudaFuncAttributeMaxDynamicSharedMemorySize, smem_edge);

    k_temb<<<1, 128>>>(tin, Wgfp, Wt_, bt_);
    k_tproj<<<LL * BB, 256>>>(Wtl, btl);
    k_hin<<<NN, 256>>>(coords, Win, bin);
    k_nbr<<<NN / 4, 128>>>(coords);
    k_eattr<<<(NN * KK + 127) / 128, 128>>>(coords);

    for (int l = 0; l < LL; l++) {
        k_edge<<<NN / 4, 256, smem_edge>>>(We + (size_t)l * EDIM * X2H, be + l * X2H, l);
        k_gemm<0><<<dim3(4, 64), 256>>>(W1 + (size_t)l * X2H * HH, b1 + l * HH, eps, l);
        k_gemm<1><<<dim3(4, 64), 256>>>(W2 + (size_t)l * HH * HH, b2 + l * HH, eps, l);
        k_gstat<<<dim3(BB, 8), 256>>>();
        k_gfin<<<64, 256>>>(gnw + l * HH, gnb + l * HH, gnms + l * HH);
    }
    k_out<<<NN / 8, 256>>>(Wout, bout, out);
}

// round 5
// speedup vs baseline: 1.2480x; 1.0685x over previous
#include <cuda_runtime.h>
#include <math.h>

#define NN     4096
#define BB     8
#define NPG    512
#define KK     30
#define NBASIS 32
#define EDIM   35      // NBASIS + 3
#define HH     256
#define X2H    512
#define TT     128
#define LL     5
#define RADIUS 1.5f

// ---------------- static scratch (no allocations allowed) ----------------
__device__ __align__(16) float d_tfeat[BB * TT];
__device__ __align__(16) float d_tproj[LL * BB * HH];
__device__ __align__(16) float d_h[NN * HH];
__device__ __align__(16) float d_aggr[NN * X2H];
__device__ __align__(16) float d_z1[NN * HH];
__device__ __align__(16) float d_z[NN * HH];
__device__ __align__(16) float d_eattr[NN * KK * 36];   // [edge][36], zeroed if invalid
__device__ __align__(16) float d_afrag[(NN / 4) * 10240];      // per-block A frags hi|lo
__device__ __align__(16) float d_bfrag[LL * 4 * 10240];        // per-(layer,chunk) B frags hi|lo
__device__ int   d_nbr[NN * KK];
__device__ int   d_cnt[NN];
__device__ __align__(16) float d_psum[64 * HH];   // gemm1 per-mblock col sums
__device__ __align__(16) float d_psumq[64 * HH];  // gemm1 per-mblock col sumsq

__device__ __forceinline__ float silu_f(float v) { return v / (1.f + expf(-v)); }

// ---------------- tf32 helpers ----------------
__device__ __forceinline__ float to_tf32(float a) {
    unsigned u;
    asm("cvt.rna.tf32.f32 %0, %1;" : "=r"(u) : "f"(a));
    return __uint_as_float(u);
}
__device__ __forceinline__ void mma_tf32(float* c, float4 a, float b0, float b1) {
    asm volatile(
        "mma.sync.aligned.m16n8k8.row.col.f32.tf32.tf32.f32 "
        "{%0,%1,%2,%3}, {%4,%5,%6,%7}, {%8,%9}, {%0,%1,%2,%3};"
        : "+f"(c[0]), "+f"(c[1]), "+f"(c[2]), "+f"(c[3])
        : "r"(__float_as_uint(a.x)), "r"(__float_as_uint(a.y)),
          "r"(__float_as_uint(a.z)), "r"(__float_as_uint(a.w)),
          "r"(__float_as_uint(b0)), "r"(__float_as_uint(b1)));
}

// ---------------- time embedding ----------------
__global__ void k_temb(const float* __restrict__ tin, const float* __restrict__ wgfp,
                       const float* __restrict__ wt, const float* __restrict__ bt) {
    __shared__ float ss[64], sc[64];
    int t = threadIdx.x; // 128
    for (int b = 0; b < BB; b++) {
        if (t < 64) {
            float xp = 6.283185307179586f * tin[b] * wgfp[t];
            ss[t] = sinf(xp);
            sc[t] = cosf(xp);
        }
        __syncthreads();
        float acc = bt[t];
        #pragma unroll 8
        for (int h = 0; h < 64; h++) {
            acc = fmaf(ss[h], wt[h * TT + t], acc);
            acc = fmaf(sc[h], wt[(64 + h) * TT + t], acc);
        }
        d_tfeat[b * TT + t] = silu_f(acc);
        __syncthreads();
    }
}

__global__ void k_tproj(const float* __restrict__ Wt, const float* __restrict__ bt) {
    int l = blockIdx.x / BB, b = blockIdx.x % BB;
    int c = threadIdx.x; // 256
    __shared__ float tf[TT];
    if (c < TT) tf[c] = d_tfeat[b * TT + c];
    __syncthreads();
    float acc = bt[l * HH + c];
    const float* w = Wt + (size_t)l * TT * HH;
    #pragma unroll 8
    for (int k = 0; k < TT; k++) acc = fmaf(tf[k], w[k * HH + c], acc);
    d_tproj[(l * BB + b) * HH + c] = acc;
}

__global__ void k_hin(const float* __restrict__ coords, const float* __restrict__ Win,
                      const float* __restrict__ bin) {
    int i = blockIdx.x;
    int c = threadIdx.x;
    float x0 = coords[i * 3 + 0], x1 = coords[i * 3 + 1], x2 = coords[i * 3 + 2];
    float v = fmaf(x0, Win[c], fmaf(x1, Win[HH + c], fmaf(x2, Win[2 * HH + c], bin[c])));
    d_h[(size_t)i * HH + c] = v;
}

// ---------------- radius graph ----------------
__global__ void __launch_bounds__(128) k_nbr(const float* __restrict__ coords) {
    __shared__ float sx[NPG], sy[NPG], sz[NPG];
    __shared__ float sd[4][NPG];
    int t = threadIdx.x;
    int base = blockIdx.x * 4;
    int goff = (base >> 9) << 9;
    for (int j = t; j < NPG; j += 128) {
        sx[j] = coords[(goff + j) * 3 + 0];
        sy[j] = coords[(goff + j) * 3 + 1];
        sz[j] = coords[(goff + j) * 3 + 2];
    }
    __syncthreads();
    int w = t >> 5, lane = t & 31;
    int il = (base & 511) + w;
    int ig = goff + il;
    float xi = sx[il], yi = sy[il], zi = sz[il];
    float sqi = xi * xi + yi * yi + zi * zi;
    for (int j = lane; j < NPG; j += 32) {
        float xj = sx[j], yj = sy[j], zj = sz[j];
        float dot = xi * xj + yi * yj + zi * zj;
        float sqj = xj * xj + yj * yj + zj * zj;
        float d2 = sqi + sqj - 2.f * dot;
        float d = sqrtf(fmaxf(d2, 1e-12f));
        sd[w][j] = (j != il && d < RADIUS) ? d : INFINITY;
    }
    __syncwarp();
    int cc = 0;
    for (int k = 0; k < KK; k++) {
        float best = INFINITY;
        int bi = -1;
        for (int j = lane; j < NPG; j += 32) {
            float v = sd[w][j];
            if (v < best) { best = v; bi = j; }
        }
        #pragma unroll
        for (int off = 16; off; off >>= 1) {
            float ov = __shfl_down_sync(0xffffffffu, best, off);
            int oi = __shfl_down_sync(0xffffffffu, bi, off);
            if (ov < best || (ov == best && (unsigned)oi < (unsigned)bi)) { best = ov; bi = oi; }
        }
        best = __shfl_sync(0xffffffffu, best, 0);
        bi = __shfl_sync(0xffffffffu, bi, 0);
        if (!(best < INFINITY)) break;
        if (lane == 0) {
            d_nbr[ig * KK + k] = goff + bi;
            sd[w][bi] = INFINITY;
        }
        cc = k + 1;
        __syncwarp();
    }
    if (lane == 0) d_cnt[ig] = cc;
}

// ---------------- edge attributes (zero rows for invalid edges) -----------
__global__ void k_eattr(const float* __restrict__ coords) {
    int e = blockIdx.x * blockDim.x + threadIdx.x;
    if (e >= NN * KK) return;
    int i = e / KK, k = e % KK;
    float* o = d_eattr + (size_t)e * 36;
    if (k >= d_cnt[i]) {
        #pragma unroll
        for (int m = 0; m < 36; m++) o[m] = 0.f;
        return;
    }
    int s = d_nbr[e];
    float ex = coords[s * 3 + 0] - coords[i * 3 + 0];
    float ey = coords[s * 3 + 1] - coords[i * 3 + 1];
    float ez = coords[s * 3 + 2] - coords[i * 3 + 2];
    float d2 = ex * ex + ey * ey + ez * ez;
    float el = sqrtf(fmaxf(d2, 1e-12f));
    float inv = 1.f / el;
    const float step = RADIUS / 33.f;
    const float istep = 33.f / RADIUS;
    #pragma unroll
    for (int m = 0; m < NBASIS; m++) {
        float dd = (el - (float)(m + 1) * step) * istep;
        o[m] = expf(-dd * dd) * (1.f / 1.12f);
    }
    o[32] = ex * inv;
    o[33] = ey * inv;
    o[34] = ez * inv;
    o[35] = 0.f;
}

// ---------------- A fragments: eattr -> fragment-order hi/lo (per block) --
__global__ void __launch_bounds__(256) k_afrag() {
    int blk = blockIdx.x;            // 1024 blocks of 4 nodes
    int i0 = blk * 4;
    float* outp = d_afrag + (size_t)blk * 10240;
    for (int idx = threadIdx.x; idx < 5120; idx += 256) {
        int r = idx & 3;
        int lidx = (idx >> 2) & 31;
        int ks = (idx >> 7) % 5;
        int ww = idx / 640;
        int row = 16 * ww + 8 * (r & 1) + (lidx >> 2);
        int col = ks * 8 + (lidx & 3) + 4 * (r >> 1);
        int n = row >> 5, k = row & 31;
        float a = 0.f;
        if (k < KK && col < EDIM)
            a = d_eattr[(size_t)((i0 + n) * KK + k) * 36 + col];
        float hi = to_tf32(a);
        outp[idx] = hi;
        outp[idx + 5120] = to_tf32(a - hi);
    }
}

// ---------------- B fragments: We -> fragment-order hi/lo (per layer,chunk)
__global__ void __launch_bounds__(256) k_befrag(const float* __restrict__ We) {
    int cc = blockIdx.x, l = blockIdx.y;
    const float* w = We + (size_t)l * EDIM * X2H;
    float* outp = d_bfrag + (size_t)(l * 4 + cc) * 10240;
    for (int idx = threadIdx.x; idx < 5120; idx += 256) {
        int r = idx & 3;
        int lidx = (idx >> 2) & 31;
        int tp = (idx >> 7) & 7;
        int ks = idx >> 10;
        int tile = 2 * tp + (r >> 1);
        int krow = ks * 8 + (lidx & 3) + 4 * (r & 1);
        int gcol = cc * 128 + tile * 8 + (lidx >> 2);
        float b = (krow < EDIM) ? w[krow * X2H + gcol] : 0.f;
        float hi = to_tf32(b);
        outp[idx] = hi;
        outp[idx + 5120] = to_tf32(b - hi);
    }
}

// ---------------- k_edge: tensor-core (3xTF32) GINE message+aggregate -----
// Block = 4 nodes (128 edge rows). 8 warps. Fragments precomputed in global.
#define OFF_AFH 0
#define OFF_AFL 5120
#define OFF_BFH 10240
#define OFF_BFL 15360
#define OFF_PART 20480   // 8*128
#define OFF_STP  21504   // 256
#define OFF_SBE  21760   // 512
#define SMEM_EDGE_FLOATS 22272

__global__ void __launch_bounds__(256) k_edge(const float* __restrict__ be, int l) {
    extern __shared__ float sm[];
    float* Afh = sm + OFF_AFH;
    float* Afl = sm + OFF_AFL;
    float* Bfh = sm + OFF_BFH;
    float* Bfl = sm + OFF_BFL;
    float* part = sm + OFF_PART;
    float* stp = sm + OFF_STP;
    float* sbe = sm + OFF_SBE;
    __shared__ int ssrc[4][32];
    __shared__ int scnt[4];

    int t = threadIdx.x;
    int w = t >> 5, lane = t & 31;
    int i0 = blockIdx.x * 4;
    int g = i0 >> 9;

    if (t < 128) {
        int n = t >> 5, k = t & 31;
        int c = d_cnt[i0 + n];
        if (k == 0) scnt[n] = c;
        ssrc[n][k] = (k < c) ? d_nbr[(i0 + n) * KK + k] : (i0 + n);
    }
    stp[t] = d_tproj[(l * BB + g) * HH + t];  // t<256
    for (int c = t; c < X2H; c += 256) sbe[c] = be[c];

    // stage A fragments: straight float4 copy (hi+lo contiguous)
    {
        const float4* asrc = (const float4*)(d_afrag + (size_t)blockIdx.x * 10240);
        float4* adst = (float4*)Afh;
        for (int idx = t; idx < 2560; idx += 256) adst[idx] = asrc[idx];
    }
    __syncthreads();

    int node = w >> 1;
    int kbase = (w & 1) * 16;
    int cnt_n = scnt[node];

    for (int cc = 0; cc < 4; cc++) {
        // stage B fragments for this chunk: straight float4 copy
        {
            const float4* bsrc = (const float4*)(d_bfrag + (size_t)(l * 4 + cc) * 10240);
            float4* bdst = (float4*)Bfh;
            for (int idx = t; idx < 2560; idx += 256) bdst[idx] = bsrc[idx];
        }
        __syncthreads();

        float acc[16][4];
        #pragma unroll
        for (int q = 0; q < 16; q++) {
            acc[q][0] = 0.f; acc[q][1] = 0.f; acc[q][2] = 0.f; acc[q][3] = 0.f;
        }
        #pragma unroll
        for (int ks = 0; ks < 5; ks++) {
            float4 ah = *(const float4*)&Afh[((w * 5 + ks) * 32 + lane) * 4];
            float4 al = *(const float4*)&Afl[((w * 5 + ks) * 32 + lane) * 4];
            #pragma unroll
            for (int tp = 0; tp < 8; tp++) {
                float4 bh = *(const float4*)&Bfh[((ks * 8 + tp) * 32 + lane) * 4];
                float4 bl = *(const float4*)&Bfl[((ks * 8 + tp) * 32 + lane) * 4];
                mma_tf32(acc[2 * tp + 0], ah, bh.x, bh.y);
                mma_tf32(acc[2 * tp + 0], al, bh.x, bh.y);
                mma_tf32(acc[2 * tp + 0], ah, bl.x, bl.y);
                mma_tf32(acc[2 * tp + 1], ah, bh.z, bh.w);
                mma_tf32(acc[2 * tp + 1], al, bh.z, bh.w);
                mma_tf32(acc[2 * tp + 1], ah, bl.z, bl.w);
            }
        }

        // epilogue: + be + x[src], relu, mask, reduce rows -> part[w][col]
        int k0 = kbase + (lane >> 2);
        int k1 = k0 + 8;
        bool v0 = k0 < cnt_n, v1 = k1 < cnt_n;
        int s0 = ssrc[node][k0 & 31], s1 = ssrc[node][k1 & 31];
        #pragma unroll
        for (int tile = 0; tile < 16; tile++) {
            int colb = tile * 8 + 2 * (lane & 3);
            int gcol = cc * 128 + colb;
            float2 be2 = *(const float2*)&sbe[gcol];
            float2 x0, x1;
            if (cc < 2) {
                x0 = *(const float2*)(d_h + (size_t)s0 * HH + gcol);
                x1 = *(const float2*)(d_h + (size_t)s1 * HH + gcol);
            } else {
                float2 tv = *(const float2*)&stp[gcol - HH];
                x0 = tv; x1 = tv;
            }
            float m00 = v0 ? fmaxf(acc[tile][0] + be2.x + x0.x, 0.f) : 0.f;
            float m01 = v0 ? fmaxf(acc[tile][1] + be2.y + x0.y, 0.f) : 0.f;
            float m10 = v1 ? fmaxf(acc[tile][2] + be2.x + x1.x, 0.f) : 0.f;
            float m11 = v1 ? fmaxf(acc[tile][3] + be2.y + x1.y, 0.f) : 0.f;
            float sA = m00 + m10;
            float sB = m01 + m11;
            #pragma unroll
            for (int off = 16; off >= 4; off >>= 1) {
                sA += __shfl_down_sync(0xffffffffu, sA, off);
                sB += __shfl_down_sync(0xffffffffu, sB, off);
            }
            if (lane < 4) {
                part[w * 128 + tile * 8 + 2 * lane] = sA;
                part[w * 128 + tile * 8 + 2 * lane + 1] = sB;
            }
        }
        __syncthreads();
        for (int q = t; q < 512; q += 256) {
            int n = q >> 7, c = q & 127;
            float s = part[(2 * n) * 128 + c] + part[(2 * n + 1) * 128 + c];
            d_aggr[(size_t)(i0 + n) * X2H + cc * 128 + c] = s;
        }
        __syncthreads();
    }
}

// ---------------- GEMM (64x64 FFMA tiles) ---------------------------------
// MODE0: z1 = silu(((1+eps)*[h|tproj] + aggr) @ W1 + b1)   K=512
// MODE1: z  = z1 @ W2 + b2 (+ GraphNorm partial col stats)  K=256
template <int MODE>
__global__ void __launch_bounds__(256) k_gemm(const float* __restrict__ Bw,
                                              const float* __restrict__ bias,
                                              const float* __restrict__ epsp, int l) {
    const int Kd = (MODE == 0) ? X2H : HH;
    const int Nd = HH;
    __shared__ float As[16][64];
    __shared__ float Bs[16][64];
    __shared__ float stp[HH];
    int t = threadIdx.x;
    int m0 = blockIdx.y * 64, n0 = blockIdx.x * 64;
    int g = m0 >> 9;
    int ty = t >> 4, tx = t & 15;
    int ar = t >> 2, akc = (t & 3) * 4;
    int br = t >> 4, bnc = (t & 15) * 4;
    float ep = (MODE == 0) ? (1.f + epsp[l]) : 0.f;
    if (MODE == 0 && t < HH) stp[t] = d_tproj[(l * BB + g) * HH + t];
    __syncthreads();
    float acc[4][4];
    #pragma unroll
    for (int i = 0; i < 4; i++)
        #pragma unroll
        for (int j = 0; j < 4; j++) acc[i][j] = 0.f;
    for (int k0 = 0; k0 < Kd; k0 += 16) {
        int kg = k0 + akc;
        float4 av;
        if (MODE == 0) {
            float4 g4 = *(const float4*)(d_aggr + (size_t)(m0 + ar) * X2H + kg);
            float4 hx;
            if (kg < HH) hx = *(const float4*)(d_h + (size_t)(m0 + ar) * HH + kg);
            else         hx = *(const float4*)(stp + (kg - HH));
            av.x = fmaf(ep, hx.x, g4.x);
            av.y = fmaf(ep, hx.y, g4.y);
            av.z = fmaf(ep, hx.z, g4.z);
            av.w = fmaf(ep, hx.w, g4.w);
        } else {
            av = *(const float4*)(d_z1 + (size_t)(m0 + ar) * HH + kg);
        }
        As[akc + 0][ar] = av.x;
        As[akc + 1][ar] = av.y;
        As[akc + 2][ar] = av.z;
        As[akc + 3][ar] = av.w;
        *(float4*)&Bs[br][bnc] = *(const float4*)(Bw + (size_t)(k0 + br) * Nd + n0 + bnc);
        __syncthreads();
        #pragma unroll
        for (int kk = 0; kk < 16; kk++) {
            float4 a4 = *(const float4*)&As[kk][ty * 4];
            float4 b4 = *(const float4*)&Bs[kk][tx * 4];
            acc[0][0] = fmaf(a4.x, b4.x, acc[0][0]); acc[0][1] = fmaf(a4.x, b4.y, acc[0][1]);
            acc[0][2] = fmaf(a4.x, b4.z, acc[0][2]); acc[0][3] = fmaf(a4.x, b4.w, acc[0][3]);
            acc[1][0] = fmaf(a4.y, b4.x, acc[1][0]); acc[1][1] = fmaf(a4.y, b4.y, acc[1][1]);
            acc[1][2] = fmaf(a4.y, b4.z, acc[1][2]); acc[1][3] = fmaf(a4.y, b4.w, acc[1][3]);
            acc[2][0] = fmaf(a4.z, b4.x, acc[2][0]); acc[2][1] = fmaf(a4.z, b4.y, acc[2][1]);
            acc[2][2] = fmaf(a4.z, b4.z, acc[2][2]); acc[2][3] = fmaf(a4.z, b4.w, acc[2][3]);
            acc[3][0] = fmaf(a4.w, b4.x, acc[3][0]); acc[3][1] = fmaf(a4.w, b4.y, acc[3][1]);
            acc[3][2] = fmaf(a4.w, b4.z, acc[3][2]); acc[3][3] = fmaf(a4.w, b4.w, acc[3][3]);
        }
        __syncthreads();
    }
    float* C = (MODE == 0) ? d_z1 : d_z;
    float s[4] = {0.f, 0.f, 0.f, 0.f};
    float q[4] = {0.f, 0.f, 0.f, 0.f};
    #pragma unroll
    for (int i = 0; i < 4; i++) {
        int row = m0 + ty * 4 + i;
        #pragma unroll
        for (int j = 0; j < 4; j++) {
            int col = n0 + tx * 4 + j;
            float v = acc[i][j] + bias[col];
            if (MODE == 0) v = silu_f(v);
            else { s[j] += v; q[j] = fmaf(v, v, q[j]); }
            C[(size_t)row * Nd + col] = v;
        }
    }
    if (MODE == 1) {
        // column partial sums over this block's 64 rows (deterministic)
        #pragma unroll
        for (int j = 0; j < 4; j++) { As[ty][tx * 4 + j] = s[j]; Bs[ty][tx * 4 + j] = q[j]; }
        __syncthreads();
        if (t < 64) {
            float S = 0.f, Q = 0.f;
            #pragma unroll
            for (int p = 0; p < 16; p++) { S += As[p][t]; Q += Bs[p][t]; }
            d_psum[blockIdx.y * HH + n0 + t] = S;
            d_psumq[blockIdx.y * HH + n0 + t] = Q;
        }
    }
}

// ---------------- GraphNorm finalize (folds gemm1 partials) ---------------
__global__ void k_gfin(const float* __restrict__ gw, const float* __restrict__ gb,
                       const float* __restrict__ gms) {
    int nb = blockIdx.x * 64;
    int g = nb >> 9;
    int c = threadIdx.x;
    float s = 0.f, q = 0.f;
    #pragma unroll
    for (int p = 0; p < 8; p++) {
        s += d_psum[(g * 8 + p) * HH + c];
        q += d_psumq[(g * 8 + p) * HH + c];
    }
    float mean = s * (1.f / 512.f);
    float ez2  = q * (1.f / 512.f);
    float mm = mean * gms[c];
    float var = ez2 - 2.f * mm * mean + mm * mm;
    float inv = 1.f / sqrtf(var + 1e-5f);
    float w = gw[c], b = gb[c];
    for (int n = 0; n < 64; n++) {
        size_t id = (size_t)(nb + n) * HH + c;
        float cc = d_z[id] - mm;
        float zn = fmaf(w * cc, inv, b);
        float hv = zn + d_h[id];
        d_h[id] = silu_f(hv);
    }
}

// ---------------- output head ----------------
__global__ void k_out(const float* __restrict__ Wout, const float* __restrict__ bout,
                      float* __restrict__ out) {
    __shared__ float sw[HH * 3];
    int t = threadIdx.x;
    for (int idx = t; idx < HH * 3; idx += 256) sw[idx] = Wout[idx];
    __syncthreads();
    int w = t >> 5, lane = t & 31;
    int i = blockIdx.x * 8 + w;
    float a0 = 0.f, a1 = 0.f, a2 = 0.f;
    for (int c = lane; c < HH; c += 32) {
        float hv = d_h[(size_t)i * HH + c];
        a0 = fmaf(hv, sw[c * 3 + 0], a0);
        a1 = fmaf(hv, sw[c * 3 + 1], a1);
        a2 = fmaf(hv, sw[c * 3 + 2], a2);
    }
    #pragma unroll
    for (int off = 16; off; off >>= 1) {
        a0 += __shfl_down_sync(0xffffffffu, a0, off);
        a1 += __shfl_down_sync(0xffffffffu, a1, off);
        a2 += __shfl_down_sync(0xffffffffu, a2, off);
    }
    if (lane == 0) {
        out[i * 3 + 0] = a0 + bout[0];
        out[i * 3 + 1] = a1 + bout[1];
        out[i * 3 + 2] = a2 + bout[2];
    }
}

// -------------------------------------------------------------------------
extern "C" void kernel_launch(void* const* d_in, const int* in_sizes, int n_in,
                              void* d_out, int out_size) {
    const float* coords = (const float*)d_in[0];
    const float* tin  = (const float*)d_in[2];
    const float* Wgfp = (const float*)d_in[3];
    const float* Wt_  = (const float*)d_in[4];
    const float* bt_  = (const float*)d_in[5];
    const float* Win  = (const float*)d_in[6];
    const float* bin  = (const float*)d_in[7];
    const float* W1   = (const float*)d_in[8];
    const float* b1   = (const float*)d_in[9];
    const float* W2   = (const float*)d_in[10];
    const float* b2   = (const float*)d_in[11];
    const float* We   = (const float*)d_in[12];
    const float* be   = (const float*)d_in[13];
    const float* eps  = (const float*)d_in[14];
    const float* gnw  = (const float*)d_in[15];
    const float* gnb  = (const float*)d_in[16];
    const float* gnms = (const float*)d_in[17];
    const float* Wtl  = (const float*)d_in[18];
    const float* btl  = (const float*)d_in[19];
    const float* Wout = (const float*)d_in[20];
    const float* bout = (const float*)d_in[21];
    float* out = (float*)d_out;

    const int smem_edge = SMEM_EDGE_FLOATS * 4;
    cudaFuncSetAttribute(k_edge, cudaFuncAttributeMaxDynamicSharedMemorySize, smem_edge);

    k_temb<<<1, 128>>>(tin, Wgfp, Wt_, bt_);
    k_tproj<<<LL * BB, 256>>>(Wtl, btl);
    k_hin<<<NN, 256>>>(coords, Win, bin);
    k_nbr<<<NN / 4, 128>>>(coords);
    k_eattr<<<(NN * KK + 127) / 128, 128>>>(coords);
    k_afrag<<<NN / 4, 256>>>();
    k_befrag<<<dim3(4, LL), 256>>>(We);

    for (int l = 0; l < LL; l++) {
        k_edge<<<NN / 4, 256, smem_edge>>>(be + l * X2H, l);
        k_gemm<0><<<dim3(4, 64), 256>>>(W1 + (size_t)l * X2H * HH, b1 + l * HH, eps, l);
        k_gemm<1><<<dim3(4, 64), 256>>>(W2 + (size_t)l * HH * HH, b2 + l * HH, eps, l);
        k_gfin<<<64, 256>>>(gnw + l * HH, gnb + l * HH, gnms + l * HH);
    }
    k_out<<<NN / 8, 256>>>(Wout, bout, out);
}

// round 6
// speedup vs baseline: 1.3777x; 1.1040x over previous
#include <cuda_runtime.h>
#include <cuda_bf16.h>
#include <math.h>

#define NN     4096
#define BB     8
#define NPG    512
#define KK     30
#define NBASIS 32
#define EDIM   35      // NBASIS + 3
#define HH     256
#define X2H    512
#define TT     128
#define LL     5
#define RADIUS 1.5f

// ---------------- static scratch (no allocations allowed) ----------------
__device__ __align__(16) float d_tfeat[BB * TT];
__device__ __align__(16) float d_tproj[LL * BB * HH];
__device__ __align__(16) float d_h[NN * HH];
__device__ __align__(16) float d_aggr[NN * X2H];
__device__ __align__(16) float d_z1[NN * HH];
__device__ __align__(16) float d_z[NN * HH];
__device__ __align__(16) float d_eattr[NN * KK * 36];   // [edge][36], zeroed if invalid
// bf16x2-packed fragments, hi(3072 words) | lo(3072 words) per unit
__device__ __align__(16) unsigned d_afrag[(NN / 4) * 6144];   // per 4-node block
__device__ __align__(16) unsigned d_bfrag[LL * 4 * 6144];     // per (layer, col-chunk)
__device__ int   d_nbr[NN * KK];
__device__ int   d_cnt[NN];
__device__ __align__(16) float d_psum[64 * HH];   // gemm1 per-mblock col sums
__device__ __align__(16) float d_psumq[64 * HH];  // gemm1 per-mblock col sumsq

__device__ __forceinline__ float silu_f(float v) { return v / (1.f + expf(-v)); }

// ---------------- bf16 helpers ----------------
__device__ __forceinline__ unsigned pack_bf16x2(float a, float b) {
    __nv_bfloat162 h = __floats2bfloat162_rn(a, b);
    return *(unsigned*)&h;
}
__device__ __forceinline__ void mma_bf16(float* c, uint4 a, unsigned b0, unsigned b1) {
    asm volatile(
        "mma.sync.aligned.m16n8k16.row.col.f32.bf16.bf16.f32 "
        "{%0,%1,%2,%3}, {%4,%5,%6,%7}, {%8,%9}, {%0,%1,%2,%3};"
        : "+f"(c[0]), "+f"(c[1]), "+f"(c[2]), "+f"(c[3])
        : "r"(a.x), "r"(a.y), "r"(a.z), "r"(a.w), "r"(b0), "r"(b1));
}

// ---------------- time embedding ----------------
__global__ void k_temb(const float* __restrict__ tin, const float* __restrict__ wgfp,
                       const float* __restrict__ wt, const float* __restrict__ bt) {
    __shared__ float ss[64], sc[64];
    int t = threadIdx.x; // 128
    for (int b = 0; b < BB; b++) {
        if (t < 64) {
            float xp = 6.283185307179586f * tin[b] * wgfp[t];
            ss[t] = sinf(xp);
            sc[t] = cosf(xp);
        }
        __syncthreads();
        float acc = bt[t];
        #pragma unroll 8
        for (int h = 0; h < 64; h++) {
            acc = fmaf(ss[h], wt[h * TT + t], acc);
            acc = fmaf(sc[h], wt[(64 + h) * TT + t], acc);
        }
        d_tfeat[b * TT + t] = silu_f(acc);
        __syncthreads();
    }
}

__global__ void k_tproj(const float* __restrict__ Wt, const float* __restrict__ bt) {
    int l = blockIdx.x / BB, b = blockIdx.x % BB;
    int c = threadIdx.x; // 256
    __shared__ float tf[TT];
    if (c < TT) tf[c] = d_tfeat[b * TT + c];
    __syncthreads();
    float acc = bt[l * HH + c];
    const float* w = Wt + (size_t)l * TT * HH;
    #pragma unroll 8
    for (int k = 0; k < TT; k++) acc = fmaf(tf[k], w[k * HH + c], acc);
    d_tproj[(l * BB + b) * HH + c] = acc;
}

__global__ void k_hin(const float* __restrict__ coords, const float* __restrict__ Win,
                      const float* __restrict__ bin) {
    int i = blockIdx.x;
    int c = threadIdx.x;
    float x0 = coords[i * 3 + 0], x1 = coords[i * 3 + 1], x2 = coords[i * 3 + 2];
    float v = fmaf(x0, Win[c], fmaf(x1, Win[HH + c], fmaf(x2, Win[2 * HH + c], bin[c])));
    d_h[(size_t)i * HH + c] = v;
}

// ---------------- radius graph ----------------
__global__ void __launch_bounds__(128) k_nbr(const float* __restrict__ coords) {
    __shared__ float sx[NPG], sy[NPG], sz[NPG];
    __shared__ float sd[4][NPG];
    int t = threadIdx.x;
    int base = blockIdx.x * 4;
    int goff = (base >> 9) << 9;
    for (int j = t; j < NPG; j += 128) {
        sx[j] = coords[(goff + j) * 3 + 0];
        sy[j] = coords[(goff + j) * 3 + 1];
        sz[j] = coords[(goff + j) * 3 + 2];
    }
    __syncthreads();
    int w = t >> 5, lane = t & 31;
    int il = (base & 511) + w;
    int ig = goff + il;
    float xi = sx[il], yi = sy[il], zi = sz[il];
    float sqi = xi * xi + yi * yi + zi * zi;
    for (int j = lane; j < NPG; j += 32) {
        float xj = sx[j], yj = sy[j], zj = sz[j];
        float dot = xi * xj + yi * yj + zi * zj;
        float sqj = xj * xj + yj * yj + zj * zj;
        float d2 = sqi + sqj - 2.f * dot;
        float d = sqrtf(fmaxf(d2, 1e-12f));
        sd[w][j] = (j != il && d < RADIUS) ? d : INFINITY;
    }
    __syncwarp();
    int cc = 0;
    for (int k = 0; k < KK; k++) {
        float best = INFINITY;
        int bi = -1;
        for (int j = lane; j < NPG; j += 32) {
            float v = sd[w][j];
            if (v < best) { best = v; bi = j; }
        }
        #pragma unroll
        for (int off = 16; off; off >>= 1) {
            float ov = __shfl_down_sync(0xffffffffu, best, off);
            int oi = __shfl_down_sync(0xffffffffu, bi, off);
            if (ov < best || (ov == best && (unsigned)oi < (unsigned)bi)) { best = ov; bi = oi; }
        }
        best = __shfl_sync(0xffffffffu, best, 0);
        bi = __shfl_sync(0xffffffffu, bi, 0);
        if (!(best < INFINITY)) break;
        if (lane == 0) {
            d_nbr[ig * KK + k] = goff + bi;
            sd[w][bi] = INFINITY;
        }
        cc = k + 1;
        __syncwarp();
    }
    if (lane == 0) d_cnt[ig] = cc;
}

// ---------------- edge attributes (zero rows for invalid edges) -----------
__global__ void k_eattr(const float* __restrict__ coords) {
    int e = blockIdx.x * blockDim.x + threadIdx.x;
    if (e >= NN * KK) return;
    int i = e / KK, k = e % KK;
    float* o = d_eattr + (size_t)e * 36;
    if (k >= d_cnt[i]) {
        #pragma unroll
        for (int m = 0; m < 36; m++) o[m] = 0.f;
        return;
    }
    int s = d_nbr[e];
    float ex = coords[s * 3 + 0] - coords[i * 3 + 0];
    float ey = coords[s * 3 + 1] - coords[i * 3 + 1];
    float ez = coords[s * 3 + 2] - coords[i * 3 + 2];
    float d2 = ex * ex + ey * ey + ez * ez;
    float el = sqrtf(fmaxf(d2, 1e-12f));
    float inv = 1.f / el;
    const float step = RADIUS / 33.f;
    const float istep = 33.f / RADIUS;
    #pragma unroll
    for (int m = 0; m < NBASIS; m++) {
        float dd = (el - (float)(m + 1) * step) * istep;
        o[m] = expf(-dd * dd) * (1.f / 1.12f);
    }
    o[32] = ex * inv;
    o[33] = ey * inv;
    o[34] = ez * inv;
    o[35] = 0.f;
}

// ---------------- A fragments: eattr -> m16n8k16 bf16 hi/lo (per block) ---
// word idx = ((w*3+ks)*32+lane)*4 + r ; A elem pair:
//   row = 16w + 8*(r&1) + lane/4 ; k = ks*16 + 8*(r>>1) + 2*(lane&3) + {0,1}
__global__ void __launch_bounds__(256) k_afrag() {
    int blk = blockIdx.x;            // 1024 blocks of 4 nodes
    int i0 = blk * 4;
    unsigned* outp = d_afrag + (size_t)blk * 6144;
    for (int idx = threadIdx.x; idx < 3072; idx += 256) {
        int r = idx & 3;
        int lane = (idx >> 2) & 31;
        int ks = (idx >> 7) % 3;
        int w = idx / 384;
        int row = 16 * w + 8 * (r & 1) + (lane >> 2);
        int kb = ks * 16 + 8 * (r >> 1) + 2 * (lane & 3);
        int n = row >> 5, k = row & 31;
        float a0 = 0.f, a1 = 0.f;
        if (k < KK) {
            const float* e = d_eattr + (size_t)((i0 + n) * KK + k) * 36;
            if (kb < EDIM)     a0 = e[kb];
            if (kb + 1 < EDIM) a1 = e[kb + 1];
        }
        float h0 = __bfloat162float(__float2bfloat16_rn(a0));
        float h1 = __bfloat162float(__float2bfloat16_rn(a1));
        outp[idx]        = pack_bf16x2(h0, h1);
        outp[idx + 3072] = pack_bf16x2(a0 - h0, a1 - h1);
    }
}

// ---------------- B fragments: We -> m16n8k16 bf16 hi/lo (layer,chunk) ----
// word idx = ((ks*8+tp)*32+lane)*4 + q ; q = ts*2 + rb ; tile = 2*tp+ts
//   k = ks*16 + 8*rb + 2*(lane&3) + {0,1} ; col = cc*128 + tile*8 + lane/4
__global__ void __launch_bounds__(256) k_befrag(const float* __restrict__ We) {
    int cc = blockIdx.x, l = blockIdx.y;
    const float* w = We + (size_t)l * EDIM * X2H;
    unsigned* outp = d_bfrag + (size_t)(l * 4 + cc) * 6144;
    for (int idx = threadIdx.x; idx < 3072; idx += 256) {
        int q = idx & 3;
        int ts = q >> 1, rb = q & 1;
        int lane = (idx >> 2) & 31;
        int tp = (idx >> 7) & 7;
        int ks = idx >> 10;
        int tile = 2 * tp + ts;
        int kb = ks * 16 + 8 * rb + 2 * (lane & 3);
        int gcol = cc * 128 + tile * 8 + (lane >> 2);
        float b0 = (kb < EDIM)     ? w[kb * X2H + gcol]       : 0.f;
        float b1 = (kb + 1 < EDIM) ? w[(kb + 1) * X2H + gcol] : 0.f;
        float h0 = __bfloat162float(__float2bfloat16_rn(b0));
        float h1 = __bfloat162float(__float2bfloat16_rn(b1));
        outp[idx]        = pack_bf16x2(h0, h1);
        outp[idx + 3072] = pack_bf16x2(b0 - h0, b1 - h1);
    }
}

// ---------------- k_edge: bf16x2-split tensor GINE message+aggregate ------
// Block = 4 nodes (128 edge rows). 8 warps. Fragments precomputed in global.
// smem word offsets:
#define OFF_AF   0        // A hi|lo : 6144 words
#define OFF_BF   6144     // B hi|lo : 6144 words
#define OFF_PART 12288    // 8*128
#define OFF_STP  13312    // 256
#define OFF_SBE  13568    // 512
#define SMEM_EDGE_WORDS 14080

__global__ void __launch_bounds__(256) k_edge(const float* __restrict__ be, int l) {
    extern __shared__ float sm[];
    unsigned* Af = (unsigned*)sm + OFF_AF;      // hi at 0, lo at +3072
    unsigned* Bf = (unsigned*)sm + OFF_BF;      // hi at 0, lo at +3072
    float* part = sm + OFF_PART;
    float* stp = sm + OFF_STP;
    float* sbe = sm + OFF_SBE;
    __shared__ int ssrc[4][32];
    __shared__ int scnt[4];

    int t = threadIdx.x;
    int w = t >> 5, lane = t & 31;
    int i0 = blockIdx.x * 4;
    int g = i0 >> 9;

    if (t < 128) {
        int n = t >> 5, k = t & 31;
        int c = d_cnt[i0 + n];
        if (k == 0) scnt[n] = c;
        ssrc[n][k] = (k < c) ? d_nbr[(i0 + n) * KK + k] : (i0 + n);
    }
    stp[t] = d_tproj[(l * BB + g) * HH + t];  // t<256
    for (int c = t; c < X2H; c += 256) sbe[c] = be[c];

    // stage A fragments: contiguous uint4 copy (hi+lo = 1536 uint4)
    {
        const uint4* asrc = (const uint4*)(d_afrag + (size_t)blockIdx.x * 6144);
        uint4* adst = (uint4*)Af;
        for (int idx = t; idx < 1536; idx += 256) adst[idx] = asrc[idx];
    }
    __syncthreads();

    int node = w >> 1;
    int kbase = (w & 1) * 16;
    int cnt_n = scnt[node];

    for (int cc = 0; cc < 4; cc++) {
        // stage B fragments for this chunk
        {
            const uint4* bsrc = (const uint4*)(d_bfrag + (size_t)(l * 4 + cc) * 6144);
            uint4* bdst = (uint4*)Bf;
            for (int idx = t; idx < 1536; idx += 256) bdst[idx] = bsrc[idx];
        }
        __syncthreads();

        float acc[16][4];
        #pragma unroll
        for (int q = 0; q < 16; q++) {
            acc[q][0] = 0.f; acc[q][1] = 0.f; acc[q][2] = 0.f; acc[q][3] = 0.f;
        }
        #pragma unroll
        for (int ks = 0; ks < 3; ks++) {
            uint4 ah = *(const uint4*)&Af[((w * 3 + ks) * 32 + lane) * 4];
            uint4 al = *(const uint4*)&Af[3072 + ((w * 3 + ks) * 32 + lane) * 4];
            #pragma unroll
            for (int tp = 0; tp < 8; tp++) {
                uint4 bh = *(const uint4*)&Bf[((ks * 8 + tp) * 32 + lane) * 4];
                uint4 bl = *(const uint4*)&Bf[3072 + ((ks * 8 + tp) * 32 + lane) * 4];
                mma_bf16(acc[2 * tp + 0], ah, bh.x, bh.y);
                mma_bf16(acc[2 * tp + 0], al, bh.x, bh.y);
                mma_bf16(acc[2 * tp + 0], ah, bl.x, bl.y);
                mma_bf16(acc[2 * tp + 1], ah, bh.z, bh.w);
                mma_bf16(acc[2 * tp + 1], al, bh.z, bh.w);
                mma_bf16(acc[2 * tp + 1], ah, bl.z, bl.w);
            }
        }

        // epilogue: + be + x[src], relu, mask, reduce rows -> part[w][col]
        int k0 = kbase + (lane >> 2);
        int k1 = k0 + 8;
        bool v0 = k0 < cnt_n, v1 = k1 < cnt_n;
        int s0 = ssrc[node][k0 & 31], s1 = ssrc[node][k1 & 31];
        #pragma unroll
        for (int tile = 0; tile < 16; tile++) {
            int colb = tile * 8 + 2 * (lane & 3);
            int gcol = cc * 128 + colb;
            float2 be2 = *(const float2*)&sbe[gcol];
            float2 x0, x1;
            if (cc < 2) {
                x0 = *(const float2*)(d_h + (size_t)s0 * HH + gcol);
                x1 = *(const float2*)(d_h + (size_t)s1 * HH + gcol);
            } else {
                float2 tv = *(const float2*)&stp[gcol - HH];
                x0 = tv; x1 = tv;
            }
            float m00 = v0 ? fmaxf(acc[tile][0] + be2.x + x0.x, 0.f) : 0.f;
            float m01 = v0 ? fmaxf(acc[tile][1] + be2.y + x0.y, 0.f) : 0.f;
            float m10 = v1 ? fmaxf(acc[tile][2] + be2.x + x1.x, 0.f) : 0.f;
            float m11 = v1 ? fmaxf(acc[tile][3] + be2.y + x1.y, 0.f) : 0.f;
            float sA = m00 + m10;
            float sB = m01 + m11;
            #pragma unroll
            for (int off = 16; off >= 4; off >>= 1) {
                sA += __shfl_down_sync(0xffffffffu, sA, off);
                sB += __shfl_down_sync(0xffffffffu, sB, off);
            }
            if (lane < 4) {
                part[w * 128 + tile * 8 + 2 * lane] = sA;
                part[w * 128 + tile * 8 + 2 * lane + 1] = sB;
            }
        }
        __syncthreads();
        for (int q = t; q < 512; q += 256) {
            int n = q >> 7, c = q & 127;
            float s = part[(2 * n) * 128 + c] + part[(2 * n + 1) * 128 + c];
            d_aggr[(size_t)(i0 + n) * X2H + cc * 128 + c] = s;
        }
        __syncthreads();
    }
}

// ---------------- GEMM (64x64 FFMA tiles) ---------------------------------
// MODE0: z1 = silu(((1+eps)*[h|tproj] + aggr) @ W1 + b1)   K=512
// MODE1: z  = z1 @ W2 + b2 (+ GraphNorm partial col stats)  K=256
template <int MODE>
__global__ void __launch_bounds__(256) k_gemm(const float* __restrict__ Bw,
                                              const float* __restrict__ bias,
                                              const float* __restrict__ epsp, int l) {
    const int Kd = (MODE == 0) ? X2H : HH;
    const int Nd = HH;
    __shared__ float As[16][64];
    __shared__ float Bs[16][64];
    __shared__ float stp[HH];
    int t = threadIdx.x;
    int m0 = blockIdx.y * 64, n0 = blockIdx.x * 64;
    int g = m0 >> 9;
    int ty = t >> 4, tx = t & 15;
    int ar = t >> 2, akc = (t & 3) * 4;
    int br = t >> 4, bnc = (t & 15) * 4;
    float ep = (MODE == 0) ? (1.f + epsp[l]) : 0.f;
    if (MODE == 0 && t < HH) stp[t] = d_tproj[(l * BB + g) * HH + t];
    __syncthreads();
    float acc[4][4];
    #pragma unroll
    for (int i = 0; i < 4; i++)
        #pragma unroll
        for (int j = 0; j < 4; j++) acc[i][j] = 0.f;
    for (int k0 = 0; k0 < Kd; k0 += 16) {
        int kg = k0 + akc;
        float4 av;
        if (MODE == 0) {
            float4 g4 = *(const float4*)(d_aggr + (size_t)(m0 + ar) * X2H + kg);
            float4 hx;
            if (kg < HH) hx = *(const float4*)(d_h + (size_t)(m0 + ar) * HH + kg);
            else         hx = *(const float4*)(stp + (kg - HH));
            av.x = fmaf(ep, hx.x, g4.x);
            av.y = fmaf(ep, hx.y, g4.y);
            av.z = fmaf(ep, hx.z, g4.z);
            av.w = fmaf(ep, hx.w, g4.w);
        } else {
            av = *(const float4*)(d_z1 + (size_t)(m0 + ar) * HH + kg);
        }
        As[akc + 0][ar] = av.x;
        As[akc + 1][ar] = av.y;
        As[akc + 2][ar] = av.z;
        As[akc + 3][ar] = av.w;
        *(float4*)&Bs[br][bnc] = *(const float4*)(Bw + (size_t)(k0 + br) * Nd + n0 + bnc);
        __syncthreads();
        #pragma unroll
        for (int kk = 0; kk < 16; kk++) {
            float4 a4 = *(const float4*)&As[kk][ty * 4];
            float4 b4 = *(const float4*)&Bs[kk][tx * 4];
            acc[0][0] = fmaf(a4.x, b4.x, acc[0][0]); acc[0][1] = fmaf(a4.x, b4.y, acc[0][1]);
            acc[0][2] = fmaf(a4.x, b4.z, acc[0][2]); acc[0][3] = fmaf(a4.x, b4.w, acc[0][3]);
            acc[1][0] = fmaf(a4.y, b4.x, acc[1][0]); acc[1][1] = fmaf(a4.y, b4.y, acc[1][1]);
            acc[1][2] = fmaf(a4.y, b4.z, acc[1][2]); acc[1][3] = fmaf(a4.y, b4.w, acc[1][3]);
            acc[2][0] = fmaf(a4.z, b4.x, acc[2][0]); acc[2][1] = fmaf(a4.z, b4.y, acc[2][1]);
            acc[2][2] = fmaf(a4.z, b4.z, acc[2][2]); acc[2][3] = fmaf(a4.z, b4.w, acc[2][3]);
            acc[3][0] = fmaf(a4.w, b4.x, acc[3][0]); acc[3][1] = fmaf(a4.w, b4.y, acc[3][1]);
            acc[3][2] = fmaf(a4.w, b4.z, acc[3][2]); acc[3][3] = fmaf(a4.w, b4.w, acc[3][3]);
        }
        __syncthreads();
    }
    float* C = (MODE == 0) ? d_z1 : d_z;
    float s[4] = {0.f, 0.f, 0.f, 0.f};
    float q[4] = {0.f, 0.f, 0.f, 0.f};
    #pragma unroll
    for (int i = 0; i < 4; i++) {
        int row = m0 + ty * 4 + i;
        #pragma unroll
        for (int j = 0; j < 4; j++) {
            int col = n0 + tx * 4 + j;
            float v = acc[i][j] + bias[col];
            if (MODE == 0) v = silu_f(v);
            else { s[j] += v; q[j] = fmaf(v, v, q[j]); }
            C[(size_t)row * Nd + col] = v;
        }
    }
    if (MODE == 1) {
        #pragma unroll
        for (int j = 0; j < 4; j++) { As[ty][tx * 4 + j] = s[j]; Bs[ty][tx * 4 + j] = q[j]; }
        __syncthreads();
        if (t < 64) {
            float S = 0.f, Q = 0.f;
            #pragma unroll
            for (int p = 0; p < 16; p++) { S += As[p][t]; Q += Bs[p][t]; }
            d_psum[blockIdx.y * HH + n0 + t] = S;
            d_psumq[blockIdx.y * HH + n0 + t] = Q;
        }
    }
}

// ---------------- GraphNorm finalize (folds gemm1 partials) ---------------
__global__ void k_gfin(const float* __restrict__ gw, const float* __restrict__ gb,
                       const float* __restrict__ gms) {
    int nb = blockIdx.x * 64;
    int g = nb >> 9;
    int c = threadIdx.x;
    float s = 0.f, q = 0.f;
    #pragma unroll
    for (int p = 0; p < 8; p++) {
        s += d_psum[(g * 8 + p) * HH + c];
        q += d_psumq[(g * 8 + p) * HH + c];
    }
    float mean = s * (1.f / 512.f);
    float ez2  = q * (1.f / 512.f);
    float mm = mean * gms[c];
    float var = ez2 - 2.f * mm * mean + mm * mm;
    float inv = 1.f / sqrtf(var + 1e-5f);
    float w = gw[c], b = gb[c];
    for (int n = 0; n < 64; n++) {
        size_t id = (size_t)(nb + n) * HH + c;
        float cc = d_z[id] - mm;
        float zn = fmaf(w * cc, inv, b);
        float hv = zn + d_h[id];
        d_h[id] = silu_f(hv);
    }
}

// ---------------- output head ----------------
__global__ void k_out(const float* __restrict__ Wout, const float* __restrict__ bout,
                      float* __restrict__ out) {
    __shared__ float sw[HH * 3];
    int t = threadIdx.x;
    for (int idx = t; idx < HH * 3; idx += 256) sw[idx] = Wout[idx];
    __syncthreads();
    int w = t >> 5, lane = t & 31;
    int i = blockIdx.x * 8 + w;
    float a0 = 0.f, a1 = 0.f, a2 = 0.f;
    for (int c = lane; c < HH; c += 32) {
        float hv = d_h[(size_t)i * HH + c];
        a0 = fmaf(hv, sw[c * 3 + 0], a0);
        a1 = fmaf(hv, sw[c * 3 + 1], a1);
        a2 = fmaf(hv, sw[c * 3 + 2], a2);
    }
    #pragma unroll
    for (int off = 16; off; off >>= 1) {
        a0 += __shfl_down_sync(0xffffffffu, a0, off);
        a1 += __shfl_down_sync(0xffffffffu, a1, off);
        a2 += __shfl_down_sync(0xffffffffu, a2, off);
    }
    if (lane == 0) {
        out[i * 3 + 0] = a0 + bout[0];
        out[i * 3 + 1] = a1 + bout[1];
        out[i * 3 + 2] = a2 + bout[2];
    }
}

// -------------------------------------------------------------------------
extern "C" void kernel_launch(void* const* d_in, const int* in_sizes, int n_in,
                              void* d_out, int out_size) {
    const float* coords = (const float*)d_in[0];
    const float* tin  = (const float*)d_in[2];
    const float* Wgfp = (const float*)d_in[3];
    const float* Wt_  = (const float*)d_in[4];
    const float* bt_  = (const float*)d_in[5];
    const float* Win  = (const float*)d_in[6];
    const float* bin  = (const float*)d_in[7];
    const float* W1   = (const float*)d_in[8];
    const float* b1   = (const float*)d_in[9];
    const float* W2   = (const float*)d_in[10];
    const float* b2   = (const float*)d_in[11];
    const float* We   = (const float*)d_in[12];
    const float* be   = (const float*)d_in[13];
    const float* eps  = (const float*)d_in[14];
    const float* gnw  = (const float*)d_in[15];
    const float* gnb  = (const float*)d_in[16];
    const float* gnms = (const float*)d_in[17];
    const float* Wtl  = (const float*)d_in[18];
    const float* btl  = (const float*)d_in[19];
    const float* Wout = (const float*)d_in[20];
    const float* bout = (const float*)d_in[21];
    float* out = (float*)d_out;

    const int smem_edge = SMEM_EDGE_WORDS * 4;
    cudaFuncSetAttribute(k_edge, cudaFuncAttributeMaxDynamicSharedMemorySize, smem_edge);

    k_temb<<<1, 128>>>(tin, Wgfp, Wt_, bt_);
    k_tproj<<<LL * BB, 256>>>(Wtl, btl);
    k_hin<<<NN, 256>>>(coords, Win, bin);
    k_nbr<<<NN / 4, 128>>>(coords);
    k_eattr<<<(NN * KK + 127) / 128, 128>>>(coords);
    k_afrag<<<NN / 4, 256>>>();
    k_befrag<<<dim3(4, LL), 256>>>(We);

    for (int l = 0; l < LL; l++) {
        k_edge<<<NN / 4, 256, smem_edge>>>(be + l * X2H, l);
        k_gemm<0><<<dim3(4, 64), 256>>>(W1 + (size_t)l * X2H * HH, b1 + l * HH, eps, l);
        k_gemm<1><<<dim3(4, 64), 256>>>(W2 + (size_t)l * HH * HH, b2 + l * HH, eps, l);
        k_gfin<<<64, 256>>>(gnw + l * HH, gnb + l * HH, gnms + l * HH);
    }
    k_out<<<NN / 8, 256>>>(Wout, bout, out);
}

// round 7
// speedup vs baseline: 1.5642x; 1.1354x over previous
#include <cuda_runtime.h>
#include <cuda_bf16.h>
#include <math.h>

#define NN     4096
#define BB     8
#define NPG    512
#define KK     30
#define NBASIS 32
#define EDIM   35      // NBASIS + 3
#define HH     256
#define X2H    512
#define TT     128
#define LL     5
#define RADIUS 1.5f

// ---------------- static scratch (no allocations allowed) ----------------
__device__ __align__(16) float d_tfeat[BB * TT];
__device__ __align__(16) float d_tproj[LL * BB * HH];
__device__ __align__(16) float d_h[NN * HH];
__device__ __align__(16) float d_aggr[NN * X2H];
__device__ __align__(16) float d_z1[NN * HH];
__device__ __align__(16) float d_z[NN * HH];
// bf16x2-packed fragments, hi(3072 words) | lo(3072 words) per unit
__device__ __align__(16) unsigned d_afrag[(NN / 4) * 6144];   // per 4-node block
__device__ __align__(16) unsigned d_bfrag[LL * 4 * 6144];     // per (layer, col-chunk)
__device__ int   d_nbr[NN * KK];
__device__ int   d_cnt[NN];
__device__ float d_elen[NN * KK];
__device__ __align__(16) float d_psum[64 * HH];   // gemm1 per-mblock col sums
__device__ __align__(16) float d_psumq[64 * HH];  // gemm1 per-mblock col sumsq

__device__ __forceinline__ float silu_f(float v) { return v / (1.f + expf(-v)); }

// ---------------- bf16 helpers ----------------
__device__ __forceinline__ unsigned pack_bf16x2(float a, float b) {
    __nv_bfloat162 h = __floats2bfloat162_rn(a, b);
    return *(unsigned*)&h;
}
__device__ __forceinline__ void mma_bf16(float* c, uint4 a, unsigned b0, unsigned b1) {
    asm volatile(
        "mma.sync.aligned.m16n8k16.row.col.f32.bf16.bf16.f32 "
        "{%0,%1,%2,%3}, {%4,%5,%6,%7}, {%8,%9}, {%0,%1,%2,%3};"
        : "+f"(c[0]), "+f"(c[1]), "+f"(c[2]), "+f"(c[3])
        : "r"(a.x), "r"(a.y), "r"(a.z), "r"(a.w), "r"(b0), "r"(b1));
}

// ---------------- time embedding ----------------
__global__ void k_temb(const float* __restrict__ tin, const float* __restrict__ wgfp,
                       const float* __restrict__ wt, const float* __restrict__ bt) {
    __shared__ float ss[64], sc[64];
    int t = threadIdx.x; // 128
    for (int b = 0; b < BB; b++) {
        if (t < 64) {
            float xp = 6.283185307179586f * tin[b] * wgfp[t];
            ss[t] = sinf(xp);
            sc[t] = cosf(xp);
        }
        __syncthreads();
        float acc = bt[t];
        #pragma unroll 8
        for (int h = 0; h < 64; h++) {
            acc = fmaf(ss[h], wt[h * TT + t], acc);
            acc = fmaf(sc[h], wt[(64 + h) * TT + t], acc);
        }
        d_tfeat[b * TT + t] = silu_f(acc);
        __syncthreads();
    }
}

__global__ void k_tproj(const float* __restrict__ Wt, const float* __restrict__ bt) {
    int l = blockIdx.x / BB, b = blockIdx.x % BB;
    int c = threadIdx.x; // 256
    __shared__ float tf[TT];
    if (c < TT) tf[c] = d_tfeat[b * TT + c];
    __syncthreads();
    float acc = bt[l * HH + c];
    const float* w = Wt + (size_t)l * TT * HH;
    #pragma unroll 8
    for (int k = 0; k < TT; k++) acc = fmaf(tf[k], w[k * HH + c], acc);
    d_tproj[(l * BB + b) * HH + c] = acc;
}

__global__ void k_hin(const float* __restrict__ coords, const float* __restrict__ Win,
                      const float* __restrict__ bin) {
    int i = blockIdx.x;
    int c = threadIdx.x;
    float x0 = coords[i * 3 + 0], x1 = coords[i * 3 + 1], x2 = coords[i * 3 + 2];
    float v = fmaf(x0, Win[c], fmaf(x1, Win[HH + c], fmaf(x2, Win[2 * HH + c], bin[c])));
    d_h[(size_t)i * HH + c] = v;
}

// ---------------- radius graph (stores selected distances too) ------------
__global__ void __launch_bounds__(128) k_nbr(const float* __restrict__ coords) {
    __shared__ float sx[NPG], sy[NPG], sz[NPG];
    __shared__ float sd[4][NPG];
    int t = threadIdx.x;
    int base = blockIdx.x * 4;
    int goff = (base >> 9) << 9;
    for (int j = t; j < NPG; j += 128) {
        sx[j] = coords[(goff + j) * 3 + 0];
        sy[j] = coords[(goff + j) * 3 + 1];
        sz[j] = coords[(goff + j) * 3 + 2];
    }
    __syncthreads();
    int w = t >> 5, lane = t & 31;
    int il = (base & 511) + w;
    int ig = goff + il;
    float xi = sx[il], yi = sy[il], zi = sz[il];
    float sqi = xi * xi + yi * yi + zi * zi;
    for (int j = lane; j < NPG; j += 32) {
        float xj = sx[j], yj = sy[j], zj = sz[j];
        float dot = xi * xj + yi * yj + zi * zj;
        float sqj = xj * xj + yj * yj + zj * zj;
        float d2 = sqi + sqj - 2.f * dot;
        float d = sqrtf(fmaxf(d2, 1e-12f));
        sd[w][j] = (j != il && d < RADIUS) ? d : INFINITY;
    }
    __syncwarp();
    int cc = 0;
    for (int k = 0; k < KK; k++) {
        float best = INFINITY;
        int bi = -1;
        for (int j = lane; j < NPG; j += 32) {
            float v = sd[w][j];
            if (v < best) { best = v; bi = j; }
        }
        #pragma unroll
        for (int off = 16; off; off >>= 1) {
            float ov = __shfl_down_sync(0xffffffffu, best, off);
            int oi = __shfl_down_sync(0xffffffffu, bi, off);
            if (ov < best || (ov == best && (unsigned)oi < (unsigned)bi)) { best = ov; bi = oi; }
        }
        best = __shfl_sync(0xffffffffu, best, 0);
        bi = __shfl_sync(0xffffffffu, bi, 0);
        if (!(best < INFINITY)) break;
        if (lane == 0) {
            d_nbr[ig * KK + k] = goff + bi;
            d_elen[ig * KK + k] = best;
            sd[w][bi] = INFINITY;
        }
        cc = k + 1;
        __syncwarp();
    }
    if (lane == 0) d_cnt[ig] = cc;
}

// ---------------- A fragments: edge attrs computed directly ---------------
// word idx = ((mg*3+ks)*32+lane)*4 + r ; elem pair:
//   row = 16mg + 8*(r&1) + lane/4 ; kb = ks*16 + 8*(r>>1) + 2*(lane&3)
// feature kb<32: gaussian(elen); 32-34: unit dir; 35: 1.0 (bias feature)
__global__ void __launch_bounds__(256) k_afrag(const float* __restrict__ coords) {
    int blk = blockIdx.x;            // 1024 blocks of 4 nodes
    int i0 = blk * 4;
    unsigned* outp = d_afrag + (size_t)blk * 6144;
    const float step = RADIUS / 33.f;
    const float istep = 33.f / RADIUS;
    for (int idx = threadIdx.x; idx < 3072; idx += 256) {
        int r = idx & 3;
        int lane = (idx >> 2) & 31;
        int ks = (idx >> 7) % 3;
        int mg = idx / 384;
        int row = 16 * mg + 8 * (r & 1) + (lane >> 2);
        int kb = ks * 16 + 8 * (r >> 1) + 2 * (lane & 3);
        int n = row >> 5, k = row & 31;
        int node = i0 + n;
        float a0 = 0.f, a1 = 0.f;
        if (k < d_cnt[node] && kb < 36) {
            float el = d_elen[node * KK + k];
            if (kb < 32) {
                float d0 = (el - (float)(kb + 1) * step) * istep;
                float d1 = (el - (float)(kb + 2) * step) * istep;
                a0 = expf(-d0 * d0) * (1.f / 1.12f);
                a1 = expf(-d1 * d1) * (1.f / 1.12f);
            } else {
                int s = d_nbr[node * KK + k];
                float inv = 1.f / el;
                float ex = coords[s * 3 + 0] - coords[node * 3 + 0];
                float ey = coords[s * 3 + 1] - coords[node * 3 + 1];
                float ez = coords[s * 3 + 2] - coords[node * 3 + 2];
                if (kb == 32) { a0 = ex * inv; a1 = ey * inv; }
                else          { a0 = ez * inv; a1 = 1.0f; }   // kb == 34
            }
        }
        float h0 = __bfloat162float(__float2bfloat16_rn(a0));
        float h1 = __bfloat162float(__float2bfloat16_rn(a1));
        outp[idx]        = pack_bf16x2(h0, h1);
        outp[idx + 3072] = pack_bf16x2(a0 - h0, a1 - h1);
    }
}

// ---------------- B fragments: We (+be as row 35) -> bf16 hi/lo ----------
__global__ void __launch_bounds__(256) k_befrag(const float* __restrict__ We,
                                                const float* __restrict__ be) {
    int cc = blockIdx.x, l = blockIdx.y;
    const float* w = We + (size_t)l * EDIM * X2H;
    const float* bp = be + (size_t)l * X2H;
    unsigned* outp = d_bfrag + (size_t)(l * 4 + cc) * 6144;
    for (int idx = threadIdx.x; idx < 3072; idx += 256) {
        int q = idx & 3;
        int ts = q >> 1, rb = q & 1;
        int lane = (idx >> 2) & 31;
        int tp = (idx >> 7) & 7;
        int ks = idx >> 10;
        int tile = 2 * tp + ts;
        int kb = ks * 16 + 8 * rb + 2 * (lane & 3);
        int gcol = cc * 128 + tile * 8 + (lane >> 2);
        float b0 = (kb < EDIM) ? w[kb * X2H + gcol] : ((kb == 35) ? bp[gcol] : 0.f);
        int kb1 = kb + 1;
        float b1 = (kb1 < EDIM) ? w[kb1 * X2H + gcol] : ((kb1 == 35) ? bp[gcol] : 0.f);
        float h0 = __bfloat162float(__float2bfloat16_rn(b0));
        float h1 = __bfloat162float(__float2bfloat16_rn(b1));
        outp[idx]        = pack_bf16x2(h0, h1);
        outp[idx + 3072] = pack_bf16x2(b0 - h0, b1 - h1);
    }
}

// ---------------- k_edge: warp-per-node bf16-split tensor GINE ------------
// Block = 4 nodes (128 edge rows). Warp w -> (node w&3, col-half w>>2):
// 2 m-tiles x 8 n-tiles. Node reduction fully intra-warp -> direct STG.
#define OFF_AF   0        // A hi|lo : 6144 words
#define OFF_BF   6144     // B hi|lo : 6144 words
#define OFF_STP  12288    // 256
#define SMEM_EDGE_WORDS 12544

__global__ void __launch_bounds__(256) k_edge(int l) {
    extern __shared__ float sm[];
    unsigned* Af = (unsigned*)sm + OFF_AF;
    unsigned* Bf = (unsigned*)sm + OFF_BF;
    float* stp = sm + OFF_STP;
    __shared__ int ssrc[4][32];
    __shared__ int scnt[4];

    int t = threadIdx.x;
    int w = t >> 5, lane = t & 31;
    int i0 = blockIdx.x * 4;
    int g = i0 >> 9;

    if (t < 128) {
        int n = t >> 5, k = t & 31;
        int c = d_cnt[i0 + n];
        if (k == 0) scnt[n] = c;
        ssrc[n][k] = (k < c) ? d_nbr[(i0 + n) * KK + k] : (i0 + n);
    }
    stp[t] = d_tproj[(l * BB + g) * HH + t];  // t<256

    // stage A fragments: contiguous uint4 copy
    {
        const uint4* asrc = (const uint4*)(d_afrag + (size_t)blockIdx.x * 6144);
        uint4* adst = (uint4*)Af;
        for (int idx = t; idx < 1536; idx += 256) adst[idx] = asrc[idx];
    }
    __syncthreads();

    int node = w & 3, half = w >> 2;
    int cnt_n = scnt[node];
    int rr = lane >> 2;
    int s0 = ssrc[node][rr],      s1 = ssrc[node][rr + 8];
    int s2 = ssrc[node][rr + 16], s3 = ssrc[node][rr + 24];
    float mk0 = (rr      < cnt_n) ? 1.f : 0.f;
    float mk1 = (rr + 8  < cnt_n) ? 1.f : 0.f;
    float mk2 = (rr + 16 < cnt_n) ? 1.f : 0.f;
    float mk3 = (rr + 24 < cnt_n) ? 1.f : 0.f;
    int mg0 = 2 * node, mg1 = 2 * node + 1;

    for (int cc = 0; cc < 4; cc++) {
        {
            const uint4* bsrc = (const uint4*)(d_bfrag + (size_t)(l * 4 + cc) * 6144);
            uint4* bdst = (uint4*)Bf;
            for (int idx = t; idx < 1536; idx += 256) bdst[idx] = bsrc[idx];
        }
        __syncthreads();

        float acc[2][8][4];
        #pragma unroll
        for (int m = 0; m < 2; m++)
            #pragma unroll
            for (int q = 0; q < 8; q++) {
                acc[m][q][0] = 0.f; acc[m][q][1] = 0.f;
                acc[m][q][2] = 0.f; acc[m][q][3] = 0.f;
            }
        #pragma unroll
        for (int ks = 0; ks < 3; ks++) {
            uint4 ah0 = *(const uint4*)&Af[((mg0 * 3 + ks) * 32 + lane) * 4];
            uint4 al0 = *(const uint4*)&Af[3072 + ((mg0 * 3 + ks) * 32 + lane) * 4];
            uint4 ah1 = *(const uint4*)&Af[((mg1 * 3 + ks) * 32 + lane) * 4];
            uint4 al1 = *(const uint4*)&Af[3072 + ((mg1 * 3 + ks) * 32 + lane) * 4];
            #pragma unroll
            for (int tt = 0; tt < 4; tt++) {
                int tp = half * 4 + tt;
                uint4 bh = *(const uint4*)&Bf[((ks * 8 + tp) * 32 + lane) * 4];
                uint4 bl = *(const uint4*)&Bf[3072 + ((ks * 8 + tp) * 32 + lane) * 4];
                mma_bf16(acc[0][2 * tt + 0], ah0, bh.x, bh.y);
                mma_bf16(acc[0][2 * tt + 0], al0, bh.x, bh.y);
                mma_bf16(acc[0][2 * tt + 0], ah0, bl.x, bl.y);
                mma_bf16(acc[0][2 * tt + 1], ah0, bh.z, bh.w);
                mma_bf16(acc[0][2 * tt + 1], al0, bh.z, bh.w);
                mma_bf16(acc[0][2 * tt + 1], ah0, bl.z, bl.w);
                mma_bf16(acc[1][2 * tt + 0], ah1, bh.x, bh.y);
                mma_bf16(acc[1][2 * tt + 0], al1, bh.x, bh.y);
                mma_bf16(acc[1][2 * tt + 0], ah1, bl.x, bl.y);
                mma_bf16(acc[1][2 * tt + 1], ah1, bh.z, bh.w);
                mma_bf16(acc[1][2 * tt + 1], al1, bh.z, bh.w);
                mma_bf16(acc[1][2 * tt + 1], ah1, bl.z, bl.w);
            }
        }
        __syncthreads();   // B consumed; next chunk may restage

        // epilogue: + x[src], relu, mask, intra-warp reduce, direct store
        #pragma unroll
        for (int nt = 0; nt < 8; nt++) {
            int gcol = cc * 128 + half * 64 + nt * 8 + 2 * (lane & 3);
            float2 x0, x1, x2, x3;
            if (cc < 2) {
                x0 = *(const float2*)(d_h + (size_t)s0 * HH + gcol);
                x1 = *(const float2*)(d_h + (size_t)s1 * HH + gcol);
                x2 = *(const float2*)(d_h + (size_t)s2 * HH + gcol);
                x3 = *(const float2*)(d_h + (size_t)s3 * HH + gcol);
            } else {
                float2 tv = *(const float2*)&stp[gcol - HH];
                x0 = tv; x1 = tv; x2 = tv; x3 = tv;
            }
            float sA = mk0 * fmaxf(acc[0][nt][0] + x0.x, 0.f);
            sA = fmaf(mk1, fmaxf(acc[0][nt][2] + x1.x, 0.f), sA);
            sA = fmaf(mk2, fmaxf(acc[1][nt][0] + x2.x, 0.f), sA);
            sA = fmaf(mk3, fmaxf(acc[1][nt][2] + x3.x, 0.f), sA);
            float sB = mk0 * fmaxf(acc[0][nt][1] + x0.y, 0.f);
            sB = fmaf(mk1, fmaxf(acc[0][nt][3] + x1.y, 0.f), sB);
            sB = fmaf(mk2, fmaxf(acc[1][nt][1] + x2.y, 0.f), sB);
            sB = fmaf(mk3, fmaxf(acc[1][nt][3] + x3.y, 0.f), sB);
            #pragma unroll
            for (int off = 16; off >= 4; off >>= 1) {
                sA += __shfl_down_sync(0xffffffffu, sA, off);
                sB += __shfl_down_sync(0xffffffffu, sB, off);
            }
            if (lane < 4) {
                int gc = cc * 128 + half * 64 + nt * 8 + 2 * lane;
                *(float2*)(d_aggr + (size_t)(i0 + node) * X2H + gc) = make_float2(sA, sB);
            }
        }
    }
}

// ---------------- GEMM (64x64 FFMA tiles) ---------------------------------
// MODE0: z1 = silu(((1+eps)*[h|tproj] + aggr) @ W1 + b1)   K=512
// MODE1: z  = z1 @ W2 + b2 (+ GraphNorm partial col stats)  K=256
template <int MODE>
__global__ void __launch_bounds__(256) k_gemm(const float* __restrict__ Bw,
                                              const float* __restrict__ bias,
                                              const float* __restrict__ epsp, int l) {
    const int Kd = (MODE == 0) ? X2H : HH;
    const int Nd = HH;
    __shared__ float As[16][64];
    __shared__ float Bs[16][64];
    __shared__ float stp[HH];
    int t = threadIdx.x;
    int m0 = blockIdx.y * 64, n0 = blockIdx.x * 64;
    int g = m0 >> 9;
    int ty = t >> 4, tx = t & 15;
    int ar = t >> 2, akc = (t & 3) * 4;
    int br = t >> 4, bnc = (t & 15) * 4;
    float ep = (MODE == 0) ? (1.f + epsp[l]) : 0.f;
    if (MODE == 0 && t < HH) stp[t] = d_tproj[(l * BB + g) * HH + t];
    __syncthreads();
    float acc[4][4];
    #pragma unroll
    for (int i = 0; i < 4; i++)
        #pragma unroll
        for (int j = 0; j < 4; j++) acc[i][j] = 0.f;
    for (int k0 = 0; k0 < Kd; k0 += 16) {
        int kg = k0 + akc;
        float4 av;
        if (MODE == 0) {
            float4 g4 = *(const float4*)(d_aggr + (size_t)(m0 + ar) * X2H + kg);
            float4 hx;
            if (kg < HH) hx = *(const float4*)(d_h + (size_t)(m0 + ar) * HH + kg);
            else         hx = *(const float4*)(stp + (kg - HH));
            av.x = fmaf(ep, hx.x, g4.x);
            av.y = fmaf(ep, hx.y, g4.y);
            av.z = fmaf(ep, hx.z, g4.z);
            av.w = fmaf(ep, hx.w, g4.w);
        } else {
            av = *(const float4*)(d_z1 + (size_t)(m0 + ar) * HH + kg);
        }
        As[akc + 0][ar] = av.x;
        As[akc + 1][ar] = av.y;
        As[akc + 2][ar] = av.z;
        As[akc + 3][ar] = av.w;
        *(float4*)&Bs[br][bnc] = *(const float4*)(Bw + (size_t)(k0 + br) * Nd + n0 + bnc);
        __syncthreads();
        #pragma unroll
        for (int kk = 0; kk < 16; kk++) {
            float4 a4 = *(const float4*)&As[kk][ty * 4];
            float4 b4 = *(const float4*)&Bs[kk][tx * 4];
            acc[0][0] = fmaf(a4.x, b4.x, acc[0][0]); acc[0][1] = fmaf(a4.x, b4.y, acc[0][1]);
            acc[0][2] = fmaf(a4.x, b4.z, acc[0][2]); acc[0][3] = fmaf(a4.x, b4.w, acc[0][3]);
            acc[1][0] = fmaf(a4.y, b4.x, acc[1][0]); acc[1][1] = fmaf(a4.y, b4.y, acc[1][1]);
            acc[1][2] = fmaf(a4.y, b4.z, acc[1][2]); acc[1][3] = fmaf(a4.y, b4.w, acc[1][3]);
            acc[2][0] = fmaf(a4.z, b4.x, acc[2][0]); acc[2][1] = fmaf(a4.z, b4.y, acc[2][1]);
            acc[2][2] = fmaf(a4.z, b4.z, acc[2][2]); acc[2][3] = fmaf(a4.z, b4.w, acc[2][3]);
            acc[3][0] = fmaf(a4.w, b4.x, acc[3][0]); acc[3][1] = fmaf(a4.w, b4.y, acc[3][1]);
            acc[3][2] = fmaf(a4.w, b4.z, acc[3][2]); acc[3][3] = fmaf(a4.w, b4.w, acc[3][3]);
        }
        __syncthreads();
    }
    float* C = (MODE == 0) ? d_z1 : d_z;
    float s[4] = {0.f, 0.f, 0.f, 0.f};
    float q[4] = {0.f, 0.f, 0.f, 0.f};
    #pragma unroll
    for (int i = 0; i < 4; i++) {
        int row = m0 + ty * 4 + i;
        #pragma unroll
        for (int j = 0; j < 4; j++) {
            int col = n0 + tx * 4 + j;
            float v = acc[i][j] + bias[col];
            if (MODE == 0) v = silu_f(v);
            else { s[j] += v; q[j] = fmaf(v, v, q[j]); }
            C[(size_t)row * Nd + col] = v;
        }
    }
    if (MODE == 1) {
        #pragma unroll
        for (int j = 0; j < 4; j++) { As[ty][tx * 4 + j] = s[j]; Bs[ty][tx * 4 + j] = q[j]; }
        __syncthreads();
        if (t < 64) {
            float S = 0.f, Q = 0.f;
            #pragma unroll
            for (int p = 0; p < 16; p++) { S += As[p][t]; Q += Bs[p][t]; }
            d_psum[blockIdx.y * HH + n0 + t] = S;
            d_psumq[blockIdx.y * HH + n0 + t] = Q;
        }
    }
}

// ---------------- GraphNorm finalize (folds gemm1 partials) ---------------
__global__ void k_gfin(const float* __restrict__ gw, const float* __restrict__ gb,
                       const float* __restrict__ gms) {
    int nb = blockIdx.x * 64;
    int g = nb >> 9;
    int c = threadIdx.x;
    float s = 0.f, q = 0.f;
    #pragma unroll
    for (int p = 0; p < 8; p++) {
        s += d_psum[(g * 8 + p) * HH + c];
        q += d_psumq[(g * 8 + p) * HH + c];
    }
    float mean = s * (1.f / 512.f);
    float ez2  = q * (1.f / 512.f);
    float mm = mean * gms[c];
    float var = ez2 - 2.f * mm * mean + mm * mm;
    float inv = 1.f / sqrtf(var + 1e-5f);
    float w = gw[c], b = gb[c];
    for (int n = 0; n < 64; n++) {
        size_t id = (size_t)(nb + n) * HH + c;
        float cc = d_z[id] - mm;
        float zn = fmaf(w * cc, inv, b);
        float hv = zn + d_h[id];
        d_h[id] = silu_f(hv);
    }
}

// ---------------- output head ----------------
__global__ void k_out(const float* __restrict__ Wout, const float* __restrict__ bout,
                      float* __restrict__ out) {
    __shared__ float sw[HH * 3];
    int t = threadIdx.x;
    for (int idx = t; idx < HH * 3; idx += 256) sw[idx] = Wout[idx];
    __syncthreads();
    int w = t >> 5, lane = t & 31;
    int i = blockIdx.x * 8 + w;
    float a0 = 0.f, a1 = 0.f, a2 = 0.f;
    for (int c = lane; c < HH; c += 32) {
        float hv = d_h[(size_t)i * HH + c];
        a0 = fmaf(hv, sw[c * 3 + 0], a0);
        a1 = fmaf(hv, sw[c * 3 + 1], a1);
        a2 = fmaf(hv, sw[c * 3 + 2], a2);
    }
    #pragma unroll
    for (int off = 16; off; off >>= 1) {
        a0 += __shfl_down_sync(0xffffffffu, a0, off);
        a1 += __shfl_down_sync(0xffffffffu, a1, off);
        a2 += __shfl_down_sync(0xffffffffu, a2, off);
    }
    if (lane == 0) {
        out[i * 3 + 0] = a0 + bout[0];
        out[i * 3 + 1] = a1 + bout[1];
        out[i * 3 + 2] = a2 + bout[2];
    }
}

// -------------------------------------------------------------------------
extern "C" void kernel_launch(void* const* d_in, const int* in_sizes, int n_in,
                              void* d_out, int out_size) {
    const float* coords = (const float*)d_in[0];
    const float* tin  = (const float*)d_in[2];
    const float* Wgfp = (const float*)d_in[3];
    const float* Wt_  = (const float*)d_in[4];
    const float* bt_  = (const float*)d_in[5];
    const float* Win  = (const float*)d_in[6];
    const float* bin  = (const float*)d_in[7];
    const float* W1   = (const float*)d_in[8];
    const float* b1   = (const float*)d_in[9];
    const float* W2   = (const float*)d_in[10];
    const float* b2   = (const float*)d_in[11];
    const float* We   = (const float*)d_in[12];
    const float* be   = (const float*)d_in[13];
    const float* eps  = (const float*)d_in[14];
    const float* gnw  = (const float*)d_in[15];
    const float* gnb  = (const float*)d_in[16];
    const float* gnms = (const float*)d_in[17];
    const float* Wtl  = (const float*)d_in[18];
    const float* btl  = (const float*)d_in[19];
    const float* Wout = (const float*)d_in[20];
    const float* bout = (const float*)d_in[21];
    float* out = (float*)d_out;

    const int smem_edge = SMEM_EDGE_WORDS * 4;
    cudaFuncSetAttribute(k_edge, cudaFuncAttributeMaxDynamicSharedMemorySize, smem_edge);

    k_temb<<<1, 128>>>(tin, Wgfp, Wt_, bt_);
    k_tproj<<<LL * BB, 256>>>(Wtl, btl);
    k_hin<<<NN, 256>>>(coords, Win, bin);
    k_nbr<<<NN / 4, 128>>>(coords);
    k_afrag<<<NN / 4, 256>>>(coords);
    k_befrag<<<dim3(4, LL), 256>>>(We, be);

    for (int l = 0; l < LL; l++) {
        k_edge<<<NN / 4, 256, smem_edge>>>(l);
        k_gemm<0><<<dim3(4, 64), 256>>>(W1 + (size_t)l * X2H * HH, b1 + l * HH, eps, l);
        k_gemm<1><<<dim3(4, 64), 256>>>(W2 + (size_t)l * HH * HH, b2 + l * HH, eps, l);
        k_gfin<<<64, 256>>>(gnw + l * HH, gnb + l * HH, gnms + l * HH);
    }
    k_out<<<NN / 8, 256>>>(Wout, bout, out);
}

// round 11
// speedup vs baseline: 1.7593x; 1.1247x over previous
#include <cuda_runtime.h>
#include <cuda_bf16.h>
#include <math.h>

#define NN     4096
#define BB     8
#define NPG    512
#define KK     30
#define NBASIS 32
#define EDIM   35      // NBASIS + 3
#define HH     256
#define X2H    512
#define TT     128
#define LL     5
#define RADIUS 1.5f

// ---------------- static scratch (no allocations allowed) ----------------
__device__ __align__(16) float d_tfeat[BB * TT];
__device__ __align__(16) float d_tproj[LL * BB * HH];
__device__ __align__(16) float d_h[NN * HH];
__device__ __align__(16) float d_aggr[NN * X2H];
__device__ __align__(16) float d_z1[NN * HH];
__device__ __align__(16) float d_z[NN * HH];
// bf16x2-packed fragments, hi | lo
__device__ __align__(16) unsigned d_afrag[(NN / 4) * 6144];   // edge A frags per 4-node block
__device__ __align__(16) unsigned d_bfrag[LL * 4 * 6144];     // edge B frags per (layer, chunk)
__device__ __align__(16) unsigned d_w1frag[LL * 32 * 4096];   // W1 frags (hi | lo per layer)
__device__ __align__(16) unsigned d_w2frag[LL * 16 * 4096];   // W2 frags
__device__ int   d_nbr[NN * KK];
__device__ int   d_cnt[NN];
__device__ float d_elen[NN * KK];
__device__ __align__(16) float d_psum[64 * HH];   // gemm1 per-mblock col sums
__device__ __align__(16) float d_psumq[64 * HH];  // gemm1 per-mblock col sumsq

__device__ __forceinline__ float silu_f(float v) { return v / (1.f + expf(-v)); }

// ---------------- bf16 helpers ----------------
__device__ __forceinline__ unsigned pack_bf16x2(float a, float b) {
    __nv_bfloat162 h = __floats2bfloat162_rn(a, b);
    return *(unsigned*)&h;
}
// float* variant (k_edge, proven R6/R7)
__device__ __forceinline__ void mma_bf16(float* c, uint4 a, unsigned b0, unsigned b1) {
    asm volatile(
        "mma.sync.aligned.m16n8k16.row.col.f32.bf16.bf16.f32 "
        "{%0,%1,%2,%3}, {%4,%5,%6,%7}, {%8,%9}, {%0,%1,%2,%3};"
        : "+f"(c[0]), "+f"(c[1]), "+f"(c[2]), "+f"(c[3])
        : "r"(a.x), "r"(a.y), "r"(a.z), "r"(a.w), "r"(b0), "r"(b1));
}
// macro on NAMED float4 lvalues
#define MMA_NAMED(cv, av, bb0, bb1)                                       \
    asm volatile(                                                         \
        "mma.sync.aligned.m16n8k16.row.col.f32.bf16.bf16.f32 "            \
        "{%0,%1,%2,%3}, {%4,%5,%6,%7}, {%8,%9}, {%0,%1,%2,%3};"           \
        : "+f"(cv.x), "+f"(cv.y), "+f"(cv.z), "+f"(cv.w)                  \
        : "r"(av.x), "r"(av.y), "r"(av.z), "r"(av.w), "r"(bb0), "r"(bb1))

// ---------------- time embedding ----------------
__global__ void k_temb(const float* __restrict__ tin, const float* __restrict__ wgfp,
                       const float* __restrict__ wt, const float* __restrict__ bt) {
    __shared__ float ss[64], sc[64];
    int t = threadIdx.x; // 128
    for (int b = 0; b < BB; b++) {
        if (t < 64) {
            float xp = 6.283185307179586f * tin[b] * wgfp[t];
            ss[t] = sinf(xp);
            sc[t] = cosf(xp);
        }
        __syncthreads();
        float acc = bt[t];
        #pragma unroll 8
        for (int h = 0; h < 64; h++) {
            acc = fmaf(ss[h], wt[h * TT + t], acc);
            acc = fmaf(sc[h], wt[(64 + h) * TT + t], acc);
        }
        d_tfeat[b * TT + t] = silu_f(acc);
        __syncthreads();
    }
}

__global__ void k_tproj(const float* __restrict__ Wt, const float* __restrict__ bt) {
    int l = blockIdx.x / BB, b = blockIdx.x % BB;
    int c = threadIdx.x; // 256
    __shared__ float tf[TT];
    if (c < TT) tf[c] = d_tfeat[b * TT + c];
    __syncthreads();
    float acc = bt[l * HH + c];
    const float* w = Wt + (size_t)l * TT * HH;
    #pragma unroll 8
    for (int k = 0; k < TT; k++) acc = fmaf(tf[k], w[k * HH + c], acc);
    d_tproj[(l * BB + b) * HH + c] = acc;
}

__global__ void k_hin(const float* __restrict__ coords, const float* __restrict__ Win,
                      const float* __restrict__ bin) {
    int i = blockIdx.x;
    int c = threadIdx.x;
    float x0 = coords[i * 3 + 0], x1 = coords[i * 3 + 1], x2 = coords[i * 3 + 2];
    float v = fmaf(x0, Win[c], fmaf(x1, Win[HH + c], fmaf(x2, Win[2 * HH + c], bin[c])));
    d_h[(size_t)i * HH + c] = v;
}

// ---------------- radius graph (stores selected distances too) ------------
__global__ void __launch_bounds__(128) k_nbr(const float* __restrict__ coords) {
    __shared__ float sx[NPG], sy[NPG], sz[NPG];
    __shared__ float sd[4][NPG];
    int t = threadIdx.x;
    int base = blockIdx.x * 4;
    int goff = (base >> 9) << 9;
    for (int j = t; j < NPG; j += 128) {
        sx[j] = coords[(goff + j) * 3 + 0];
        sy[j] = coords[(goff + j) * 3 + 1];
        sz[j] = coords[(goff + j) * 3 + 2];
    }
    __syncthreads();
    int w = t >> 5, lane = t & 31;
    int il = (base & 511) + w;
    int ig = goff + il;
    float xi = sx[il], yi = sy[il], zi = sz[il];
    float sqi = xi * xi + yi * yi + zi * zi;
    for (int j = lane; j < NPG; j += 32) {
        float xj = sx[j], yj = sy[j], zj = sz[j];
        float dot = xi * xj + yi * yj + zi * zj;
        float sqj = xj * xj + yj * yj + zj * zj;
        float d2 = sqi + sqj - 2.f * dot;
        float d = sqrtf(fmaxf(d2, 1e-12f));
        sd[w][j] = (j != il && d < RADIUS) ? d : INFINITY;
    }
    __syncwarp();
    int cc = 0;
    for (int k = 0; k < KK; k++) {
        float best = INFINITY;
        int bi = -1;
        for (int j = lane; j < NPG; j += 32) {
            float v = sd[w][j];
            if (v < best) { best = v; bi = j; }
        }
        #pragma unroll
        for (int off = 16; off; off >>= 1) {
            float ov = __shfl_down_sync(0xffffffffu, best, off);
            int oi = __shfl_down_sync(0xffffffffu, bi, off);
            if (ov < best || (ov == best && (unsigned)oi < (unsigned)bi)) { best = ov; bi = oi; }
        }
        best = __shfl_sync(0xffffffffu, best, 0);
        bi = __shfl_sync(0xffffffffu, bi, 0);
        if (!(best < INFINITY)) break;
        if (lane == 0) {
            d_nbr[ig * KK + k] = goff + bi;
            d_elen[ig * KK + k] = best;
            sd[w][bi] = INFINITY;
        }
        cc = k + 1;
        __syncwarp();
    }
    if (lane == 0) d_cnt[ig] = cc;
}

// ---------------- A fragments: edge attrs computed directly ---------------
__global__ void __launch_bounds__(256) k_afrag(const float* __restrict__ coords) {
    int blk = blockIdx.x;            // 1024 blocks of 4 nodes
    int i0 = blk * 4;
    unsigned* outp = d_afrag + (size_t)blk * 6144;
    const float step = RADIUS / 33.f;
    const float istep = 33.f / RADIUS;
    for (int idx = threadIdx.x; idx < 3072; idx += 256) {
        int r = idx & 3;
        int lane = (idx >> 2) & 31;
        int ks = (idx >> 7) % 3;
        int mg = idx / 384;
        int row = 16 * mg + 8 * (r & 1) + (lane >> 2);
        int kb = ks * 16 + 8 * (r >> 1) + 2 * (lane & 3);
        int n = row >> 5, k = row & 31;
        int node = i0 + n;
        float a0 = 0.f, a1 = 0.f;
        if (k < d_cnt[node] && kb < 36) {
            float el = d_elen[node * KK + k];
            if (kb < 32) {
                float d0 = (el - (float)(kb + 1) * step) * istep;
                float d1 = (el - (float)(kb + 2) * step) * istep;
                a0 = expf(-d0 * d0) * (1.f / 1.12f);
                a1 = expf(-d1 * d1) * (1.f / 1.12f);
            } else {
                int s = d_nbr[node * KK + k];
                float inv = 1.f / el;
                float ex = coords[s * 3 + 0] - coords[node * 3 + 0];
                float ey = coords[s * 3 + 1] - coords[node * 3 + 1];
                float ez = coords[s * 3 + 2] - coords[node * 3 + 2];
                if (kb == 32) { a0 = ex * inv; a1 = ey * inv; }
                else          { a0 = ez * inv; a1 = 1.0f; }   // kb == 34
            }
        }
        float h0 = __bfloat162float(__float2bfloat16_rn(a0));
        float h1 = __bfloat162float(__float2bfloat16_rn(a1));
        outp[idx]        = pack_bf16x2(h0, h1);
        outp[idx + 3072] = pack_bf16x2(a0 - h0, a1 - h1);
    }
}

// ---------------- B fragments for k_edge: We (+be as row 35) --------------
__global__ void __launch_bounds__(256) k_befrag(const float* __restrict__ We,
                                                const float* __restrict__ be) {
    int cc = blockIdx.x, l = blockIdx.y;
    const float* w = We + (size_t)l * EDIM * X2H;
    const float* bp = be + (size_t)l * X2H;
    unsigned* outp = d_bfrag + (size_t)(l * 4 + cc) * 6144;
    for (int idx = threadIdx.x; idx < 3072; idx += 256) {
        int q = idx & 3;
        int ts = q >> 1, rb = q & 1;
        int lane = (idx >> 2) & 31;
        int tp = (idx >> 7) & 7;
        int ks = idx >> 10;
        int tile = 2 * tp + ts;
        int kb = ks * 16 + 8 * rb + 2 * (lane & 3);
        int gcol = cc * 128 + tile * 8 + (lane >> 2);
        float b0 = (kb < EDIM) ? w[kb * X2H + gcol] : ((kb == 35) ? bp[gcol] : 0.f);
        int kb1 = kb + 1;
        float b1 = (kb1 < EDIM) ? w[kb1 * X2H + gcol] : ((kb1 == 35) ? bp[gcol] : 0.f);
        float h0 = __bfloat162float(__float2bfloat16_rn(b0));
        float h1 = __bfloat162float(__float2bfloat16_rn(b1));
        outp[idx]        = pack_bf16x2(h0, h1);
        outp[idx + 3072] = pack_bf16x2(b0 - h0, b1 - h1);
    }
}

// ---------------- weight fragments for MLP GEMMs --------------------------
// DST chosen INSIDE the kernel (device symbols must not be passed from host).
template <int KS>
__global__ void __launch_bounds__(256) k_wfrag(const float* __restrict__ W) {
    int ksg = blockIdx.x, l = blockIdx.y;
    const float* wl = W + (size_t)l * KS * 16 * HH;
    unsigned* dl = ((KS == 32) ? d_w1frag : d_w2frag) + (size_t)l * KS * 4096;
    for (int idx = threadIdx.x; idx < 2048; idx += 256) {
        int ntg = idx >> 6;
        int lane = (idx >> 1) & 31;
        int tt = idx & 1;
        int kb = ksg * 16 + 8 * tt + 2 * (lane & 3);
        int col = ntg * 8 + (lane >> 2);
        float b0 = wl[(size_t)kb * HH + col];
        float b1 = wl[(size_t)(kb + 1) * HH + col];
        float h0 = __bfloat162float(__float2bfloat16_rn(b0));
        float h1 = __bfloat162float(__float2bfloat16_rn(b1));
        dl[(size_t)ksg * 2048 + idx] = pack_bf16x2(h0, h1);
        dl[(size_t)KS * 2048 + (size_t)ksg * 2048 + idx] = pack_bf16x2(b0 - h0, b1 - h1);
    }
}

// ---------------- k_edge: warp-per-node bf16-split tensor GINE ------------
#define OFF_AF   0        // A hi|lo : 6144 words
#define OFF_BF   6144     // B hi|lo : 6144 words
#define OFF_STP  12288    // 256
#define SMEM_EDGE_WORDS 12544

__global__ void __launch_bounds__(256) k_edge(int l) {
    extern __shared__ float sm[];
    unsigned* Af = (unsigned*)sm + OFF_AF;
    unsigned* Bf = (unsigned*)sm + OFF_BF;
    float* stp = sm + OFF_STP;
    __shared__ int ssrc[4][32];
    __shared__ int scnt[4];

    int t = threadIdx.x;
    int w = t >> 5, lane = t & 31;
    int i0 = blockIdx.x * 4;
    int g = i0 >> 9;

    if (t < 128) {
        int n = t >> 5, k = t & 31;
        int c = d_cnt[i0 + n];
        if (k == 0) scnt[n] = c;
        ssrc[n][k] = (k < c) ? d_nbr[(i0 + n) * KK + k] : (i0 + n);
    }
    stp[t] = d_tproj[(l * BB + g) * HH + t];  // t<256

    {
        const uint4* asrc = (const uint4*)(d_afrag + (size_t)blockIdx.x * 6144);
        uint4* adst = (uint4*)Af;
        for (int idx = t; idx < 1536; idx += 256) adst[idx] = asrc[idx];
    }
    __syncthreads();

    int node = w & 3, half = w >> 2;
    int cnt_n = scnt[node];
    int rr = lane >> 2;
    int s0 = ssrc[node][rr],      s1 = ssrc[node][rr + 8];
    int s2 = ssrc[node][rr + 16], s3 = ssrc[node][rr + 24];
    float mk0 = (rr      < cnt_n) ? 1.f : 0.f;
    float mk1 = (rr + 8  < cnt_n) ? 1.f : 0.f;
    float mk2 = (rr + 16 < cnt_n) ? 1.f : 0.f;
    float mk3 = (rr + 24 < cnt_n) ? 1.f : 0.f;
    int mg0 = 2 * node, mg1 = 2 * node + 1;

    for (int cc = 0; cc < 4; cc++) {
        {
            const uint4* bsrc = (const uint4*)(d_bfrag + (size_t)(l * 4 + cc) * 6144);
            uint4* bdst = (uint4*)Bf;
            for (int idx = t; idx < 1536; idx += 256) bdst[idx] = bsrc[idx];
        }
        __syncthreads();

        float acc[2][8][4];
        #pragma unroll
        for (int m = 0; m < 2; m++)
            #pragma unroll
            for (int q = 0; q < 8; q++) {
                acc[m][q][0] = 0.f; acc[m][q][1] = 0.f;
                acc[m][q][2] = 0.f; acc[m][q][3] = 0.f;
            }
        #pragma unroll
        for (int ks = 0; ks < 3; ks++) {
            uint4 ah0 = *(const uint4*)&Af[((mg0 * 3 + ks) * 32 + lane) * 4];
            uint4 al0 = *(const uint4*)&Af[3072 + ((mg0 * 3 + ks) * 32 + lane) * 4];
            uint4 ah1 = *(const uint4*)&Af[((mg1 * 3 + ks) * 32 + lane) * 4];
            uint4 al1 = *(const uint4*)&Af[3072 + ((mg1 * 3 + ks) * 32 + lane) * 4];
            #pragma unroll
            for (int tt = 0; tt < 4; tt++) {
                int tp = half * 4 + tt;
                uint4 bh = *(const uint4*)&Bf[((ks * 8 + tp) * 32 + lane) * 4];
                uint4 bl = *(const uint4*)&Bf[3072 + ((ks * 8 + tp) * 32 + lane) * 4];
                mma_bf16(acc[0][2 * tt + 0], ah0, bh.x, bh.y);
                mma_bf16(acc[0][2 * tt + 0], al0, bh.x, bh.y);
                mma_bf16(acc[0][2 * tt + 0], ah0, bl.x, bl.y);
                mma_bf16(acc[0][2 * tt + 1], ah0, bh.z, bh.w);
                mma_bf16(acc[0][2 * tt + 1], al0, bh.z, bh.w);
                mma_bf16(acc[0][2 * tt + 1], ah0, bl.z, bl.w);
                mma_bf16(acc[1][2 * tt + 0], ah1, bh.x, bh.y);
                mma_bf16(acc[1][2 * tt + 0], al1, bh.x, bh.y);
                mma_bf16(acc[1][2 * tt + 0], ah1, bl.x, bl.y);
                mma_bf16(acc[1][2 * tt + 1], ah1, bh.z, bh.w);
                mma_bf16(acc[1][2 * tt + 1], al1, bh.z, bh.w);
                mma_bf16(acc[1][2 * tt + 1], ah1, bl.z, bl.w);
            }
        }
        __syncthreads();

        #pragma unroll
        for (int nt = 0; nt < 8; nt++) {
            int gcol = cc * 128 + half * 64 + nt * 8 + 2 * (lane & 3);
            float2 x0, x1, x2, x3;
            if (cc < 2) {
                x0 = *(const float2*)(d_h + (size_t)s0 * HH + gcol);
                x1 = *(const float2*)(d_h + (size_t)s1 * HH + gcol);
                x2 = *(const float2*)(d_h + (size_t)s2 * HH + gcol);
                x3 = *(const float2*)(d_h + (size_t)s3 * HH + gcol);
            } else {
                float2 tv = *(const float2*)&stp[gcol - HH];
                x0 = tv; x1 = tv; x2 = tv; x3 = tv;
            }
            float sA = mk0 * fmaxf(acc[0][nt][0] + x0.x, 0.f);
            sA = fmaf(mk1, fmaxf(acc[0][nt][2] + x1.x, 0.f), sA);
            sA = fmaf(mk2, fmaxf(acc[1][nt][0] + x2.x, 0.f), sA);
            sA = fmaf(mk3, fmaxf(acc[1][nt][2] + x3.x, 0.f), sA);
            float sB = mk0 * fmaxf(acc[0][nt][1] + x0.y, 0.f);
            sB = fmaf(mk1, fmaxf(acc[0][nt][3] + x1.y, 0.f), sB);
            sB = fmaf(mk2, fmaxf(acc[1][nt][1] + x2.y, 0.f), sB);
            sB = fmaf(mk3, fmaxf(acc[1][nt][3] + x3.y, 0.f), sB);
            #pragma unroll
            for (int off = 16; off >= 4; off >>= 1) {
                sA += __shfl_down_sync(0xffffffffu, sA, off);
                sB += __shfl_down_sync(0xffffffffu, sB, off);
            }
            if (lane < 4) {
                int gc = cc * 128 + half * 64 + nt * 8 + 2 * lane;
                *(float2*)(d_aggr + (size_t)(i0 + node) * X2H + gc) = make_float2(sA, sB);
            }
        }
    }
}

// ---------------- tensor-core MLP GEMM (weights via device symbols) -------
// Block = 64 rows x 64 cols. 8 warps = 4 m-tiles x 2 col-halves (4 n-tiles/warp).
// MODE0: z1 = silu(((1+eps)*[h|tproj] + aggr) @ W1 + b1)   K=512
// MODE1: z  = z1 @ W2 + b2 (+ GraphNorm col partials)       K=256
#define SMEM_G_WORDS 8448

#define MMA_STEP(cv)                                                         \
    do {                                                                     \
        uint2 bh = *(const uint2*)&Bf[ks * 512 + ntl * 64 + lane * 2];       \
        uint2 bl = *(const uint2*)&Bf[2048 + ks * 512 + ntl * 64 + lane * 2];\
        MMA_NAMED(cv, ah, bh.x, bh.y);                                       \
        MMA_NAMED(cv, al, bh.x, bh.y);                                       \
        MMA_NAMED(cv, ah, bl.x, bl.y);                                       \
        ntl++;                                                               \
    } while (0)

template <int MODE>
__global__ void __launch_bounds__(256) k_mgemm(const float* __restrict__ bias,
                                               const float* __restrict__ epsp, int l) {
    const int KS = (MODE == 0) ? 32 : 16;
    const int NKSC = KS / 4;
    extern __shared__ float sm[];
    unsigned* Af = (unsigned*)sm;          // hi 0..2048, lo 2048..4096
    unsigned* Bf = (unsigned*)sm + 4096;   // hi 0..2048, lo 2048..4096
    float* stp = sm + 8192;                // 256
    int t = threadIdx.x;
    int w = t >> 5, lane = t & 31;
    int bx = blockIdx.x, mb = blockIdx.y;
    int m0 = mb * 64;
    int g = m0 >> 9;
    float ep = (MODE == 0) ? (1.f + epsp[l]) : 0.f;
    if (MODE == 0 && t < HH) stp[t] = d_tproj[(l * BB + g) * HH + t];
    const unsigned* wl = ((MODE == 0) ? d_w1frag : d_w2frag) + (size_t)l * KS * 4096;
    int mt = w & 3, half = w >> 2;

    float4 acc0 = make_float4(0.f, 0.f, 0.f, 0.f);
    float4 acc1 = make_float4(0.f, 0.f, 0.f, 0.f);
    float4 acc2 = make_float4(0.f, 0.f, 0.f, 0.f);
    float4 acc3 = make_float4(0.f, 0.f, 0.f, 0.f);

    for (int ksc = 0; ksc < NKSC; ksc++) {
        __syncthreads();
        // stage A: bf16 hi/lo fragments with fused input epilogue
        for (int idx = t; idx < 2048; idx += 256) {
            int mtl = idx >> 9;
            int rem = idx & 511;
            int ksl = rem >> 7;
            int ln = (rem >> 2) & 31;
            int r = idx & 3;
            int row = m0 + 16 * mtl + 8 * (r & 1) + (ln >> 2);
            int kb = ksc * 64 + ksl * 16 + 8 * (r >> 1) + 2 * (ln & 3);
            float v0, v1;
            if (MODE == 0) {
                float2 ag = *(const float2*)(d_aggr + (size_t)row * X2H + kb);
                float2 hx;
                if (kb < HH) hx = *(const float2*)(d_h + (size_t)row * HH + kb);
                else         hx = *(const float2*)&stp[kb - HH];
                v0 = fmaf(ep, hx.x, ag.x);
                v1 = fmaf(ep, hx.y, ag.y);
            } else {
                float2 zz = *(const float2*)(d_z1 + (size_t)row * HH + kb);
                v0 = zz.x; v1 = zz.y;
            }
            float h0 = __bfloat162float(__float2bfloat16_rn(v0));
            float h1 = __bfloat162float(__float2bfloat16_rn(v1));
            Af[idx]        = pack_bf16x2(h0, h1);
            Af[idx + 2048] = pack_bf16x2(v0 - h0, v1 - h1);
        }
        // stage B: contiguous slices of precomputed weight fragments
        if (t < 128) {
            #pragma unroll
            for (int ks4 = 0; ks4 < 4; ks4++) {
                int ksg = ksc * 4 + ks4;
                const uint4* sh = (const uint4*)(wl + (size_t)ksg * 2048 + bx * 512);
                const uint4* sl = (const uint4*)(wl + (size_t)KS * 2048 +
                                                 (size_t)ksg * 2048 + bx * 512);
                ((uint4*)(Bf + ks4 * 512))[t] = sh[t];
                ((uint4*)(Bf + 2048 + ks4 * 512))[t] = sl[t];
            }
        }
        __syncthreads();
        #pragma unroll
        for (int ks = 0; ks < 4; ks++) {
            uint4 ah = *(const uint4*)&Af[((mt * 4 + ks) * 32 + lane) * 4];
            uint4 al = *(const uint4*)&Af[2048 + ((mt * 4 + ks) * 32 + lane) * 4];
            int ntl = half * 4;
            MMA_STEP(acc0);
            MMA_STEP(acc1);
            MMA_STEP(acc2);
            MMA_STEP(acc3);
        }
    }
    __syncthreads();

    int r0 = m0 + mt * 16 + (lane >> 2);
    if (MODE == 0) {
        #define EPI0(cv, NTL)                                                        \
        {                                                                            \
            int col = bx * 64 + (half * 4 + (NTL)) * 8 + 2 * (lane & 3);             \
            float b0v = bias[col], b1v = bias[col + 1];                              \
            *(float2*)(d_z1 + (size_t)r0 * HH + col) =                               \
                make_float2(silu_f(cv.x + b0v), silu_f(cv.y + b1v));                 \
            *(float2*)(d_z1 + (size_t)(r0 + 8) * HH + col) =                         \
                make_float2(silu_f(cv.z + b0v), silu_f(cv.w + b1v));                 \
        }
        EPI0(acc0, 0) EPI0(acc1, 1) EPI0(acc2, 2) EPI0(acc3, 3)
        #undef EPI0
    } else {
        float* sps = sm;          // reuse Af region (256 + 256 floats)
        float* spq = sm + 256;
        #define EPI1(cv, NTL)                                                        \
        {                                                                            \
            int cl = (half * 4 + (NTL)) * 8 + 2 * (lane & 3);                        \
            int col = bx * 64 + cl;                                                  \
            float b0v = bias[col], b1v = bias[col + 1];                              \
            float v00 = cv.x + b0v, v01 = cv.y + b1v;                                \
            float v10 = cv.z + b0v, v11 = cv.w + b1v;                                \
            *(float2*)(d_z + (size_t)r0 * HH + col) = make_float2(v00, v01);         \
            *(float2*)(d_z + (size_t)(r0 + 8) * HH + col) = make_float2(v10, v11);   \
            float s0 = v00 + v10, s1 = v01 + v11;                                    \
            float q0 = v00 * v00 + v10 * v10, q1 = v01 * v01 + v11 * v11;            \
            for (int off = 16; off >= 4; off >>= 1) {                                \
                s0 += __shfl_down_sync(0xffffffffu, s0, off);                        \
                s1 += __shfl_down_sync(0xffffffffu, s1, off);                        \
                q0 += __shfl_down_sync(0xffffffffu, q0, off);                        \
                q1 += __shfl_down_sync(0xffffffffu, q1, off);                        \
            }                                                                        \
            if (lane < 4) {                                                          \
                int c2 = (half * 4 + (NTL)) * 8 + 2 * lane;                          \
                sps[mt * 64 + c2] = s0; sps[mt * 64 + c2 + 1] = s1;                  \
                spq[mt * 64 + c2] = q0; spq[mt * 64 + c2 + 1] = q1;                  \
            }                                                                        \
        }
        EPI1(acc0, 0) EPI1(acc1, 1) EPI1(acc2, 2) EPI1(acc3, 3)
        #undef EPI1
        __syncthreads();
        if (t < 64) {
            float S = 0.f, Q = 0.f;
            #pragma unroll
            for (int p = 0; p < 4; p++) { S += sps[p * 64 + t]; Q += spq[p * 64 + t]; }
            d_psum[mb * HH + bx * 64 + t] = S;
            d_psumq[mb * HH + bx * 64 + t] = Q;
        }
    }
}

// ---------------- GraphNorm finalize (folds gemm1 partials) ---------------
__global__ void k_gfin(const float* __restrict__ gw, const float* __restrict__ gb,
                       const float* __restrict__ gms) {
    int nb = blockIdx.x * 64;
    int g = nb >> 9;
    int c = threadIdx.x;
    float s = 0.f, q = 0.f;
    #pragma unroll
    for (int p = 0; p < 8; p++) {
        s += d_psum[(g * 8 + p) * HH + c];
        q += d_psumq[(g * 8 + p) * HH + c];
    }
    float mean = s * (1.f / 512.f);
    float ez2  = q * (1.f / 512.f);
    float mm = mean * gms[c];
    float var = ez2 - 2.f * mm * mean + mm * mm;
    float inv = 1.f / sqrtf(var + 1e-5f);
    float w = gw[c], b = gb[c];
    for (int n = 0; n < 64; n++) {
        size_t id = (size_t)(nb + n) * HH + c;
        float cc = d_z[id] - mm;
        float zn = fmaf(w * cc, inv, b);
        float hv = zn + d_h[id];
        d_h[id] = silu_f(hv);
    }
}

// ---------------- output head ----------------
__global__ void k_out(const float* __restrict__ Wout, const float* __restrict__ bout,
                      float* __restrict__ out) {
    __shared__ float sw[HH * 3];
    int t = threadIdx.x;
    for (int idx = t; idx < HH * 3; idx += 256) sw[idx] = Wout[idx];
    __syncthreads();
    int w = t >> 5, lane = t & 31;
    int i = blockIdx.x * 8 + w;
    float a0 = 0.f, a1 = 0.f, a2 = 0.f;
    for (int c = lane; c < HH; c += 32) {
        float hv = d_h[(size_t)i * HH + c];
        a0 = fmaf(hv, sw[c * 3 + 0], a0);
        a1 = fmaf(hv, sw[c * 3 + 1], a1);
        a2 = fmaf(hv, sw[c * 3 + 2], a2);
    }
    #pragma unroll
    for (int off = 16; off; off >>= 1) {
        a0 += __shfl_down_sync(0xffffffffu, a0, off);
        a1 += __shfl_down_sync(0xffffffffu, a1, off);
        a2 += __shfl_down_sync(0xffffffffu, a2, off);
    }
    if (lane == 0) {
        out[i * 3 + 0] = a0 + bout[0];
        out[i * 3 + 1] = a1 + bout[1];
        out[i * 3 + 2] = a2 + bout[2];
    }
}

// -------------------------------------------------------------------------
extern "C" void kernel_launch(void* const* d_in, const int* in_sizes, int n_in,
                              void* d_out, int out_size) {
    const float* coords = (const float*)d_in[0];
    const float* tin  = (const float*)d_in[2];
    const float* Wgfp = (const float*)d_in[3];
    const float* Wt_  = (const float*)d_in[4];
    const float* bt_  = (const float*)d_in[5];
    const float* Win  = (const float*)d_in[6];
    const float* bin  = (const float*)d_in[7];
    const float* W1   = (const float*)d_in[8];
    const float* b1   = (const float*)d_in[9];
    const float* W2   = (const float*)d_in[10];
    const float* b2   = (const float*)d_in[11];
    const float* We   = (const float*)d_in[12];
    const float* be   = (const float*)d_in[13];
    const float* eps  = (const float*)d_in[14];
    const float* gnw  = (const float*)d_in[15];
    const float* gnb  = (const float*)d_in[16];
    const float* gnms = (const float*)d_in[17];
    const float* Wtl  = (const float*)d_in[18];
    const float* btl  = (const float*)d_in[19];
    const float* Wout = (const float*)d_in[20];
    const float* bout = (const float*)d_in[21];
    float* out = (float*)d_out;

    const int smem_edge = SMEM_EDGE_WORDS * 4;
    const int smem_g = SMEM_G_WORDS * 4;   // 33792 B, under 48KB default
    cudaFuncSetAttribute(k_edge, cudaFuncAttributeMaxDynamicSharedMemorySize, smem_edge);

    k_temb<<<1, 128>>>(tin, Wgfp, Wt_, bt_);
    k_tproj<<<LL * BB, 256>>>(Wtl, btl);
    k_hin<<<NN, 256>>>(coords, Win, bin);
    k_nbr<<<NN / 4, 128>>>(coords);
    k_afrag<<<NN / 4, 256>>>(coords);
    k_befrag<<<dim3(4, LL), 256>>>(We, be);
    k_wfrag<32><<<dim3(32, LL), 256>>>(W1);
    k_wfrag<16><<<dim3(16, LL), 256>>>(W2);

    for (int l = 0; l < LL; l++) {
        k_edge<<<NN / 4, 256, smem_edge>>>(l);
        k_mgemm<0><<<dim3(4, 64), 256, smem_g>>>(b1 + l * HH, eps, l);
        k_mgemm<1><<<dim3(4, 64), 256, smem_g>>>(b2 + l * HH, eps, l);
        k_gfin<<<64, 256>>>(gnw + l * HH, gnb + l * HH, gnms + l * HH);
    }
    k_out<<<NN / 8, 256>>>(Wout, bout, out);
}

// round 12
// speedup vs baseline: 1.8030x; 1.0249x over previous
#include <cuda_runtime.h>
#include <cuda_bf16.h>
#include <math.h>

#define NN     4096
#define BB     8
#define NPG    512
#define KK     30
#define NBASIS 32
#define EDIM   35      // NBASIS + 3
#define HH     256
#define X2H    512
#define TT     128
#define LL     5
#define RADIUS 1.5f

// ---------------- static scratch (no allocations allowed) ----------------
__device__ __align__(16) float d_tfeat[BB * TT];
__device__ __align__(16) float d_tproj[LL * BB * HH];
__device__ __align__(16) float d_h[NN * HH];
__device__ __align__(16) float d_aggr[NN * X2H];
__device__ __align__(16) float d_z1[NN * HH];
__device__ __align__(16) float d_z[NN * HH];
// bf16x2-packed fragments, hi | lo
__device__ __align__(16) unsigned d_afrag[(NN / 4) * 6144];   // edge A frags per 4-node block
__device__ __align__(16) unsigned d_bfrag[LL * 4 * 6144];     // edge B frags per (layer, chunk)
__device__ __align__(16) unsigned d_w1frag[LL * 32 * 4096];   // W1 frags (hi | lo per layer)
__device__ __align__(16) unsigned d_w2frag[LL * 16 * 4096];   // W2 frags
__device__ int   d_nbr[NN * KK];
__device__ int   d_cnt[NN];
__device__ float d_elen[NN * KK];
__device__ __align__(16) float d_psum[64 * HH];   // gemm1 per-mblock col sums
__device__ __align__(16) float d_psumq[64 * HH];  // gemm1 per-mblock col sumsq

__device__ __forceinline__ float silu_f(float v) { return v / (1.f + expf(-v)); }

// ---------------- bf16 helpers ----------------
__device__ __forceinline__ unsigned pack_bf16x2(float a, float b) {
    __nv_bfloat162 h = __floats2bfloat162_rn(a, b);
    return *(unsigned*)&h;
}
__device__ __forceinline__ void mma_bf16(float* c, uint4 a, unsigned b0, unsigned b1) {
    asm volatile(
        "mma.sync.aligned.m16n8k16.row.col.f32.bf16.bf16.f32 "
        "{%0,%1,%2,%3}, {%4,%5,%6,%7}, {%8,%9}, {%0,%1,%2,%3};"
        : "+f"(c[0]), "+f"(c[1]), "+f"(c[2]), "+f"(c[3])
        : "r"(a.x), "r"(a.y), "r"(a.z), "r"(a.w), "r"(b0), "r"(b1));
}

// ---------------- time embedding ----------------
__global__ void k_temb(const float* __restrict__ tin, const float* __restrict__ wgfp,
                       const float* __restrict__ wt, const float* __restrict__ bt) {
    __shared__ float ss[64], sc[64];
    int t = threadIdx.x; // 128
    for (int b = 0; b < BB; b++) {
        if (t < 64) {
            float xp = 6.283185307179586f * tin[b] * wgfp[t];
            ss[t] = sinf(xp);
            sc[t] = cosf(xp);
        }
        __syncthreads();
        float acc = bt[t];
        #pragma unroll 8
        for (int h = 0; h < 64; h++) {
            acc = fmaf(ss[h], wt[h * TT + t], acc);
            acc = fmaf(sc[h], wt[(64 + h) * TT + t], acc);
        }
        d_tfeat[b * TT + t] = silu_f(acc);
        __syncthreads();
    }
}

__global__ void k_tproj(const float* __restrict__ Wt, const float* __restrict__ bt) {
    int l = blockIdx.x / BB, b = blockIdx.x % BB;
    int c = threadIdx.x; // 256
    __shared__ float tf[TT];
    if (c < TT) tf[c] = d_tfeat[b * TT + c];
    __syncthreads();
    float acc = bt[l * HH + c];
    const float* w = Wt + (size_t)l * TT * HH;
    #pragma unroll 8
    for (int k = 0; k < TT; k++) acc = fmaf(tf[k], w[k * HH + c], acc);
    d_tproj[(l * BB + b) * HH + c] = acc;
}

__global__ void k_hin(const float* __restrict__ coords, const float* __restrict__ Win,
                      const float* __restrict__ bin) {
    int i = blockIdx.x;
    int c = threadIdx.x;
    float x0 = coords[i * 3 + 0], x1 = coords[i * 3 + 1], x2 = coords[i * 3 + 2];
    float v = fmaf(x0, Win[c], fmaf(x1, Win[HH + c], fmaf(x2, Win[2 * HH + c], bin[c])));
    d_h[(size_t)i * HH + c] = v;
}

// ---------------- radius graph (stores selected distances too) ------------
__global__ void __launch_bounds__(128) k_nbr(const float* __restrict__ coords) {
    __shared__ float sx[NPG], sy[NPG], sz[NPG];
    __shared__ float sd[4][NPG];
    int t = threadIdx.x;
    int base = blockIdx.x * 4;
    int goff = (base >> 9) << 9;
    for (int j = t; j < NPG; j += 128) {
        sx[j] = coords[(goff + j) * 3 + 0];
        sy[j] = coords[(goff + j) * 3 + 1];
        sz[j] = coords[(goff + j) * 3 + 2];
    }
    __syncthreads();
    int w = t >> 5, lane = t & 31;
    int il = (base & 511) + w;
    int ig = goff + il;
    float xi = sx[il], yi = sy[il], zi = sz[il];
    float sqi = xi * xi + yi * yi + zi * zi;
    for (int j = lane; j < NPG; j += 32) {
        float xj = sx[j], yj = sy[j], zj = sz[j];
        float dot = xi * xj + yi * yj + zi * zj;
        float sqj = xj * xj + yj * yj + zj * zj;
        float d2 = sqi + sqj - 2.f * dot;
        float d = sqrtf(fmaxf(d2, 1e-12f));
        sd[w][j] = (j != il && d < RADIUS) ? d : INFINITY;
    }
    __syncwarp();
    int cc = 0;
    for (int k = 0; k < KK; k++) {
        float best = INFINITY;
        int bi = -1;
        for (int j = lane; j < NPG; j += 32) {
            float v = sd[w][j];
            if (v < best) { best = v; bi = j; }
        }
        #pragma unroll
        for (int off = 16; off; off >>= 1) {
            float ov = __shfl_down_sync(0xffffffffu, best, off);
            int oi = __shfl_down_sync(0xffffffffu, bi, off);
            if (ov < best || (ov == best && (unsigned)oi < (unsigned)bi)) { best = ov; bi = oi; }
        }
        best = __shfl_sync(0xffffffffu, best, 0);
        bi = __shfl_sync(0xffffffffu, bi, 0);
        if (!(best < INFINITY)) break;
        if (lane == 0) {
            d_nbr[ig * KK + k] = goff + bi;
            d_elen[ig * KK + k] = best;
            sd[w][bi] = INFINITY;
        }
        cc = k + 1;
        __syncwarp();
    }
    if (lane == 0) d_cnt[ig] = cc;
}

// ---------------- A fragments: edge attrs computed directly ---------------
__global__ void __launch_bounds__(256) k_afrag(const float* __restrict__ coords) {
    int blk = blockIdx.x;            // 1024 blocks of 4 nodes
    int i0 = blk * 4;
    unsigned* outp = d_afrag + (size_t)blk * 6144;
    const float step = RADIUS / 33.f;
    const float istep = 33.f / RADIUS;
    for (int idx = threadIdx.x; idx < 3072; idx += 256) {
        int r = idx & 3;
        int lane = (idx >> 2) & 31;
        int ks = (idx >> 7) % 3;
        int mg = idx / 384;
        int row = 16 * mg + 8 * (r & 1) + (lane >> 2);
        int kb = ks * 16 + 8 * (r >> 1) + 2 * (lane & 3);
        int n = row >> 5, k = row & 31;
        int node = i0 + n;
        float a0 = 0.f, a1 = 0.f;
        if (k < d_cnt[node] && kb < 36) {
            float el = d_elen[node * KK + k];
            if (kb < 32) {
                float d0 = (el - (float)(kb + 1) * step) * istep;
                float d1 = (el - (float)(kb + 2) * step) * istep;
                a0 = expf(-d0 * d0) * (1.f / 1.12f);
                a1 = expf(-d1 * d1) * (1.f / 1.12f);
            } else {
                int s = d_nbr[node * KK + k];
                float inv = 1.f / el;
                float ex = coords[s * 3 + 0] - coords[node * 3 + 0];
                float ey = coords[s * 3 + 1] - coords[node * 3 + 1];
                float ez = coords[s * 3 + 2] - coords[node * 3 + 2];
                if (kb == 32) { a0 = ex * inv; a1 = ey * inv; }
                else          { a0 = ez * inv; a1 = 1.0f; }   // kb == 34
            }
        }
        float h0 = __bfloat162float(__float2bfloat16_rn(a0));
        float h1 = __bfloat162float(__float2bfloat16_rn(a1));
        outp[idx]        = pack_bf16x2(h0, h1);
        outp[idx + 3072] = pack_bf16x2(a0 - h0, a1 - h1);
    }
}

// ---------------- B fragments for k_edge: We (+be as row 35) --------------
__global__ void __launch_bounds__(256) k_befrag(const float* __restrict__ We,
                                                const float* __restrict__ be) {
    int cc = blockIdx.x, l = blockIdx.y;
    const float* w = We + (size_t)l * EDIM * X2H;
    const float* bp = be + (size_t)l * X2H;
    unsigned* outp = d_bfrag + (size_t)(l * 4 + cc) * 6144;
    for (int idx = threadIdx.x; idx < 3072; idx += 256) {
        int q = idx & 3;
        int ts = q >> 1, rb = q & 1;
        int lane = (idx >> 2) & 31;
        int tp = (idx >> 7) & 7;
        int ks = idx >> 10;
        int tile = 2 * tp + ts;
        int kb = ks * 16 + 8 * rb + 2 * (lane & 3);
        int gcol = cc * 128 + tile * 8 + (lane >> 2);
        float b0 = (kb < EDIM) ? w[kb * X2H + gcol] : ((kb == 35) ? bp[gcol] : 0.f);
        int kb1 = kb + 1;
        float b1 = (kb1 < EDIM) ? w[kb1 * X2H + gcol] : ((kb1 == 35) ? bp[gcol] : 0.f);
        float h0 = __bfloat162float(__float2bfloat16_rn(b0));
        float h1 = __bfloat162float(__float2bfloat16_rn(b1));
        outp[idx]        = pack_bf16x2(h0, h1);
        outp[idx + 3072] = pack_bf16x2(b0 - h0, b1 - h1);
    }
}

// ---------------- weight fragments for MLP GEMMs (device-symbol dst) ------
template <int KS>
__global__ void __launch_bounds__(256) k_wfrag(const float* __restrict__ W) {
    int ksg = blockIdx.x, l = blockIdx.y;
    const float* wl = W + (size_t)l * KS * 16 * HH;
    unsigned* dl = ((KS == 32) ? d_w1frag : d_w2frag) + (size_t)l * KS * 4096;
    for (int idx = threadIdx.x; idx < 2048; idx += 256) {
        int ntg = idx >> 6;
        int lane = (idx >> 1) & 31;
        int tt = idx & 1;
        int kb = ksg * 16 + 8 * tt + 2 * (lane & 3);
        int col = ntg * 8 + (lane >> 2);
        float b0 = wl[(size_t)kb * HH + col];
        float b1 = wl[(size_t)(kb + 1) * HH + col];
        float h0 = __bfloat162float(__float2bfloat16_rn(b0));
        float h1 = __bfloat162float(__float2bfloat16_rn(b1));
        dl[(size_t)ksg * 2048 + idx] = pack_bf16x2(h0, h1);
        dl[(size_t)KS * 2048 + (size_t)ksg * 2048 + idx] = pack_bf16x2(b0 - h0, b1 - h1);
    }
}

// ---------------- k_edge: warp-per-node, double-buffered B ----------------
#define OFF_AF   0        // A hi|lo : 6144 words
#define OFF_BF   6144     // B double buffer: 2 x 6144 words
#define OFF_STP  18432    // 256
#define SMEM_EDGE_WORDS 18688

__global__ void __launch_bounds__(256) k_edge(int l) {
    extern __shared__ float sm[];
    unsigned* Af = (unsigned*)sm + OFF_AF;
    unsigned* Bf = (unsigned*)sm + OFF_BF;
    float* stp = sm + OFF_STP;
    __shared__ int ssrc[4][32];
    __shared__ int scnt[4];

    int t = threadIdx.x;
    int w = t >> 5, lane = t & 31;
    int i0 = blockIdx.x * 4;
    int g = i0 >> 9;

    if (t < 128) {
        int n = t >> 5, k = t & 31;
        int c = d_cnt[i0 + n];
        if (k == 0) scnt[n] = c;
        ssrc[n][k] = (k < c) ? d_nbr[(i0 + n) * KK + k] : (i0 + n);
    }
    stp[t] = d_tproj[(l * BB + g) * HH + t];  // t<256

    {
        const uint4* asrc = (const uint4*)(d_afrag + (size_t)blockIdx.x * 6144);
        uint4* adst = (uint4*)Af;
        for (int idx = t; idx < 1536; idx += 256) adst[idx] = asrc[idx];
    }
    __syncthreads();

    int node = w & 3, half = w >> 2;
    int cnt_n = scnt[node];
    int rr = lane >> 2;
    int s0 = ssrc[node][rr],      s1 = ssrc[node][rr + 8];
    int s2 = ssrc[node][rr + 16], s3 = ssrc[node][rr + 24];
    float mk0 = (rr      < cnt_n) ? 1.f : 0.f;
    float mk1 = (rr + 8  < cnt_n) ? 1.f : 0.f;
    float mk2 = (rr + 16 < cnt_n) ? 1.f : 0.f;
    float mk3 = (rr + 24 < cnt_n) ? 1.f : 0.f;
    int mg0 = 2 * node, mg1 = 2 * node + 1;

    for (int cc = 0; cc < 4; cc++) {
        unsigned* Bfc = Bf + (cc & 1) * 6144;
        {
            const uint4* bsrc = (const uint4*)(d_bfrag + (size_t)(l * 4 + cc) * 6144);
            uint4* bdst = (uint4*)Bfc;
            for (int idx = t; idx < 1536; idx += 256) bdst[idx] = bsrc[idx];
        }
        __syncthreads();

        float acc[2][8][4];
        #pragma unroll
        for (int m = 0; m < 2; m++)
            #pragma unroll
            for (int q = 0; q < 8; q++) {
                acc[m][q][0] = 0.f; acc[m][q][1] = 0.f;
                acc[m][q][2] = 0.f; acc[m][q][3] = 0.f;
            }
        #pragma unroll
        for (int ks = 0; ks < 3; ks++) {
            uint4 ah0 = *(const uint4*)&Af[((mg0 * 3 + ks) * 32 + lane) * 4];
            uint4 al0 = *(const uint4*)&Af[3072 + ((mg0 * 3 + ks) * 32 + lane) * 4];
            uint4 ah1 = *(const uint4*)&Af[((mg1 * 3 + ks) * 32 + lane) * 4];
            uint4 al1 = *(const uint4*)&Af[3072 + ((mg1 * 3 + ks) * 32 + lane) * 4];
            #pragma unroll
            for (int tt = 0; tt < 4; tt++) {
                int tp = half * 4 + tt;
                uint4 bh = *(const uint4*)&Bfc[((ks * 8 + tp) * 32 + lane) * 4];
                uint4 bl = *(const uint4*)&Bfc[3072 + ((ks * 8 + tp) * 32 + lane) * 4];
                mma_bf16(acc[0][2 * tt + 0], ah0, bh.x, bh.y);
                mma_bf16(acc[0][2 * tt + 0], al0, bh.x, bh.y);
                mma_bf16(acc[0][2 * tt + 0], ah0, bl.x, bl.y);
                mma_bf16(acc[0][2 * tt + 1], ah0, bh.z, bh.w);
                mma_bf16(acc[0][2 * tt + 1], al0, bh.z, bh.w);
                mma_bf16(acc[0][2 * tt + 1], ah0, bl.z, bl.w);
                mma_bf16(acc[1][2 * tt + 0], ah1, bh.x, bh.y);
                mma_bf16(acc[1][2 * tt + 0], al1, bh.x, bh.y);
                mma_bf16(acc[1][2 * tt + 0], ah1, bl.x, bl.y);
                mma_bf16(acc[1][2 * tt + 1], ah1, bh.z, bh.w);
                mma_bf16(acc[1][2 * tt + 1], al1, bh.z, bh.w);
                mma_bf16(acc[1][2 * tt + 1], ah1, bl.z, bl.w);
            }
        }
        // no sync here: next iteration writes the OTHER B buffer

        #pragma unroll
        for (int nt = 0; nt < 8; nt++) {
            int gcol = cc * 128 + half * 64 + nt * 8 + 2 * (lane & 3);
            float2 x0, x1, x2, x3;
            if (cc < 2) {
                x0 = *(const float2*)(d_h + (size_t)s0 * HH + gcol);
                x1 = *(const float2*)(d_h + (size_t)s1 * HH + gcol);
                x2 = *(const float2*)(d_h + (size_t)s2 * HH + gcol);
                x3 = *(const float2*)(d_h + (size_t)s3 * HH + gcol);
            } else {
                float2 tv = *(const float2*)&stp[gcol - HH];
                x0 = tv; x1 = tv; x2 = tv; x3 = tv;
            }
            float sA = mk0 * fmaxf(acc[0][nt][0] + x0.x, 0.f);
            sA = fmaf(mk1, fmaxf(acc[0][nt][2] + x1.x, 0.f), sA);
            sA = fmaf(mk2, fmaxf(acc[1][nt][0] + x2.x, 0.f), sA);
            sA = fmaf(mk3, fmaxf(acc[1][nt][2] + x3.x, 0.f), sA);
            float sB = mk0 * fmaxf(acc[0][nt][1] + x0.y, 0.f);
            sB = fmaf(mk1, fmaxf(acc[0][nt][3] + x1.y, 0.f), sB);
            sB = fmaf(mk2, fmaxf(acc[1][nt][1] + x2.y, 0.f), sB);
            sB = fmaf(mk3, fmaxf(acc[1][nt][3] + x3.y, 0.f), sB);
            #pragma unroll
            for (int off = 16; off >= 4; off >>= 1) {
                sA += __shfl_down_sync(0xffffffffu, sA, off);
                sB += __shfl_down_sync(0xffffffffu, sB, off);
            }
            if (lane < 4) {
                int gc = cc * 128 + half * 64 + nt * 8 + 2 * lane;
                *(float2*)(d_aggr + (size_t)(i0 + node) * X2H + gc) = make_float2(sA, sB);
            }
        }
    }
}

// ---------------- tensor-core MLP GEMM (wide: 64 rows x 128 cols) ---------
// grid (2, 64); 8 warps = 4 m-tiles x 2 col-64-halves (8 n-tiles each).
// MODE0: z1 = silu(((1+eps)*[h|tproj] + aggr) @ W1 + b1)   K=512
// MODE1: z  = z1 @ W2 + b2 (+ GraphNorm col partials)       K=256
// smem: Af 4096 (hi|lo) | Bf 8192 (hi|lo 4096) | stp 256 = 12544 words
#define SMEM_G_WORDS 12544

template <int MODE>
__global__ void __launch_bounds__(256) k_mgemm(const float* __restrict__ bias,
                                               const float* __restrict__ epsp, int l) {
    const int KS = (MODE == 0) ? 32 : 16;
    const int NKSC = KS / 4;
    extern __shared__ float sm[];
    unsigned* Af = (unsigned*)sm;          // hi 0..2048, lo 2048..4096
    unsigned* Bf = (unsigned*)sm + 4096;   // hi 0..4096, lo 4096..8192
    float* stp = sm + 12288;               // 256
    int t = threadIdx.x;
    int w = t >> 5, lane = t & 31;
    int bx = blockIdx.x, mb = blockIdx.y;  // bx in {0,1}: 128-col half
    int m0 = mb * 64;
    int g = m0 >> 9;
    float ep = (MODE == 0) ? (1.f + epsp[l]) : 0.f;
    if (MODE == 0 && t < HH) stp[t] = d_tproj[(l * BB + g) * HH + t];
    const unsigned* wl = ((MODE == 0) ? d_w1frag : d_w2frag) + (size_t)l * KS * 4096;
    int mt = w & 3, half = w >> 2;

    float acc[8][4];
    #pragma unroll
    for (int q = 0; q < 8; q++) {
        acc[q][0] = 0.f; acc[q][1] = 0.f; acc[q][2] = 0.f; acc[q][3] = 0.f;
    }

    for (int ksc = 0; ksc < NKSC; ksc++) {
        __syncthreads();
        // stage A: bf16 hi/lo fragments with fused input epilogue
        for (int idx = t; idx < 2048; idx += 256) {
            int mtl = idx >> 9;
            int rem = idx & 511;
            int ksl = rem >> 7;
            int ln = (rem >> 2) & 31;
            int r = idx & 3;
            int row = m0 + 16 * mtl + 8 * (r & 1) + (ln >> 2);
            int kb = ksc * 64 + ksl * 16 + 8 * (r >> 1) + 2 * (ln & 3);
            float v0, v1;
            if (MODE == 0) {
                float2 ag = *(const float2*)(d_aggr + (size_t)row * X2H + kb);
                float2 hx;
                if (kb < HH) hx = *(const float2*)(d_h + (size_t)row * HH + kb);
                else         hx = *(const float2*)&stp[kb - HH];
                v0 = fmaf(ep, hx.x, ag.x);
                v1 = fmaf(ep, hx.y, ag.y);
            } else {
                float2 zz = *(const float2*)(d_z1 + (size_t)row * HH + kb);
                v0 = zz.x; v1 = zz.y;
            }
            float h0 = __bfloat162float(__float2bfloat16_rn(v0));
            float h1 = __bfloat162float(__float2bfloat16_rn(v1));
            Af[idx]        = pack_bf16x2(h0, h1);
            Af[idx + 2048] = pack_bf16x2(v0 - h0, v1 - h1);
        }
        // stage B: 128-col slice of precomputed weight fragments (1 uint4/thr/region)
        #pragma unroll
        for (int ks4 = 0; ks4 < 4; ks4++) {
            int ksg = ksc * 4 + ks4;
            const uint4* sh = (const uint4*)(wl + (size_t)ksg * 2048 + bx * 1024);
            const uint4* sl = (const uint4*)(wl + (size_t)KS * 2048 +
                                             (size_t)ksg * 2048 + bx * 1024);
            ((uint4*)(Bf + ks4 * 1024))[t] = sh[t];
            ((uint4*)(Bf + 4096 + ks4 * 1024))[t] = sl[t];
        }
        __syncthreads();
        #pragma unroll
        for (int ks = 0; ks < 4; ks++) {
            uint4 ah = *(const uint4*)&Af[((mt * 4 + ks) * 32 + lane) * 4];
            uint4 al = *(const uint4*)&Af[2048 + ((mt * 4 + ks) * 32 + lane) * 4];
            #pragma unroll
            for (int j = 0; j < 8; j++) {
                int ntl = half * 8 + j;
                uint2 bh = *(const uint2*)&Bf[ks * 1024 + ntl * 64 + lane * 2];
                uint2 bl = *(const uint2*)&Bf[4096 + ks * 1024 + ntl * 64 + lane * 2];
                mma_bf16(acc[j], ah, bh.x, bh.y);
                mma_bf16(acc[j], al, bh.x, bh.y);
                mma_bf16(acc[j], ah, bl.x, bl.y);
            }
        }
    }
    __syncthreads();

    int r0 = m0 + mt * 16 + (lane >> 2);
    if (MODE == 0) {
        #pragma unroll
        for (int j = 0; j < 8; j++) {
            int col = bx * 128 + (half * 8 + j) * 8 + 2 * (lane & 3);
            float b0v = bias[col], b1v = bias[col + 1];
            *(float2*)(d_z1 + (size_t)r0 * HH + col) =
                make_float2(silu_f(acc[j][0] + b0v), silu_f(acc[j][1] + b1v));
            *(float2*)(d_z1 + (size_t)(r0 + 8) * HH + col) =
                make_float2(silu_f(acc[j][2] + b0v), silu_f(acc[j][3] + b1v));
        }
    } else {
        float* sps = sm;          // reuse Af region: 4*128 + 4*128 floats
        float* spq = sm + 512;
        #pragma unroll
        for (int j = 0; j < 8; j++) {
            int cl = (half * 8 + j) * 8 + 2 * (lane & 3);
            int col = bx * 128 + cl;
            float b0v = bias[col], b1v = bias[col + 1];
            float v00 = acc[j][0] + b0v, v01 = acc[j][1] + b1v;
            float v10 = acc[j][2] + b0v, v11 = acc[j][3] + b1v;
            *(float2*)(d_z + (size_t)r0 * HH + col) = make_float2(v00, v01);
            *(float2*)(d_z + (size_t)(r0 + 8) * HH + col) = make_float2(v10, v11);
            float s0 = v00 + v10, s1 = v01 + v11;
            float q0 = v00 * v00 + v10 * v10, q1 = v01 * v01 + v11 * v11;
            #pragma unroll
            for (int off = 16; off >= 4; off >>= 1) {
                s0 += __shfl_down_sync(0xffffffffu, s0, off);
                s1 += __shfl_down_sync(0xffffffffu, s1, off);
                q0 += __shfl_down_sync(0xffffffffu, q0, off);
                q1 += __shfl_down_sync(0xffffffffu, q1, off);
            }
            if (lane < 4) {
                int c2 = (half * 8 + j) * 8 + 2 * lane;
                sps[mt * 128 + c2] = s0; sps[mt * 128 + c2 + 1] = s1;
                spq[mt * 128 + c2] = q0; spq[mt * 128 + c2 + 1] = q1;
            }
        }
        __syncthreads();
        if (t < 128) {
            float S = 0.f, Q = 0.f;
            #pragma unroll
            for (int p = 0; p < 4; p++) { S += sps[p * 128 + t]; Q += spq[p * 128 + t]; }
            d_psum[mb * HH + bx * 128 + t] = S;
            d_psumq[mb * HH + bx * 128 + t] = Q;
        }
    }
}

// ---------------- GraphNorm finalize (folds gemm1 partials) ---------------
__global__ void k_gfin(const float* __restrict__ gw, const float* __restrict__ gb,
                       const float* __restrict__ gms) {
    int nb = blockIdx.x * 64;
    int g = nb >> 9;
    int c = threadIdx.x;
    float s = 0.f, q = 0.f;
    #pragma unroll
    for (int p = 0; p < 8; p++) {
        s += d_psum[(g * 8 + p) * HH + c];
        q += d_psumq[(g * 8 + p) * HH + c];
    }
    float mean = s * (1.f / 512.f);
    float ez2  = q * (1.f / 512.f);
    float mm = mean * gms[c];
    float var = ez2 - 2.f * mm * mean + mm * mm;
    float inv = 1.f / sqrtf(var + 1e-5f);
    float w = gw[c], b = gb[c];
    for (int n = 0; n < 64; n++) {
        size_t id = (size_t)(nb + n) * HH + c;
        float cc = d_z[id] - mm;
        float zn = fmaf(w * cc, inv, b);
        float hv = zn + d_h[id];
        d_h[id] = silu_f(hv);
    }
}

// ---------------- output head ----------------
__global__ void k_out(const float* __restrict__ Wout, const float* __restrict__ bout,
                      float* __restrict__ out) {
    __shared__ float sw[HH * 3];
    int t = threadIdx.x;
    for (int idx = t; idx < HH * 3; idx += 256) sw[idx] = Wout[idx];
    __syncthreads();
    int w = t >> 5, lane = t & 31;
    int i = blockIdx.x * 8 + w;
    float a0 = 0.f, a1 = 0.f, a2 = 0.f;
    for (int c = lane; c < HH; c += 32) {
        float hv = d_h[(size_t)i * HH + c];
        a0 = fmaf(hv, sw[c * 3 + 0], a0);
        a1 = fmaf(hv, sw[c * 3 + 1], a1);
        a2 = fmaf(hv, sw[c * 3 + 2], a2);
    }
    #pragma unroll
    for (int off = 16; off; off >>= 1) {
        a0 += __shfl_down_sync(0xffffffffu, a0, off);
        a1 += __shfl_down_sync(0xffffffffu, a1, off);
        a2 += __shfl_down_sync(0xffffffffu, a2, off);
    }
    if (lane == 0) {
        out[i * 3 + 0] = a0 + bout[0];
        out[i * 3 + 1] = a1 + bout[1];
        out[i * 3 + 2] = a2 + bout[2];
    }
}

// -------------------------------------------------------------------------
extern "C" void kernel_launch(void* const* d_in, const int* in_sizes, int n_in,
                              void* d_out, int out_size) {
    const float* coords = (const float*)d_in[0];
    const float* tin  = (const float*)d_in[2];
    const float* Wgfp = (const float*)d_in[3];
    const float* Wt_  = (const float*)d_in[4];
    const float* bt_  = (const float*)d_in[5];
    const float* Win  = (const float*)d_in[6];
    const float* bin  = (const float*)d_in[7];
    const float* W1   = (const float*)d_in[8];
    const float* b1   = (const float*)d_in[9];
    const float* W2   = (const float*)d_in[10];
    const float* b2   = (const float*)d_in[11];
    const float* We   = (const float*)d_in[12];
    const float* be   = (const float*)d_in[13];
    const float* eps  = (const float*)d_in[14];
    const float* gnw  = (const float*)d_in[15];
    const float* gnb  = (const float*)d_in[16];
    const float* gnms = (const float*)d_in[17];
    const float* Wtl  = (const float*)d_in[18];
    const float* btl  = (const float*)d_in[19];
    const float* Wout = (const float*)d_in[20];
    const float* bout = (const float*)d_in[21];
    float* out = (float*)d_out;

    const int smem_edge = SMEM_EDGE_WORDS * 4;   // 74752 B
    const int smem_g = SMEM_G_WORDS * 4;         // 50176 B
    cudaFuncSetAttribute(k_edge, cudaFuncAttributeMaxDynamicSharedMemorySize, smem_edge);
    cudaFuncSetAttribute(k_mgemm<0>, cudaFuncAttributeMaxDynamicSharedMemorySize, smem_g);
    cudaFuncSetAttribute(k_mgemm<1>, cudaFuncAttributeMaxDynamicSharedMemorySize, smem_g);

    k_temb<<<1, 128>>>(tin, Wgfp, Wt_, bt_);
    k_tproj<<<LL * BB, 256>>>(Wtl, btl);
    k_hin<<<NN, 256>>>(coords, Win, bin);
    k_nbr<<<NN / 4, 128>>>(coords);
    k_afrag<<<NN / 4, 256>>>(coords);
    k_befrag<<<dim3(4, LL), 256>>>(We, be);
    k_wfrag<32><<<dim3(32, LL), 256>>>(W1);
    k_wfrag<16><<<dim3(16, LL), 256>>>(W2);

    for (int l = 0; l < LL; l++) {
        k_edge<<<NN / 4, 256, smem_edge>>>(l);
        k_mgemm<0><<<dim3(2, 64), 256, smem_g>>>(b1 + l * HH, eps, l);
        k_mgemm<1><<<dim3(2, 64), 256, smem_g>>>(b2 + l * HH, eps, l);
        k_gfin<<<64, 256>>>(gnw + l * HH, gnb + l * HH, gnms + l * HH);
    }
    k_out<<<NN / 8, 256>>>(Wout, bout, out);
}

// round 13
// speedup vs baseline: 1.8074x; 1.0024x over previous
#include <cuda_runtime.h>
#include <cuda_bf16.h>
#include <math.h>

#define NN     4096
#define BB     8
#define NPG    512
#define KK     30
#define NBASIS 32
#define EDIM   35      // NBASIS + 3
#define HH     256
#define X2H    512
#define TT     128
#define LL     5
#define RADIUS 1.5f

// ---------------- static scratch (no allocations allowed) ----------------
__device__ __align__(16) float d_tfeat[BB * TT];
__device__ __align__(16) float d_tproj[LL * BB * HH];
__device__ __align__(16) float d_h[NN * HH];
__device__ __align__(16) float d_aggr[NN * X2H];
__device__ __align__(16) float d_z1[NN * HH];
__device__ __align__(16) float d_z[NN * HH];
// bf16x2-packed fragments, hi | lo
__device__ __align__(16) unsigned d_afrag[(NN / 4) * 6144];   // edge A frags per 4-node block
__device__ __align__(16) unsigned d_bfrag[LL * 4 * 6144];     // edge B frags per (layer, chunk)
__device__ __align__(16) unsigned d_w1frag[LL * 32 * 4096];   // W1 frags (hi | lo per layer)
__device__ __align__(16) unsigned d_w2frag[LL * 16 * 4096];   // W2 frags
__device__ int   d_nbr[NN * KK];
__device__ int   d_cnt[NN];
__device__ float d_elen[NN * KK];
__device__ __align__(16) float d_psum[64 * HH];   // gemm1 per-mblock col sums
__device__ __align__(16) float d_psumq[64 * HH];  // gemm1 per-mblock col sumsq

__device__ __forceinline__ float silu_f(float v) { return v / (1.f + expf(-v)); }

// ---------------- bf16 helpers ----------------
__device__ __forceinline__ unsigned pack_bf16x2(float a, float b) {
    __nv_bfloat162 h = __floats2bfloat162_rn(a, b);
    return *(unsigned*)&h;
}
__device__ __forceinline__ void mma_bf16(float* c, uint4 a, unsigned b0, unsigned b1) {
    asm volatile(
        "mma.sync.aligned.m16n8k16.row.col.f32.bf16.bf16.f32 "
        "{%0,%1,%2,%3}, {%4,%5,%6,%7}, {%8,%9}, {%0,%1,%2,%3};"
        : "+f"(c[0]), "+f"(c[1]), "+f"(c[2]), "+f"(c[3])
        : "r"(a.x), "r"(a.y), "r"(a.z), "r"(a.w), "r"(b0), "r"(b1));
}

// ---------------- time embedding ----------------
__global__ void k_temb(const float* __restrict__ tin, const float* __restrict__ wgfp,
                       const float* __restrict__ wt, const float* __restrict__ bt) {
    __shared__ float ss[64], sc[64];
    int t = threadIdx.x; // 128
    for (int b = 0; b < BB; b++) {
        if (t < 64) {
            float xp = 6.283185307179586f * tin[b] * wgfp[t];
            ss[t] = sinf(xp);
            sc[t] = cosf(xp);
        }
        __syncthreads();
        float acc = bt[t];
        #pragma unroll 8
        for (int h = 0; h < 64; h++) {
            acc = fmaf(ss[h], wt[h * TT + t], acc);
            acc = fmaf(sc[h], wt[(64 + h) * TT + t], acc);
        }
        d_tfeat[b * TT + t] = silu_f(acc);
        __syncthreads();
    }
}

__global__ void k_tproj(const float* __restrict__ Wt, const float* __restrict__ bt) {
    int l = blockIdx.x / BB, b = blockIdx.x % BB;
    int c = threadIdx.x; // 256
    __shared__ float tf[TT];
    if (c < TT) tf[c] = d_tfeat[b * TT + c];
    __syncthreads();
    float acc = bt[l * HH + c];
    const float* w = Wt + (size_t)l * TT * HH;
    #pragma unroll 8
    for (int k = 0; k < TT; k++) acc = fmaf(tf[k], w[k * HH + c], acc);
    d_tproj[(l * BB + b) * HH + c] = acc;
}

__global__ void k_hin(const float* __restrict__ coords, const float* __restrict__ Win,
                      const float* __restrict__ bin) {
    int i = blockIdx.x;
    int c = threadIdx.x;
    float x0 = coords[i * 3 + 0], x1 = coords[i * 3 + 1], x2 = coords[i * 3 + 2];
    float v = fmaf(x0, Win[c], fmaf(x1, Win[HH + c], fmaf(x2, Win[2 * HH + c], bin[c])));
    d_h[(size_t)i * HH + c] = v;
}

// ---------------- radius graph (stores selected distances too) ------------
__global__ void __launch_bounds__(128) k_nbr(const float* __restrict__ coords) {
    __shared__ float sx[NPG], sy[NPG], sz[NPG];
    __shared__ float sd[4][NPG];
    int t = threadIdx.x;
    int base = blockIdx.x * 4;
    int goff = (base >> 9) << 9;
    for (int j = t; j < NPG; j += 128) {
        sx[j] = coords[(goff + j) * 3 + 0];
        sy[j] = coords[(goff + j) * 3 + 1];
        sz[j] = coords[(goff + j) * 3 + 2];
    }
    __syncthreads();
    int w = t >> 5, lane = t & 31;
    int il = (base & 511) + w;
    int ig = goff + il;
    float xi = sx[il], yi = sy[il], zi = sz[il];
    float sqi = xi * xi + yi * yi + zi * zi;
    for (int j = lane; j < NPG; j += 32) {
        float xj = sx[j], yj = sy[j], zj = sz[j];
        float dot = xi * xj + yi * yj + zi * zj;
        float sqj = xj * xj + yj * yj + zj * zj;
        float d2 = sqi + sqj - 2.f * dot;
        float d = sqrtf(fmaxf(d2, 1e-12f));
        sd[w][j] = (j != il && d < RADIUS) ? d : INFINITY;
    }
    __syncwarp();
    int cc = 0;
    for (int k = 0; k < KK; k++) {
        float best = INFINITY;
        int bi = -1;
        for (int j = lane; j < NPG; j += 32) {
            float v = sd[w][j];
            if (v < best) { best = v; bi = j; }
        }
        #pragma unroll
        for (int off = 16; off; off >>= 1) {
            float ov = __shfl_down_sync(0xffffffffu, best, off);
            int oi = __shfl_down_sync(0xffffffffu, bi, off);
            if (ov < best || (ov == best && (unsigned)oi < (unsigned)bi)) { best = ov; bi = oi; }
        }
        best = __shfl_sync(0xffffffffu, best, 0);
        bi = __shfl_sync(0xffffffffu, bi, 0);
        if (!(best < INFINITY)) break;
        if (lane == 0) {
            d_nbr[ig * KK + k] = goff + bi;
            d_elen[ig * KK + k] = best;
            sd[w][bi] = INFINITY;
        }
        cc = k + 1;
        __syncwarp();
    }
    if (lane == 0) d_cnt[ig] = cc;
}

// ---------------- A fragments: edge attrs computed directly ---------------
__global__ void __launch_bounds__(256) k_afrag(const float* __restrict__ coords) {
    int blk = blockIdx.x;            // 1024 blocks of 4 nodes
    int i0 = blk * 4;
    unsigned* outp = d_afrag + (size_t)blk * 6144;
    const float step = RADIUS / 33.f;
    const float istep = 33.f / RADIUS;
    for (int idx = threadIdx.x; idx < 3072; idx += 256) {
        int r = idx & 3;
        int lane = (idx >> 2) & 31;
        int ks = (idx >> 7) % 3;
        int mg = idx / 384;
        int row = 16 * mg + 8 * (r & 1) + (lane >> 2);
        int kb = ks * 16 + 8 * (r >> 1) + 2 * (lane & 3);
        int n = row >> 5, k = row & 31;
        int node = i0 + n;
        float a0 = 0.f, a1 = 0.f;
        if (k < d_cnt[node] && kb < 36) {
            float el = d_elen[node * KK + k];
            if (kb < 32) {
                float d0 = (el - (float)(kb + 1) * step) * istep;
                float d1 = (el - (float)(kb + 2) * step) * istep;
                a0 = expf(-d0 * d0) * (1.f / 1.12f);
                a1 = expf(-d1 * d1) * (1.f / 1.12f);
            } else {
                int s = d_nbr[node * KK + k];
                float inv = 1.f / el;
                float ex = coords[s * 3 + 0] - coords[node * 3 + 0];
                float ey = coords[s * 3 + 1] - coords[node * 3 + 1];
                float ez = coords[s * 3 + 2] - coords[node * 3 + 2];
                if (kb == 32) { a0 = ex * inv; a1 = ey * inv; }
                else          { a0 = ez * inv; a1 = 1.0f; }   // kb == 34
            }
        }
        float h0 = __bfloat162float(__float2bfloat16_rn(a0));
        float h1 = __bfloat162float(__float2bfloat16_rn(a1));
        outp[idx]        = pack_bf16x2(h0, h1);
        outp[idx + 3072] = pack_bf16x2(a0 - h0, a1 - h1);
    }
}

// ---------------- B fragments for k_edge: We (+be as row 35) --------------
__global__ void __launch_bounds__(256) k_befrag(const float* __restrict__ We,
                                                const float* __restrict__ be) {
    int cc = blockIdx.x, l = blockIdx.y;
    const float* w = We + (size_t)l * EDIM * X2H;
    const float* bp = be + (size_t)l * X2H;
    unsigned* outp = d_bfrag + (size_t)(l * 4 + cc) * 6144;
    for (int idx = threadIdx.x; idx < 3072; idx += 256) {
        int q = idx & 3;
        int ts = q >> 1, rb = q & 1;
        int lane = (idx >> 2) & 31;
        int tp = (idx >> 7) & 7;
        int ks = idx >> 10;
        int tile = 2 * tp + ts;
        int kb = ks * 16 + 8 * rb + 2 * (lane & 3);
        int gcol = cc * 128 + tile * 8 + (lane >> 2);
        float b0 = (kb < EDIM) ? w[kb * X2H + gcol] : ((kb == 35) ? bp[gcol] : 0.f);
        int kb1 = kb + 1;
        float b1 = (kb1 < EDIM) ? w[kb1 * X2H + gcol] : ((kb1 == 35) ? bp[gcol] : 0.f);
        float h0 = __bfloat162float(__float2bfloat16_rn(b0));
        float h1 = __bfloat162float(__float2bfloat16_rn(b1));
        outp[idx]        = pack_bf16x2(h0, h1);
        outp[idx + 3072] = pack_bf16x2(b0 - h0, b1 - h1);
    }
}

// ---------------- weight fragments for MLP GEMMs (device-symbol dst) ------
template <int KS>
__global__ void __launch_bounds__(256) k_wfrag(const float* __restrict__ W) {
    int ksg = blockIdx.x, l = blockIdx.y;
    const float* wl = W + (size_t)l * KS * 16 * HH;
    unsigned* dl = ((KS == 32) ? d_w1frag : d_w2frag) + (size_t)l * KS * 4096;
    for (int idx = threadIdx.x; idx < 2048; idx += 256) {
        int ntg = idx >> 6;
        int lane = (idx >> 1) & 31;
        int tt = idx & 1;
        int kb = ksg * 16 + 8 * tt + 2 * (lane & 3);
        int col = ntg * 8 + (lane >> 2);
        float b0 = wl[(size_t)kb * HH + col];
        float b1 = wl[(size_t)(kb + 1) * HH + col];
        float h0 = __bfloat162float(__float2bfloat16_rn(b0));
        float h1 = __bfloat162float(__float2bfloat16_rn(b1));
        dl[(size_t)ksg * 2048 + idx] = pack_bf16x2(h0, h1);
        dl[(size_t)KS * 2048 + (size_t)ksg * 2048 + idx] = pack_bf16x2(b0 - h0, b1 - h1);
    }
}

// ---------------- k_edge: warp-per-node, double-buffered B ----------------
#define OFF_AF   0        // A hi|lo : 6144 words
#define OFF_BF   6144     // B double buffer: 2 x 6144 words
#define OFF_STP  18432    // 256
#define SMEM_EDGE_WORDS 18688

__global__ void __launch_bounds__(256) k_edge(int l) {
    extern __shared__ float sm[];
    unsigned* Af = (unsigned*)sm + OFF_AF;
    unsigned* Bf = (unsigned*)sm + OFF_BF;
    float* stp = sm + OFF_STP;
    __shared__ int ssrc[4][32];
    __shared__ int scnt[4];

    int t = threadIdx.x;
    int w = t >> 5, lane = t & 31;
    int i0 = blockIdx.x * 4;
    int g = i0 >> 9;

    if (t < 128) {
        int n = t >> 5, k = t & 31;
        int c = d_cnt[i0 + n];
        if (k == 0) scnt[n] = c;
        ssrc[n][k] = (k < c) ? d_nbr[(i0 + n) * KK + k] : (i0 + n);
    }
    stp[t] = d_tproj[(l * BB + g) * HH + t];  // t<256

    {
        const uint4* asrc = (const uint4*)(d_afrag + (size_t)blockIdx.x * 6144);
        uint4* adst = (uint4*)Af;
        for (int idx = t; idx < 1536; idx += 256) adst[idx] = asrc[idx];
    }
    __syncthreads();

    int node = w & 3, half = w >> 2;
    int cnt_n = scnt[node];
    int rr = lane >> 2;
    int s0 = ssrc[node][rr],      s1 = ssrc[node][rr + 8];
    int s2 = ssrc[node][rr + 16], s3 = ssrc[node][rr + 24];
    float mk0 = (rr      < cnt_n) ? 1.f : 0.f;
    float mk1 = (rr + 8  < cnt_n) ? 1.f : 0.f;
    float mk2 = (rr + 16 < cnt_n) ? 1.f : 0.f;
    float mk3 = (rr + 24 < cnt_n) ? 1.f : 0.f;
    int mg0 = 2 * node, mg1 = 2 * node + 1;

    for (int cc = 0; cc < 4; cc++) {
        unsigned* Bfc = Bf + (cc & 1) * 6144;
        {
            const uint4* bsrc = (const uint4*)(d_bfrag + (size_t)(l * 4 + cc) * 6144);
            uint4* bdst = (uint4*)Bfc;
            for (int idx = t; idx < 1536; idx += 256) bdst[idx] = bsrc[idx];
        }
        __syncthreads();

        float acc[2][8][4];
        #pragma unroll
        for (int m = 0; m < 2; m++)
            #pragma unroll
            for (int q = 0; q < 8; q++) {
                acc[m][q][0] = 0.f; acc[m][q][1] = 0.f;
                acc[m][q][2] = 0.f; acc[m][q][3] = 0.f;
            }
        #pragma unroll
        for (int ks = 0; ks < 3; ks++) {
            uint4 ah0 = *(const uint4*)&Af[((mg0 * 3 + ks) * 32 + lane) * 4];
            uint4 al0 = *(const uint4*)&Af[3072 + ((mg0 * 3 + ks) * 32 + lane) * 4];
            uint4 ah1 = *(const uint4*)&Af[((mg1 * 3 + ks) * 32 + lane) * 4];
            uint4 al1 = *(const uint4*)&Af[3072 + ((mg1 * 3 + ks) * 32 + lane) * 4];
            #pragma unroll
            for (int tt = 0; tt < 4; tt++) {
                int tp = half * 4 + tt;
                uint4 bh = *(const uint4*)&Bfc[((ks * 8 + tp) * 32 + lane) * 4];
                uint4 bl = *(const uint4*)&Bfc[3072 + ((ks * 8 + tp) * 32 + lane) * 4];
                mma_bf16(acc[0][2 * tt + 0], ah0, bh.x, bh.y);
                mma_bf16(acc[0][2 * tt + 0], al0, bh.x, bh.y);
                mma_bf16(acc[0][2 * tt + 0], ah0, bl.x, bl.y);
                mma_bf16(acc[0][2 * tt + 1], ah0, bh.z, bh.w);
                mma_bf16(acc[0][2 * tt + 1], al0, bh.z, bh.w);
                mma_bf16(acc[0][2 * tt + 1], ah0, bl.z, bl.w);
                mma_bf16(acc[1][2 * tt + 0], ah1, bh.x, bh.y);
                mma_bf16(acc[1][2 * tt + 0], al1, bh.x, bh.y);
                mma_bf16(acc[1][2 * tt + 0], ah1, bl.x, bl.y);
                mma_bf16(acc[1][2 * tt + 1], ah1, bh.z, bh.w);
                mma_bf16(acc[1][2 * tt + 1], al1, bh.z, bh.w);
                mma_bf16(acc[1][2 * tt + 1], ah1, bl.z, bl.w);
            }
        }
        // no sync here: next iteration writes the OTHER B buffer

        #pragma unroll
        for (int nt = 0; nt < 8; nt++) {
            int gcol = cc * 128 + half * 64 + nt * 8 + 2 * (lane & 3);
            float2 x0, x1, x2, x3;
            if (cc < 2) {
                x0 = *(const float2*)(d_h + (size_t)s0 * HH + gcol);
                x1 = *(const float2*)(d_h + (size_t)s1 * HH + gcol);
                x2 = *(const float2*)(d_h + (size_t)s2 * HH + gcol);
                x3 = *(const float2*)(d_h + (size_t)s3 * HH + gcol);
            } else {
                float2 tv = *(const float2*)&stp[gcol - HH];
                x0 = tv; x1 = tv; x2 = tv; x3 = tv;
            }
            float sA = mk0 * fmaxf(acc[0][nt][0] + x0.x, 0.f);
            sA = fmaf(mk1, fmaxf(acc[0][nt][2] + x1.x, 0.f), sA);
            sA = fmaf(mk2, fmaxf(acc[1][nt][0] + x2.x, 0.f), sA);
            sA = fmaf(mk3, fmaxf(acc[1][nt][2] + x3.x, 0.f), sA);
            float sB = mk0 * fmaxf(acc[0][nt][1] + x0.y, 0.f);
            sB = fmaf(mk1, fmaxf(acc[0][nt][3] + x1.y, 0.f), sB);
            sB = fmaf(mk2, fmaxf(acc[1][nt][1] + x2.y, 0.f), sB);
            sB = fmaf(mk3, fmaxf(acc[1][nt][3] + x3.y, 0.f), sB);
            #pragma unroll
            for (int off = 16; off >= 4; off >>= 1) {
                sA += __shfl_down_sync(0xffffffffu, sA, off);
                sB += __shfl_down_sync(0xffffffffu, sB, off);
            }
            if (lane < 4) {
                int gc = cc * 128 + half * 64 + nt * 8 + 2 * lane;
                *(float2*)(d_aggr + (size_t)(i0 + node) * X2H + gc) = make_float2(sA, sB);
            }
        }
    }
}

// ---------------- tensor-core MLP GEMM (wide: 64 rows x 128 cols) ---------
// grid (2, 64); 8 warps = 4 m-tiles x 2 col-64-halves (8 n-tiles each).
// MODE0: z1 = silu(((1+eps)*[h|tproj] + aggr) @ W1 + b1)   K=512
// MODE1: z  = z1 @ W2 + b2 (+ GraphNorm col partials)       K=256
// smem: Af 4096 (hi|lo) | Bf 8192 (hi|lo 4096) | stp 256 = 12544 words
#define SMEM_G_WORDS 12544

template <int MODE>
__global__ void __launch_bounds__(256) k_mgemm(const float* __restrict__ bias,
                                               const float* __restrict__ epsp, int l) {
    const int KS = (MODE == 0) ? 32 : 16;
    const int NKSC = KS / 4;
    extern __shared__ float sm[];
    unsigned* Af = (unsigned*)sm;          // hi 0..2048, lo 2048..4096
    unsigned* Bf = (unsigned*)sm + 4096;   // hi 0..4096, lo 4096..8192
    float* stp = sm + 12288;               // 256
    int t = threadIdx.x;
    int w = t >> 5, lane = t & 31;
    int bx = blockIdx.x, mb = blockIdx.y;  // bx in {0,1}: 128-col half
    int m0 = mb * 64;
    int g = m0 >> 9;
    float ep = (MODE == 0) ? (1.f + epsp[l]) : 0.f;
    if (MODE == 0 && t < HH) stp[t] = d_tproj[(l * BB + g) * HH + t];
    const unsigned* wl = ((MODE == 0) ? d_w1frag : d_w2frag) + (size_t)l * KS * 4096;
    int mt = w & 3, half = w >> 2;

    float acc[8][4];
    #pragma unroll
    for (int q = 0; q < 8; q++) {
        acc[q][0] = 0.f; acc[q][1] = 0.f; acc[q][2] = 0.f; acc[q][3] = 0.f;
    }

    for (int ksc = 0; ksc < NKSC; ksc++) {
        __syncthreads();
        // stage A: bf16 hi/lo fragments with fused input epilogue
        for (int idx = t; idx < 2048; idx += 256) {
            int mtl = idx >> 9;
            int rem = idx & 511;
            int ksl = rem >> 7;
            int ln = (rem >> 2) & 31;
            int r = idx & 3;
            int row = m0 + 16 * mtl + 8 * (r & 1) + (ln >> 2);
            int kb = ksc * 64 + ksl * 16 + 8 * (r >> 1) + 2 * (ln & 3);
            float v0, v1;
            if (MODE == 0) {
                float2 ag = *(const float2*)(d_aggr + (size_t)row * X2H + kb);
                float2 hx;
                if (kb < HH) hx = *(const float2*)(d_h + (size_t)row * HH + kb);
                else         hx = *(const float2*)&stp[kb - HH];
                v0 = fmaf(ep, hx.x, ag.x);
                v1 = fmaf(ep, hx.y, ag.y);
            } else {
                float2 zz = *(const float2*)(d_z1 + (size_t)row * HH + kb);
                v0 = zz.x; v1 = zz.y;
            }
            float h0 = __bfloat162float(__float2bfloat16_rn(v0));
            float h1 = __bfloat162float(__float2bfloat16_rn(v1));
            Af[idx]        = pack_bf16x2(h0, h1);
            Af[idx + 2048] = pack_bf16x2(v0 - h0, v1 - h1);
        }
        // stage B: 128-col slice of precomputed weight fragments (1 uint4/thr/region)
        #pragma unroll
        for (int ks4 = 0; ks4 < 4; ks4++) {
            int ksg = ksc * 4 + ks4;
            const uint4* sh = (const uint4*)(wl + (size_t)ksg * 2048 + bx * 1024);
            const uint4* sl = (const uint4*)(wl + (size_t)KS * 2048 +
                                             (size_t)ksg * 2048 + bx * 1024);
            ((uint4*)(Bf + ks4 * 1024))[t] = sh[t];
            ((uint4*)(Bf + 4096 + ks4 * 1024))[t] = sl[t];
        }
        __syncthreads();
        #pragma unroll
        for (int ks = 0; ks < 4; ks++) {
            uint4 ah = *(const uint4*)&Af[((mt * 4 + ks) * 32 + lane) * 4];
            uint4 al = *(const uint4*)&Af[2048 + ((mt * 4 + ks) * 32 + lane) * 4];
            #pragma unroll
            for (int j = 0; j < 8; j++) {
                int ntl = half * 8 + j;
                uint2 bh = *(const uint2*)&Bf[ks * 1024 + ntl * 64 + lane * 2];
                uint2 bl = *(const uint2*)&Bf[4096 + ks * 1024 + ntl * 64 + lane * 2];
                mma_bf16(acc[j], ah, bh.x, bh.y);
                mma_bf16(acc[j], al, bh.x, bh.y);
                mma_bf16(acc[j], ah, bl.x, bl.y);
            }
        }
    }
    __syncthreads();

    int r0 = m0 + mt * 16 + (lane >> 2);
    if (MODE == 0) {
        #pragma unroll
        for (int j = 0; j < 8; j++) {
            int col = bx * 128 + (half * 8 + j) * 8 + 2 * (lane & 3);
            float b0v = bias[col], b1v = bias[col + 1];
            *(float2*)(d_z1 + (size_t)r0 * HH + col) =
                make_float2(silu_f(acc[j][0] + b0v), silu_f(acc[j][1] + b1v));
            *(float2*)(d_z1 + (size_t)(r0 + 8) * HH + col) =
                make_float2(silu_f(acc[j][2] + b0v), silu_f(acc[j][3] + b1v));
        }
    } else {
        float* sps = sm;          // reuse Af region: 4*128 + 4*128 floats
        float* spq = sm + 512;
        #pragma unroll
        for (int j = 0; j < 8; j++) {
            int cl = (half * 8 + j) * 8 + 2 * (lane & 3);
            int col = bx * 128 + cl;
            float b0v = bias[col], b1v = bias[col + 1];
            float v00 = acc[j][0] + b0v, v01 = acc[j][1] + b1v;
            float v10 = acc[j][2] + b0v, v11 = acc[j][3] + b1v;
            *(float2*)(d_z + (size_t)r0 * HH + col) = make_float2(v00, v01);
            *(float2*)(d_z + (size_t)(r0 + 8) * HH + col) = make_float2(v10, v11);
            float s0 = v00 + v10, s1 = v01 + v11;
            float q0 = v00 * v00 + v10 * v10, q1 = v01 * v01 + v11 * v11;
            #pragma unroll
            for (int off = 16; off >= 4; off >>= 1) {
                s0 += __shfl_down_sync(0xffffffffu, s0, off);
                s1 += __shfl_down_sync(0xffffffffu, s1, off);
                q0 += __shfl_down_sync(0xffffffffu, q0, off);
                q1 += __shfl_down_sync(0xffffffffu, q1, off);
            }
            if (lane < 4) {
                int c2 = (half * 8 + j) * 8 + 2 * lane;
                sps[mt * 128 + c2] = s0; sps[mt * 128 + c2 + 1] = s1;
                spq[mt * 128 + c2] = q0; spq[mt * 128 + c2 + 1] = q1;
            }
        }
        __syncthreads();
        if (t < 128) {
            float S = 0.f, Q = 0.f;
            #pragma unroll
            for (int p = 0; p < 4; p++) { S += sps[p * 128 + t]; Q += spq[p * 128 + t]; }
            d_psum[mb * HH + bx * 128 + t] = S;
            d_psumq[mb * HH + bx * 128 + t] = Q;
        }
    }
}

// ---------------- GraphNorm finalize (folds gemm1 partials) ---------------
__global__ void k_gfin(const float* __restrict__ gw, const float* __restrict__ gb,
                       const float* __restrict__ gms) {
    int nb = blockIdx.x * 64;
    int g = nb >> 9;
    int c = threadIdx.x;
    float s = 0.f, q = 0.f;
    #pragma unroll
    for (int p = 0; p < 8; p++) {
        s += d_psum[(g * 8 + p) * HH + c];
        q += d_psumq[(g * 8 + p) * HH + c];
    }
    float mean = s * (1.f / 512.f);
    float ez2  = q * (1.f / 512.f);
    float mm = mean * gms[c];
    float var = ez2 - 2.f * mm * mean + mm * mm;
    float inv = 1.f / sqrtf(var + 1e-5f);
    float w = gw[c], b = gb[c];
    for (int n = 0; n < 64; n++) {
        size_t id = (size_t)(nb + n) * HH + c;
        float cc = d_z[id] - mm;
        float zn = fmaf(w * cc, inv, b);
        float hv = zn + d_h[id];
        d_h[id] = silu_f(hv);
    }
}

// ---------------- output head ----------------
__global__ void k_out(const float* __restrict__ Wout, const float* __restrict__ bout,
                      float* __restrict__ out) {
    __shared__ float sw[HH * 3];
    int t = threadIdx.x;
    for (int idx = t; idx < HH * 3; idx += 256) sw[idx] = Wout[idx];
    __syncthreads();
    int w = t >> 5, lane = t & 31;
    int i = blockIdx.x * 8 + w;
    float a0 = 0.f, a1 = 0.f, a2 = 0.f;
    for (int c = lane; c < HH; c += 32) {
        float hv = d_h[(size_t)i * HH + c];
        a0 = fmaf(hv, sw[c * 3 + 0], a0);
        a1 = fmaf(hv, sw[c * 3 + 1], a1);
        a2 = fmaf(hv, sw[c * 3 + 2], a2);
    }
    #pragma unroll
    for (int off = 16; off; off >>= 1) {
        a0 += __shfl_down_sync(0xffffffffu, a0, off);
        a1 += __shfl_down_sync(0xffffffffu, a1, off);
        a2 += __shfl_down_sync(0xffffffffu, a2, off);
    }
    if (lane == 0) {
        out[i * 3 + 0] = a0 + bout[0];
        out[i * 3 + 1] = a1 + bout[1];
        out[i * 3 + 2] = a2 + bout[2];
    }
}

// -------------------------------------------------------------------------
extern "C" void kernel_launch(void* const* d_in, const int* in_sizes, int n_in,
                              void* d_out, int out_size) {
    const float* coords = (const float*)d_in[0];
    const float* tin  = (const float*)d_in[2];
    const float* Wgfp = (const float*)d_in[3];
    const float* Wt_  = (const float*)d_in[4];
    const float* bt_  = (const float*)d_in[5];
    const float* Win  = (const float*)d_in[6];
    const float* bin  = (const float*)d_in[7];
    const float* W1   = (const float*)d_in[8];
    const float* b1   = (const float*)d_in[9];
    const float* W2   = (const float*)d_in[10];
    const float* b2   = (const float*)d_in[11];
    const float* We   = (const float*)d_in[12];
    const float* be   = (const float*)d_in[13];
    const float* eps  = (const float*)d_in[14];
    const float* gnw  = (const float*)d_in[15];
    const float* gnb  = (const float*)d_in[16];
    const float* gnms = (const float*)d_in[17];
    const float* Wtl  = (const float*)d_in[18];
    const float* btl  = (const float*)d_in[19];
    const float* Wout = (const float*)d_in[20];
    const float* bout = (const float*)d_in[21];
    float* out = (float*)d_out;

    const int smem_edge = SMEM_EDGE_WORDS * 4;   // 74752 B
    const int smem_g = SMEM_G_WORDS * 4;         // 50176 B
    cudaFuncSetAttribute(k_edge, cudaFuncAttributeMaxDynamicSharedMemorySize, smem_edge);
    cudaFuncSetAttribute(k_mgemm<0>, cudaFuncAttributeMaxDynamicSharedMemorySize, smem_g);
    cudaFuncSetAttribute(k_mgemm<1>, cudaFuncAttributeMaxDynamicSharedMemorySize, smem_g);

    k_temb<<<1, 128>>>(tin, Wgfp, Wt_, bt_);
    k_tproj<<<LL * BB, 256>>>(Wtl, btl);
    k_hin<<<NN, 256>>>(coords, Win, bin);
    k_nbr<<<NN / 4, 128>>>(coords);
    k_afrag<<<NN / 4, 256>>>(coords);
    k_befrag<<<dim3(4, LL), 256>>>(We, be);
    k_wfrag<32><<<dim3(32, LL), 256>>>(W1);
    k_wfrag<16><<<dim3(16, LL), 256>>>(W2);

    for (int l = 0; l < LL; l++) {
        k_edge<<<NN / 4, 256, smem_edge>>>(l);
        k_mgemm<0><<<dim3(2, 64), 256, smem_g>>>(b1 + l * HH, eps, l);
        k_mgemm<1><<<dim3(2, 64), 256, smem_g>>>(b2 + l * HH, eps, l);
        k_gfin<<<64, 256>>>(gnw + l * HH, gnb + l * HH, gnms + l * HH);
    }
    k_out<<<NN / 8, 256>>>(Wout, bout, out);
}

// round 15
// speedup vs baseline: 1.9504x; 1.0791x over previous
#include <cuda_runtime.h>
#include <cuda_bf16.h>
#include <math.h>

#define NN     4096
#define BB     8
#define NPG    512
#define KK     30
#define NBASIS 32
#define EDIM   35      // NBASIS + 3
#define HH     256
#define X2H    512
#define TT     128
#define LL     5
#define RADIUS 1.5f

// ---------------- static scratch (no allocations allowed) ----------------
__device__ __align__(16) float d_tfeat[BB * TT];
__device__ __align__(16) float d_tproj[LL * BB * HH];
__device__ __align__(16) float d_h[NN * HH];
__device__ __align__(16) float d_aggr[NN * X2H];
__device__ __align__(16) float d_z1[NN * HH];
__device__ __align__(16) float d_z[NN * HH];
// bf16x2-packed fragments, hi | lo
__device__ __align__(16) unsigned d_afrag[(NN / 4) * 6144];   // edge A frags per 4-node block
__device__ __align__(16) unsigned d_bfrag[LL * 4 * 6144];     // edge B frags per (layer, chunk)
__device__ __align__(16) unsigned d_w1frag[LL * 32 * 4096];   // W1 frags (hi | lo per layer)
__device__ __align__(16) unsigned d_w2frag[LL * 16 * 4096];   // W2 frags
__device__ int   d_nbr[NN * KK];
__device__ int   d_cnt[NN];
__device__ float d_elen[NN * KK];
__device__ __align__(16) float d_psum[64 * HH];   // gemm1 per-mblock col sums
__device__ __align__(16) float d_psumq[64 * HH];  // gemm1 per-mblock col sumsq

__device__ __forceinline__ float silu_f(float v) { return v / (1.f + expf(-v)); }

// ---------------- bf16 helpers ----------------
__device__ __forceinline__ unsigned pack_bf16x2(float a, float b) {
    __nv_bfloat162 h = __floats2bfloat162_rn(a, b);
    return *(unsigned*)&h;
}
__device__ __forceinline__ void mma_bf16(float* c, uint4 a, unsigned b0, unsigned b1) {
    asm volatile(
        "mma.sync.aligned.m16n8k16.row.col.f32.bf16.bf16.f32 "
        "{%0,%1,%2,%3}, {%4,%5,%6,%7}, {%8,%9}, {%0,%1,%2,%3};"
        : "+f"(c[0]), "+f"(c[1]), "+f"(c[2]), "+f"(c[3])
        : "r"(a.x), "r"(a.y), "r"(a.z), "r"(a.w), "r"(b0), "r"(b1));
}

// ---------------- time embedding ----------------
__global__ void k_temb(const float* __restrict__ tin, const float* __restrict__ wgfp,
                       const float* __restrict__ wt, const float* __restrict__ bt) {
    __shared__ float ss[64], sc[64];
    int t = threadIdx.x; // 128
    for (int b = 0; b < BB; b++) {
        if (t < 64) {
            float xp = 6.283185307179586f * tin[b] * wgfp[t];
            ss[t] = sinf(xp);
            sc[t] = cosf(xp);
        }
        __syncthreads();
        float acc = bt[t];
        #pragma unroll 8
        for (int h = 0; h < 64; h++) {
            acc = fmaf(ss[h], wt[h * TT + t], acc);
            acc = fmaf(sc[h], wt[(64 + h) * TT + t], acc);
        }
        d_tfeat[b * TT + t] = silu_f(acc);
        __syncthreads();
    }
}

__global__ void k_tproj(const float* __restrict__ Wt, const float* __restrict__ bt) {
    int l = blockIdx.x / BB, b = blockIdx.x % BB;
    int c = threadIdx.x; // 256
    __shared__ float tf[TT];
    if (c < TT) tf[c] = d_tfeat[b * TT + c];
    __syncthreads();
    float acc = bt[l * HH + c];
    const float* w = Wt + (size_t)l * TT * HH;
    #pragma unroll 8
    for (int k = 0; k < TT; k++) acc = fmaf(tf[k], w[k * HH + c], acc);
    d_tproj[(l * BB + b) * HH + c] = acc;
}

__global__ void k_hin(const float* __restrict__ coords, const float* __restrict__ Win,
                      const float* __restrict__ bin) {
    int i = blockIdx.x;
    int c = threadIdx.x;
    float x0 = coords[i * 3 + 0], x1 = coords[i * 3 + 1], x2 = coords[i * 3 + 2];
    float v = fmaf(x0, Win[c], fmaf(x1, Win[HH + c], fmaf(x2, Win[2 * HH + c], bin[c])));
    d_h[(size_t)i * HH + c] = v;
}

// ---------------- radius graph (stores selected distances too) ------------
__global__ void __launch_bounds__(128) k_nbr(const float* __restrict__ coords) {
    __shared__ float sx[NPG], sy[NPG], sz[NPG];
    __shared__ float sd[4][NPG];
    int t = threadIdx.x;
    int base = blockIdx.x * 4;
    int goff = (base >> 9) << 9;
    for (int j = t; j < NPG; j += 128) {
        sx[j] = coords[(goff + j) * 3 + 0];
        sy[j] = coords[(goff + j) * 3 + 1];
        sz[j] = coords[(goff + j) * 3 + 2];
    }
    __syncthreads();
    int w = t >> 5, lane = t & 31;
    int il = (base & 511) + w;
    int ig = goff + il;
    float xi = sx[il], yi = sy[il], zi = sz[il];
    float sqi = xi * xi + yi * yi + zi * zi;
    for (int j = lane; j < NPG; j += 32) {
        float xj = sx[j], yj = sy[j], zj = sz[j];
        float dot = xi * xj + yi * yj + zi * zj;
        float sqj = xj * xj + yj * yj + zj * zj;
        float d2 = sqi + sqj - 2.f * dot;
        float d = sqrtf(fmaxf(d2, 1e-12f));
        sd[w][j] = (j != il && d < RADIUS) ? d : INFINITY;
    }
    __syncwarp();
    int cc = 0;
    for (int k = 0; k < KK; k++) {
        float best = INFINITY;
        int bi = -1;
        for (int j = lane; j < NPG; j += 32) {
            float v = sd[w][j];
            if (v < best) { best = v; bi = j; }
        }
        #pragma unroll
        for (int off = 16; off; off >>= 1) {
            float ov = __shfl_down_sync(0xffffffffu, best, off);
            int oi = __shfl_down_sync(0xffffffffu, bi, off);
            if (ov < best || (ov == best && (unsigned)oi < (unsigned)bi)) { best = ov; bi = oi; }
        }
        best = __shfl_sync(0xffffffffu, best, 0);
        bi = __shfl_sync(0xffffffffu, bi, 0);
        if (!(best < INFINITY)) break;
        if (lane == 0) {
            d_nbr[ig * KK + k] = goff + bi;
            d_elen[ig * KK + k] = best;
            sd[w][bi] = INFINITY;
        }
        cc = k + 1;
        __syncwarp();
    }
    if (lane == 0) d_cnt[ig] = cc;
}

// ---------------- A fragments: edge attrs computed directly ---------------
__global__ void __launch_bounds__(256) k_afrag(const float* __restrict__ coords) {
    int blk = blockIdx.x;            // 1024 blocks of 4 nodes
    int i0 = blk * 4;
    unsigned* outp = d_afrag + (size_t)blk * 6144;
    const float step = RADIUS / 33.f;
    const float istep = 33.f / RADIUS;
    for (int idx = threadIdx.x; idx < 3072; idx += 256) {
        int r = idx & 3;
        int lane = (idx >> 2) & 31;
        int ks = (idx >> 7) % 3;
        int mg = idx / 384;
        int row = 16 * mg + 8 * (r & 1) + (lane >> 2);
        int kb = ks * 16 + 8 * (r >> 1) + 2 * (lane & 3);
        int n = row >> 5, k = row & 31;
        int node = i0 + n;
        float a0 = 0.f, a1 = 0.f;
        if (k < d_cnt[node] && kb < 36) {
            float el = d_elen[node * KK + k];
            if (kb < 32) {
                float d0 = (el - (float)(kb + 1) * step) * istep;
                float d1 = (el - (float)(kb + 2) * step) * istep;
                a0 = expf(-d0 * d0) * (1.f / 1.12f);
                a1 = expf(-d1 * d1) * (1.f / 1.12f);
            } else {
                int s = d_nbr[node * KK + k];
                float inv = 1.f / el;
                float ex = coords[s * 3 + 0] - coords[node * 3 + 0];
                float ey = coords[s * 3 + 1] - coords[node * 3 + 1];
                float ez = coords[s * 3 + 2] - coords[node * 3 + 2];
                if (kb == 32) { a0 = ex * inv; a1 = ey * inv; }
                else          { a0 = ez * inv; a1 = 1.0f; }   // kb == 34
            }
        }
        float h0 = __bfloat162float(__float2bfloat16_rn(a0));
        float h1 = __bfloat162float(__float2bfloat16_rn(a1));
        outp[idx]        = pack_bf16x2(h0, h1);
        outp[idx + 3072] = pack_bf16x2(a0 - h0, a1 - h1);
    }
}

// ---------------- B fragments for k_edge: We (+be as row 35) --------------
__global__ void __launch_bounds__(256) k_befrag(const float* __restrict__ We,
                                                const float* __restrict__ be) {
    int cc = blockIdx.x, l = blockIdx.y;
    const float* w = We + (size_t)l * EDIM * X2H;
    const float* bp = be + (size_t)l * X2H;
    unsigned* outp = d_bfrag + (size_t)(l * 4 + cc) * 6144;
    for (int idx = threadIdx.x; idx < 3072; idx += 256) {
        int q = idx & 3;
        int ts = q >> 1, rb = q & 1;
        int lane = (idx >> 2) & 31;
        int tp = (idx >> 7) & 7;
        int ks = idx >> 10;
        int tile = 2 * tp + ts;
        int kb = ks * 16 + 8 * rb + 2 * (lane & 3);
        int gcol = cc * 128 + tile * 8 + (lane >> 2);
        float b0 = (kb < EDIM) ? w[kb * X2H + gcol] : ((kb == 35) ? bp[gcol] : 0.f);
        int kb1 = kb + 1;
        float b1 = (kb1 < EDIM) ? w[kb1 * X2H + gcol] : ((kb1 == 35) ? bp[gcol] : 0.f);
        float h0 = __bfloat162float(__float2bfloat16_rn(b0));
        float h1 = __bfloat162float(__float2bfloat16_rn(b1));
        outp[idx]        = pack_bf16x2(h0, h1);
        outp[idx + 3072] = pack_bf16x2(b0 - h0, b1 - h1);
    }
}

// ---------------- weight fragments for MLP GEMMs (device-symbol dst) ------
template <int KS>
__global__ void __launch_bounds__(256) k_wfrag(const float* __restrict__ W) {
    int ksg = blockIdx.x, l = blockIdx.y;
    const float* wl = W + (size_t)l * KS * 16 * HH;
    unsigned* dl = ((KS == 32) ? d_w1frag : d_w2frag) + (size_t)l * KS * 4096;
    for (int idx = threadIdx.x; idx < 2048; idx += 256) {
        int ntg = idx >> 6;
        int lane = (idx >> 1) & 31;
        int tt = idx & 1;
        int kb = ksg * 16 + 8 * tt + 2 * (lane & 3);
        int col = ntg * 8 + (lane >> 2);
        float b0 = wl[(size_t)kb * HH + col];
        float b1 = wl[(size_t)(kb + 1) * HH + col];
        float h0 = __bfloat162float(__float2bfloat16_rn(b0));
        float h1 = __bfloat162float(__float2bfloat16_rn(b1));
        dl[(size_t)ksg * 2048 + idx] = pack_bf16x2(h0, h1);
        dl[(size_t)KS * 2048 + (size_t)ksg * 2048 + idx] = pack_bf16x2(b0 - h0, b1 - h1);
    }
}

// ---------------- k_edge: warp-per-node, double-buffered B ----------------
#define OFF_AF   0        // A hi|lo : 6144 words
#define OFF_BF   6144     // B double buffer: 2 x 6144 words
#define OFF_STP  18432    // 256
#define SMEM_EDGE_WORDS 18688

__global__ void __launch_bounds__(256) k_edge(int l) {
    extern __shared__ float sm[];
    unsigned* Af = (unsigned*)sm + OFF_AF;
    unsigned* Bf = (unsigned*)sm + OFF_BF;
    float* stp = sm + OFF_STP;
    __shared__ int ssrc[4][32];
    __shared__ int scnt[4];

    int t = threadIdx.x;
    int w = t >> 5, lane = t & 31;
    int i0 = blockIdx.x * 4;
    int g = i0 >> 9;

    if (t < 128) {
        int n = t >> 5, k = t & 31;
        int c = d_cnt[i0 + n];
        if (k == 0) scnt[n] = c;
        ssrc[n][k] = (k < c) ? d_nbr[(i0 + n) * KK + k] : (i0 + n);
    }
    stp[t] = d_tproj[(l * BB + g) * HH + t];  // t<256

    {
        const uint4* asrc = (const uint4*)(d_afrag + (size_t)blockIdx.x * 6144);
        uint4* adst = (uint4*)Af;
        for (int idx = t; idx < 1536; idx += 256) adst[idx] = asrc[idx];
    }
    __syncthreads();

    int node = w & 3, half = w >> 2;
    int cnt_n = scnt[node];
    int rr = lane >> 2;
    int s0 = ssrc[node][rr],      s1 = ssrc[node][rr + 8];
    int s2 = ssrc[node][rr + 16], s3 = ssrc[node][rr + 24];
    float mk0 = (rr      < cnt_n) ? 1.f : 0.f;
    float mk1 = (rr + 8  < cnt_n) ? 1.f : 0.f;
    float mk2 = (rr + 16 < cnt_n) ? 1.f : 0.f;
    float mk3 = (rr + 24 < cnt_n) ? 1.f : 0.f;
    int mg0 = 2 * node, mg1 = 2 * node + 1;

    for (int cc = 0; cc < 4; cc++) {
        unsigned* Bfc = Bf + (cc & 1) * 6144;
        {
            const uint4* bsrc = (const uint4*)(d_bfrag + (size_t)(l * 4 + cc) * 6144);
            uint4* bdst = (uint4*)Bfc;
            for (int idx = t; idx < 1536; idx += 256) bdst[idx] = bsrc[idx];
        }
        __syncthreads();

        float acc[2][8][4];
        #pragma unroll
        for (int m = 0; m < 2; m++)
            #pragma unroll
            for (int q = 0; q < 8; q++) {
                acc[m][q][0] = 0.f; acc[m][q][1] = 0.f;
                acc[m][q][2] = 0.f; acc[m][q][3] = 0.f;
            }
        #pragma unroll
        for (int ks = 0; ks < 3; ks++) {
            uint4 ah0 = *(const uint4*)&Af[((mg0 * 3 + ks) * 32 + lane) * 4];
            uint4 al0 = *(const uint4*)&Af[3072 + ((mg0 * 3 + ks) * 32 + lane) * 4];
            uint4 ah1 = *(const uint4*)&Af[((mg1 * 3 + ks) * 32 + lane) * 4];
            uint4 al1 = *(const uint4*)&Af[3072 + ((mg1 * 3 + ks) * 32 + lane) * 4];
            #pragma unroll
            for (int tt = 0; tt < 4; tt++) {
                int tp = half * 4 + tt;
                uint4 bh = *(const uint4*)&Bfc[((ks * 8 + tp) * 32 + lane) * 4];
                uint4 bl = *(const uint4*)&Bfc[3072 + ((ks * 8 + tp) * 32 + lane) * 4];
                mma_bf16(acc[0][2 * tt + 0], ah0, bh.x, bh.y);
                mma_bf16(acc[0][2 * tt + 0], al0, bh.x, bh.y);
                mma_bf16(acc[0][2 * tt + 0], ah0, bl.x, bl.y);
                mma_bf16(acc[0][2 * tt + 1], ah0, bh.z, bh.w);
                mma_bf16(acc[0][2 * tt + 1], al0, bh.z, bh.w);
                mma_bf16(acc[0][2 * tt + 1], ah0, bl.z, bl.w);
                mma_bf16(acc[1][2 * tt + 0], ah1, bh.x, bh.y);
                mma_bf16(acc[1][2 * tt + 0], al1, bh.x, bh.y);
                mma_bf16(acc[1][2 * tt + 0], ah1, bl.x, bl.y);
                mma_bf16(acc[1][2 * tt + 1], ah1, bh.z, bh.w);
                mma_bf16(acc[1][2 * tt + 1], al1, bh.z, bh.w);
                mma_bf16(acc[1][2 * tt + 1], ah1, bl.z, bl.w);
            }
        }
        // no sync here: next iteration writes the OTHER B buffer

        #pragma unroll
        for (int nt = 0; nt < 8; nt++) {
            int gcol = cc * 128 + half * 64 + nt * 8 + 2 * (lane & 3);
            float2 x0, x1, x2, x3;
            if (cc < 2) {
                x0 = *(const float2*)(d_h + (size_t)s0 * HH + gcol);
                x1 = *(const float2*)(d_h + (size_t)s1 * HH + gcol);
                x2 = *(const float2*)(d_h + (size_t)s2 * HH + gcol);
                x3 = *(const float2*)(d_h + (size_t)s3 * HH + gcol);
            } else {
                float2 tv = *(const float2*)&stp[gcol - HH];
                x0 = tv; x1 = tv; x2 = tv; x3 = tv;
            }
            float sA = mk0 * fmaxf(acc[0][nt][0] + x0.x, 0.f);
            sA = fmaf(mk1, fmaxf(acc[0][nt][2] + x1.x, 0.f), sA);
            sA = fmaf(mk2, fmaxf(acc[1][nt][0] + x2.x, 0.f), sA);
            sA = fmaf(mk3, fmaxf(acc[1][nt][2] + x3.x, 0.f), sA);
            float sB = mk0 * fmaxf(acc[0][nt][1] + x0.y, 0.f);
            sB = fmaf(mk1, fmaxf(acc[0][nt][3] + x1.y, 0.f), sB);
            sB = fmaf(mk2, fmaxf(acc[1][nt][1] + x2.y, 0.f), sB);
            sB = fmaf(mk3, fmaxf(acc[1][nt][3] + x3.y, 0.f), sB);
            #pragma unroll
            for (int off = 16; off >= 4; off >>= 1) {
                sA += __shfl_down_sync(0xffffffffu, sA, off);
                sB += __shfl_down_sync(0xffffffffu, sB, off);
            }
            if (lane < 4) {
                int gc = cc * 128 + half * 64 + nt * 8 + 2 * lane;
                *(float2*)(d_aggr + (size_t)(i0 + node) * X2H + gc) = make_float2(sA, sB);
            }
        }
    }
}

// ---------------- tensor-core MLP GEMM (wide: 64 rows x 128 cols) ---------
// grid (2, 64); 8 warps = 4 m-tiles x 2 col-64-halves (8 n-tiles each).
// MODE0: z1 = silu(((1+eps)*[h|tproj] + aggr) @ W1 + b1)   K=512
// MODE1: z  = z1 @ W2 + b2 (+ GraphNorm col partials)       K=256
#define SMEM_G_WORDS 12544

template <int MODE>
__global__ void __launch_bounds__(256) k_mgemm(const float* __restrict__ bias,
                                               const float* __restrict__ epsp, int l) {
    const int KS = (MODE == 0) ? 32 : 16;
    const int NKSC = KS / 4;
    extern __shared__ float sm[];
    unsigned* Af = (unsigned*)sm;          // hi 0..2048, lo 2048..4096
    unsigned* Bf = (unsigned*)sm + 4096;   // hi 0..4096, lo 4096..8192
    float* stp = sm + 12288;               // 256
    int t = threadIdx.x;
    int w = t >> 5, lane = t & 31;
    int bx = blockIdx.x, mb = blockIdx.y;  // bx in {0,1}: 128-col half
    int m0 = mb * 64;
    int g = m0 >> 9;
    float ep = (MODE == 0) ? (1.f + epsp[l]) : 0.f;
    if (MODE == 0 && t < HH) stp[t] = d_tproj[(l * BB + g) * HH + t];
    const unsigned* wl = ((MODE == 0) ? d_w1frag : d_w2frag) + (size_t)l * KS * 4096;
    int mt = w & 3, half = w >> 2;

    float acc[8][4];
    #pragma unroll
    for (int q = 0; q < 8; q++) {
        acc[q][0] = 0.f; acc[q][1] = 0.f; acc[q][2] = 0.f; acc[q][3] = 0.f;
    }

    for (int ksc = 0; ksc < NKSC; ksc++) {
        __syncthreads();
        // stage A: bf16 hi/lo fragments with fused input epilogue
        for (int idx = t; idx < 2048; idx += 256) {
            int mtl = idx >> 9;
            int rem = idx & 511;
            int ksl = rem >> 7;
            int ln = (rem >> 2) & 31;
            int r = idx & 3;
            int row = m0 + 16 * mtl + 8 * (r & 1) + (ln >> 2);
            int kb = ksc * 64 + ksl * 16 + 8 * (r >> 1) + 2 * (ln & 3);
            float v0, v1;
            if (MODE == 0) {
                float2 ag = *(const float2*)(d_aggr + (size_t)row * X2H + kb);
                float2 hx;
                if (kb < HH) hx = *(const float2*)(d_h + (size_t)row * HH + kb);
                else         hx = *(const float2*)&stp[kb - HH];
                v0 = fmaf(ep, hx.x, ag.x);
                v1 = fmaf(ep, hx.y, ag.y);
            } else {
                float2 zz = *(const float2*)(d_z1 + (size_t)row * HH + kb);
                v0 = zz.x; v1 = zz.y;
            }
            float h0 = __bfloat162float(__float2bfloat16_rn(v0));
            float h1 = __bfloat162float(__float2bfloat16_rn(v1));
            Af[idx]        = pack_bf16x2(h0, h1);
            Af[idx + 2048] = pack_bf16x2(v0 - h0, v1 - h1);
        }
        // stage B: 128-col slice of precomputed weight fragments (1 uint4/thr/region)
        #pragma unroll
        for (int ks4 = 0; ks4 < 4; ks4++) {
            int ksg = ksc * 4 + ks4;
            const uint4* sh = (const uint4*)(wl + (size_t)ksg * 2048 + bx * 1024);
            const uint4* sl = (const uint4*)(wl + (size_t)KS * 2048 +
                                             (size_t)ksg * 2048 + bx * 1024);
            ((uint4*)(Bf + ks4 * 1024))[t] = sh[t];
            ((uint4*)(Bf + 4096 + ks4 * 1024))[t] = sl[t];
        }
        __syncthreads();
        #pragma unroll
        for (int ks = 0; ks < 4; ks++) {
            uint4 ah = *(const uint4*)&Af[((mt * 4 + ks) * 32 + lane) * 4];
            uint4 al = *(const uint4*)&Af[2048 + ((mt * 4 + ks) * 32 + lane) * 4];
            #pragma unroll
            for (int j = 0; j < 8; j++) {
                int ntl = half * 8 + j;
                uint2 bh = *(const uint2*)&Bf[ks * 1024 + ntl * 64 + lane * 2];
                uint2 bl = *(const uint2*)&Bf[4096 + ks * 1024 + ntl * 64 + lane * 2];
                mma_bf16(acc[j], ah, bh.x, bh.y);
                mma_bf16(acc[j], al, bh.x, bh.y);
                mma_bf16(acc[j], ah, bl.x, bl.y);
            }
        }
    }
    __syncthreads();

    int r0 = m0 + mt * 16 + (lane >> 2);
    if (MODE == 0) {
        #pragma unroll
        for (int j = 0; j < 8; j++) {
            int col = bx * 128 + (half * 8 + j) * 8 + 2 * (lane & 3);
            float b0v = bias[col], b1v = bias[col + 1];
            *(float2*)(d_z1 + (size_t)r0 * HH + col) =
                make_float2(silu_f(acc[j][0] + b0v), silu_f(acc[j][1] + b1v));
            *(float2*)(d_z1 + (size_t)(r0 + 8) * HH + col) =
                make_float2(silu_f(acc[j][2] + b0v), silu_f(acc[j][3] + b1v));
        }
    } else {
        float* sps = sm;          // reuse Af region: 4*128 + 4*128 floats
        float* spq = sm + 512;
        #pragma unroll
        for (int j = 0; j < 8; j++) {
            int cl = (half * 8 + j) * 8 + 2 * (lane & 3);
            int col = bx * 128 + cl;
            float b0v = bias[col], b1v = bias[col + 1];
            float v00 = acc[j][0] + b0v, v01 = acc[j][1] + b1v;
            float v10 = acc[j][2] + b0v, v11 = acc[j][3] + b1v;
            *(float2*)(d_z + (size_t)r0 * HH + col) = make_float2(v00, v01);
            *(float2*)(d_z + (size_t)(r0 + 8) * HH + col) = make_float2(v10, v11);
            float s0 = v00 + v10, s1 = v01 + v11;
            float q0 = v00 * v00 + v10 * v10, q1 = v01 * v01 + v11 * v11;
            #pragma unroll
            for (int off = 16; off >= 4; off >>= 1) {
                s0 += __shfl_down_sync(0xffffffffu, s0, off);
                s1 += __shfl_down_sync(0xffffffffu, s1, off);
                q0 += __shfl_down_sync(0xffffffffu, q0, off);
                q1 += __shfl_down_sync(0xffffffffu, q1, off);
            }
            if (lane < 4) {
                int c2 = (half * 8 + j) * 8 + 2 * lane;
                sps[mt * 128 + c2] = s0; sps[mt * 128 + c2 + 1] = s1;
                spq[mt * 128 + c2] = q0; spq[mt * 128 + c2 + 1] = q1;
            }
        }
        __syncthreads();
        if (t < 128) {
            float S = 0.f, Q = 0.f;
            #pragma unroll
            for (int p = 0; p < 4; p++) { S += sps[p * 128 + t]; Q += spq[p * 128 + t]; }
            d_psum[mb * HH + bx * 128 + t] = S;
            d_psumq[mb * HH + bx * 128 + t] = Q;
        }
    }
}

// ---------------- GraphNorm finalize (folds gemm1 partials) ---------------
// grid 128 blocks x 32 rows (halved per-block loop vs 64x64)
__global__ void k_gfin(const float* __restrict__ gw, const float* __restrict__ gb,
                       const float* __restrict__ gms) {
    int nb = blockIdx.x * 32;
    int g = nb >> 9;
    int c = threadIdx.x;
    float s = 0.f, q = 0.f;
    #pragma unroll
    for (int p = 0; p < 8; p++) {
        s += d_psum[(g * 8 + p) * HH + c];
        q += d_psumq[(g * 8 + p) * HH + c];
    }
    float mean = s * (1.f / 512.f);
    float ez2  = q * (1.f / 512.f);
    float mm = mean * gms[c];
    float var = ez2 - 2.f * mm * mean + mm * mm;
    float inv = 1.f / sqrtf(var + 1e-5f);
    float w = gw[c], b = gb[c];
    for (int n = 0; n < 32; n++) {
        size_t id = (size_t)(nb + n) * HH + c;
        float cc = d_z[id] - mm;
        float zn = fmaf(w * cc, inv, b);
        float hv = zn + d_h[id];
        d_h[id] = silu_f(hv);
    }
}

// ---------------- output head ----------------
__global__ void k_out(const float* __restrict__ Wout, const float* __restrict__ bout,
                      float* __restrict__ out) {
    __shared__ float sw[HH * 3];
    int t = threadIdx.x;
    for (int idx = t; idx < HH * 3; idx += 256) sw[idx] = Wout[idx];
    __syncthreads();
    int w = t >> 5, lane = t & 31;
    int i = blockIdx.x * 8 + w;
    float a0 = 0.f, a1 = 0.f, a2 = 0.f;
    for (int c = lane; c < HH; c += 32) {
        float hv = d_h[(size_t)i * HH + c];
        a0 = fmaf(hv, sw[c * 3 + 0], a0);
        a1 = fmaf(hv, sw[c * 3 + 1], a1);
        a2 = fmaf(hv, sw[c * 3 + 2], a2);
    }
    #pragma unroll
    for (int off = 16; off; off >>= 1) {
        a0 += __shfl_down_sync(0xffffffffu, a0, off);
        a1 += __shfl_down_sync(0xffffffffu, a1, off);
        a2 += __shfl_down_sync(0xffffffffu, a2, off);
    }
    if (lane == 0) {
        out[i * 3 + 0] = a0 + bout[0];
        out[i * 3 + 1] = a1 + bout[1];
        out[i * 3 + 2] = a2 + bout[2];
    }
}

// -------------------------------------------------------------------------
extern "C" void kernel_launch(void* const* d_in, const int* in_sizes, int n_in,
                              void* d_out, int out_size) {
    const float* coords = (const float*)d_in[0];
    const float* tin  = (const float*)d_in[2];
    const float* Wgfp = (const float*)d_in[3];
    const float* Wt_  = (const float*)d_in[4];
    const float* bt_  = (const float*)d_in[5];
    const float* Win  = (const float*)d_in[6];
    const float* bin  = (const float*)d_in[7];
    const float* W1   = (const float*)d_in[8];
    const float* b1   = (const float*)d_in[9];
    const float* W2   = (const float*)d_in[10];
    const float* b2   = (const float*)d_in[11];
    const float* We   = (const float*)d_in[12];
    const float* be   = (const float*)d_in[13];
    const float* eps  = (const float*)d_in[14];
    const float* gnw  = (const float*)d_in[15];
    const float* gnb  = (const float*)d_in[16];
    const float* gnms = (const float*)d_in[17];
    const float* Wtl  = (const float*)d_in[18];
    const float* btl  = (const float*)d_in[19];
    const float* Wout = (const float*)d_in[20];
    const float* bout = (const float*)d_in[21];
    float* out = (float*)d_out;

    const int smem_edge = SMEM_EDGE_WORDS * 4;   // 74752 B
    const int smem_g = SMEM_G_WORDS * 4;         // 50176 B
    cudaFuncSetAttribute(k_edge, cudaFuncAttributeMaxDynamicSharedMemorySize, smem_edge);
    cudaFuncSetAttribute(k_mgemm<0>, cudaFuncAttributeMaxDynamicSharedMemorySize, smem_g);
    cudaFuncSetAttribute(k_mgemm<1>, cudaFuncAttributeMaxDynamicSharedMemorySize, smem_g);

    k_temb<<<1, 128>>>(tin, Wgfp, Wt_, bt_);
    k_tproj<<<LL * BB, 256>>>(Wtl, btl);
    k_hin<<<NN, 256>>>(coords, Win, bin);
    k_nbr<<<NN / 4, 128>>>(coords);
    k_afrag<<<NN / 4, 256>>>(coords);
    k_befrag<<<dim3(4, LL), 256>>>(We, be);
    k_wfrag<32><<<dim3(32, LL), 256>>>(W1);
    k_wfrag<16><<<dim3(16, LL), 256>>>(W2);

    for (int l = 0; l < LL; l++) {
        k_edge<<<NN / 4, 256, smem_edge>>>(l);
        k_mgemm<0><<<dim3(2, 64), 256, smem_g>>>(b1 + l * HH, eps, l);
        k_mgemm<1><<<dim3(2, 64), 256, smem_g>>>(b2 + l * HH, eps, l);
        k_gfin<<<128, 256>>>(gnw + l * HH, gnb + l * HH, gnms + l * HH);
    }
    k_out<<<NN / 8, 256>>>(Wout, bout, out);
}

// round 16
// speedup vs baseline: 2.1133x; 1.0835x over previous
#include <cuda_runtime.h>
#include <cuda_bf16.h>
#include <math.h>

#define NN     4096
#define BB     8
#define NPG    512
#define KK     30
#define NBASIS 32
#define EDIM   35      // NBASIS + 3
#define HH     256
#define X2H    512
#define TT     128
#define LL     5
#define RADIUS 1.5f

// ---------------- static scratch (no allocations allowed) ----------------
__device__ __align__(16) float d_tfeat[BB * TT];
__device__ __align__(16) float d_tproj[LL * BB * HH];
__device__ __align__(16) float d_h[NN * HH];
__device__ __align__(16) float d_aggr[NN * X2H];
__device__ __align__(16) float d_z1[NN * HH];
__device__ __align__(16) float d_z[NN * HH];
// bf16x2-packed fragments, hi | lo
__device__ __align__(16) unsigned d_afrag[(NN / 8) * 12288];  // edge A frags per 8-node block
__device__ __align__(16) unsigned d_bfrag[LL * 4 * 6144];     // edge B frags per (layer, chunk)
__device__ __align__(16) unsigned d_w1frag[LL * 32 * 4096];   // W1 frags (hi | lo per layer)
__device__ __align__(16) unsigned d_w2frag[LL * 16 * 4096];   // W2 frags
__device__ int   d_nbr[NN * KK];
__device__ int   d_cnt[NN];
__device__ float d_elen[NN * KK];
__device__ __align__(16) float d_psum[64 * HH];   // gemm1 per-mblock col sums
__device__ __align__(16) float d_psumq[64 * HH];  // gemm1 per-mblock col sumsq

__device__ __forceinline__ float silu_f(float v) { return v / (1.f + expf(-v)); }

// ---------------- bf16 helpers ----------------
__device__ __forceinline__ unsigned pack_bf16x2(float a, float b) {
    __nv_bfloat162 h = __floats2bfloat162_rn(a, b);
    return *(unsigned*)&h;
}
__device__ __forceinline__ void mma_bf16(float* c, uint4 a, unsigned b0, unsigned b1) {
    asm volatile(
        "mma.sync.aligned.m16n8k16.row.col.f32.bf16.bf16.f32 "
        "{%0,%1,%2,%3}, {%4,%5,%6,%7}, {%8,%9}, {%0,%1,%2,%3};"
        : "+f"(c[0]), "+f"(c[1]), "+f"(c[2]), "+f"(c[3])
        : "r"(a.x), "r"(a.y), "r"(a.z), "r"(a.w), "r"(b0), "r"(b1));
}

// ---------------- time embedding ----------------
__global__ void k_temb(const float* __restrict__ tin, const float* __restrict__ wgfp,
                       const float* __restrict__ wt, const float* __restrict__ bt) {
    __shared__ float ss[64], sc[64];
    int t = threadIdx.x; // 128
    for (int b = 0; b < BB; b++) {
        if (t < 64) {
            float xp = 6.283185307179586f * tin[b] * wgfp[t];
            ss[t] = sinf(xp);
            sc[t] = cosf(xp);
        }
        __syncthreads();
        float acc = bt[t];
        #pragma unroll 8
        for (int h = 0; h < 64; h++) {
            acc = fmaf(ss[h], wt[h * TT + t], acc);
            acc = fmaf(sc[h], wt[(64 + h) * TT + t], acc);
        }
        d_tfeat[b * TT + t] = silu_f(acc);
        __syncthreads();
    }
}

__global__ void k_tproj(const float* __restrict__ Wt, const float* __restrict__ bt) {
    int l = blockIdx.x / BB, b = blockIdx.x % BB;
    int c = threadIdx.x; // 256
    __shared__ float tf[TT];
    if (c < TT) tf[c] = d_tfeat[b * TT + c];
    __syncthreads();
    float acc = bt[l * HH + c];
    const float* w = Wt + (size_t)l * TT * HH;
    #pragma unroll 8
    for (int k = 0; k < TT; k++) acc = fmaf(tf[k], w[k * HH + c], acc);
    d_tproj[(l * BB + b) * HH + c] = acc;
}

__global__ void k_hin(const float* __restrict__ coords, const float* __restrict__ Win,
                      const float* __restrict__ bin) {
    int i = blockIdx.x;
    int c = threadIdx.x;
    float x0 = coords[i * 3 + 0], x1 = coords[i * 3 + 1], x2 = coords[i * 3 + 2];
    float v = fmaf(x0, Win[c], fmaf(x1, Win[HH + c], fmaf(x2, Win[2 * HH + c], bin[c])));
    d_h[(size_t)i * HH + c] = v;
}

// ---------------- radius graph (stores selected distances too) ------------
__global__ void __launch_bounds__(128) k_nbr(const float* __restrict__ coords) {
    __shared__ float sx[NPG], sy[NPG], sz[NPG];
    __shared__ float sd[4][NPG];
    int t = threadIdx.x;
    int base = blockIdx.x * 4;
    int goff = (base >> 9) << 9;
    for (int j = t; j < NPG; j += 128) {
        sx[j] = coords[(goff + j) * 3 + 0];
        sy[j] = coords[(goff + j) * 3 + 1];
        sz[j] = coords[(goff + j) * 3 + 2];
    }
    __syncthreads();
    int w = t >> 5, lane = t & 31;
    int il = (base & 511) + w;
    int ig = goff + il;
    float xi = sx[il], yi = sy[il], zi = sz[il];
    float sqi = xi * xi + yi * yi + zi * zi;
    for (int j = lane; j < NPG; j += 32) {
        float xj = sx[j], yj = sy[j], zj = sz[j];
        float dot = xi * xj + yi * yj + zi * zj;
        float sqj = xj * xj + yj * yj + zj * zj;
        float d2 = sqi + sqj - 2.f * dot;
        float d = sqrtf(fmaxf(d2, 1e-12f));
        sd[w][j] = (j != il && d < RADIUS) ? d : INFINITY;
    }
    __syncwarp();
    int cc = 0;
    for (int k = 0; k < KK; k++) {
        float best = INFINITY;
        int bi = -1;
        for (int j = lane; j < NPG; j += 32) {
            float v = sd[w][j];
            if (v < best) { best = v; bi = j; }
        }
        #pragma unroll
        for (int off = 16; off; off >>= 1) {
            float ov = __shfl_down_sync(0xffffffffu, best, off);
            int oi = __shfl_down_sync(0xffffffffu, bi, off);
            if (ov < best || (ov == best && (unsigned)oi < (unsigned)bi)) { best = ov; bi = oi; }
        }
        best = __shfl_sync(0xffffffffu, best, 0);
        bi = __shfl_sync(0xffffffffu, bi, 0);
        if (!(best < INFINITY)) break;
        if (lane == 0) {
            d_nbr[ig * KK + k] = goff + bi;
            d_elen[ig * KK + k] = best;
            sd[w][bi] = INFINITY;
        }
        cc = k + 1;
        __syncwarp();
    }
    if (lane == 0) d_cnt[ig] = cc;
}

// ---------------- A fragments: edge attrs, 8-node blocks ------------------
__global__ void __launch_bounds__(256) k_afrag(const float* __restrict__ coords) {
    int blk = blockIdx.x;            // 512 blocks of 8 nodes
    int i0 = blk * 8;
    unsigned* outp = d_afrag + (size_t)blk * 12288;
    const float step = RADIUS / 33.f;
    const float istep = 33.f / RADIUS;
    for (int idx = threadIdx.x; idx < 6144; idx += 256) {
        int r = idx & 3;
        int lane = (idx >> 2) & 31;
        int ks = (idx >> 7) % 3;
        int mg = idx / 384;                       // 0..15
        int row = 16 * mg + 8 * (r & 1) + (lane >> 2);   // 0..255
        int kb = ks * 16 + 8 * (r >> 1) + 2 * (lane & 3);
        int n = row >> 5, k = row & 31;
        int node = i0 + n;
        float a0 = 0.f, a1 = 0.f;
        if (k < d_cnt[node] && kb < 36) {
            float el = d_elen[node * KK + k];
            if (kb < 32) {
                float d0 = (el - (float)(kb + 1) * step) * istep;
                float d1 = (el - (float)(kb + 2) * step) * istep;
                a0 = expf(-d0 * d0) * (1.f / 1.12f);
                a1 = expf(-d1 * d1) * (1.f / 1.12f);
            } else {
                int s = d_nbr[node * KK + k];
                float inv = 1.f / el;
                float ex = coords[s * 3 + 0] - coords[node * 3 + 0];
                float ey = coords[s * 3 + 1] - coords[node * 3 + 1];
                float ez = coords[s * 3 + 2] - coords[node * 3 + 2];
                if (kb == 32) { a0 = ex * inv; a1 = ey * inv; }
                else          { a0 = ez * inv; a1 = 1.0f; }   // kb == 34
            }
        }
        float h0 = __bfloat162float(__float2bfloat16_rn(a0));
        float h1 = __bfloat162float(__float2bfloat16_rn(a1));
        outp[idx]        = pack_bf16x2(h0, h1);
        outp[idx + 6144] = pack_bf16x2(a0 - h0, a1 - h1);
    }
}

// ---------------- B fragments for k_edge: We (+be as row 35) --------------
__global__ void __launch_bounds__(256) k_befrag(const float* __restrict__ We,
                                                const float* __restrict__ be) {
    int cc = blockIdx.x, l = blockIdx.y;
    const float* w = We + (size_t)l * EDIM * X2H;
    const float* bp = be + (size_t)l * X2H;
    unsigned* outp = d_bfrag + (size_t)(l * 4 + cc) * 6144;
    for (int idx = threadIdx.x; idx < 3072; idx += 256) {
        int q = idx & 3;
        int ts = q >> 1, rb = q & 1;
        int lane = (idx >> 2) & 31;
        int tp = (idx >> 7) & 7;
        int ks = idx >> 10;
        int tile = 2 * tp + ts;
        int kb = ks * 16 + 8 * rb + 2 * (lane & 3);
        int gcol = cc * 128 + tile * 8 + (lane >> 2);
        float b0 = (kb < EDIM) ? w[kb * X2H + gcol] : ((kb == 35) ? bp[gcol] : 0.f);
        int kb1 = kb + 1;
        float b1 = (kb1 < EDIM) ? w[kb1 * X2H + gcol] : ((kb1 == 35) ? bp[gcol] : 0.f);
        float h0 = __bfloat162float(__float2bfloat16_rn(b0));
        float h1 = __bfloat162float(__float2bfloat16_rn(b1));
        outp[idx]        = pack_bf16x2(h0, h1);
        outp[idx + 3072] = pack_bf16x2(b0 - h0, b1 - h1);
    }
}

// ---------------- weight fragments for MLP GEMMs (device-symbol dst) ------
template <int KS>
__global__ void __launch_bounds__(256) k_wfrag(const float* __restrict__ W) {
    int ksg = blockIdx.x, l = blockIdx.y;
    const float* wl = W + (size_t)l * KS * 16 * HH;
    unsigned* dl = ((KS == 32) ? d_w1frag : d_w2frag) + (size_t)l * KS * 4096;
    for (int idx = threadIdx.x; idx < 2048; idx += 256) {
        int ntg = idx >> 6;
        int lane = (idx >> 1) & 31;
        int tt = idx & 1;
        int kb = ksg * 16 + 8 * tt + 2 * (lane & 3);
        int col = ntg * 8 + (lane >> 2);
        float b0 = wl[(size_t)kb * HH + col];
        float b1 = wl[(size_t)(kb + 1) * HH + col];
        float h0 = __bfloat162float(__float2bfloat16_rn(b0));
        float h1 = __bfloat162float(__float2bfloat16_rn(b1));
        dl[(size_t)ksg * 2048 + idx] = pack_bf16x2(h0, h1);
        dl[(size_t)KS * 2048 + (size_t)ksg * 2048 + idx] = pack_bf16x2(b0 - h0, b1 - h1);
    }
}

// ---------------- k_edge: 8 nodes/block, warp-per-node, db B --------------
#define OFF_AF   0        // A hi|lo : 12288 words
#define OFF_BF   12288    // B double buffer: 2 x 6144 words
#define OFF_STP  24576    // 256
#define SMEM_EDGE_WORDS 24832

__global__ void __launch_bounds__(256) k_edge(int l) {
    extern __shared__ float sm[];
    unsigned* Af = (unsigned*)sm + OFF_AF;
    unsigned* Bf = (unsigned*)sm + OFF_BF;
    float* stp = sm + OFF_STP;
    __shared__ int ssrc[8][32];
    __shared__ int scnt[8];

    int t = threadIdx.x;
    int w = t >> 5, lane = t & 31;
    int i0 = blockIdx.x * 8;
    int g = i0 >> 9;

    {   // all 256 threads stage neighbor table (8 nodes x 32)
        int n = t >> 5, k = t & 31;
        int c = d_cnt[i0 + n];
        if (k == 0) scnt[n] = c;
        ssrc[n][k] = (k < c) ? d_nbr[(i0 + n) * KK + k] : (i0 + n);
    }
    stp[t] = d_tproj[(l * BB + g) * HH + t];  // t<256

    {
        const uint4* asrc = (const uint4*)(d_afrag + (size_t)blockIdx.x * 12288);
        uint4* adst = (uint4*)Af;
        for (int idx = t; idx < 3072; idx += 256) adst[idx] = asrc[idx];
    }
    __syncthreads();

    int node = w;                         // warp owns one node
    int cnt_n = scnt[node];
    int rr = lane >> 2;
    int s0 = ssrc[node][rr],      s1 = ssrc[node][rr + 8];
    int s2 = ssrc[node][rr + 16], s3 = ssrc[node][rr + 24];
    float mk0 = (rr      < cnt_n) ? 1.f : 0.f;
    float mk1 = (rr + 8  < cnt_n) ? 1.f : 0.f;
    float mk2 = (rr + 16 < cnt_n) ? 1.f : 0.f;
    float mk3 = (rr + 24 < cnt_n) ? 1.f : 0.f;
    int mg0 = 2 * node, mg1 = 2 * node + 1;

    for (int cc = 0; cc < 4; cc++) {
        unsigned* Bfc = Bf + (cc & 1) * 6144;
        {
            const uint4* bsrc = (const uint4*)(d_bfrag + (size_t)(l * 4 + cc) * 6144);
            uint4* bdst = (uint4*)Bfc;
            for (int idx = t; idx < 1536; idx += 256) bdst[idx] = bsrc[idx];
        }
        __syncthreads();

        #pragma unroll
        for (int p = 0; p < 2; p++) {     // two 64-col passes per chunk
            float acc[2][8][4];
            #pragma unroll
            for (int m = 0; m < 2; m++)
                #pragma unroll
                for (int q = 0; q < 8; q++) {
                    acc[m][q][0] = 0.f; acc[m][q][1] = 0.f;
                    acc[m][q][2] = 0.f; acc[m][q][3] = 0.f;
                }
            #pragma unroll
            for (int ks = 0; ks < 3; ks++) {
                uint4 ah0 = *(const uint4*)&Af[((mg0 * 3 + ks) * 32 + lane) * 4];
                uint4 al0 = *(const uint4*)&Af[6144 + ((mg0 * 3 + ks) * 32 + lane) * 4];
                uint4 ah1 = *(const uint4*)&Af[((mg1 * 3 + ks) * 32 + lane) * 4];
                uint4 al1 = *(const uint4*)&Af[6144 + ((mg1 * 3 + ks) * 32 + lane) * 4];
                #pragma unroll
                for (int tt = 0; tt < 4; tt++) {
                    int tp = p * 4 + tt;
                    uint4 bh = *(const uint4*)&Bfc[((ks * 8 + tp) * 32 + lane) * 4];
                    uint4 bl = *(const uint4*)&Bfc[3072 + ((ks * 8 + tp) * 32 + lane) * 4];
                    mma_bf16(acc[0][2 * tt + 0], ah0, bh.x, bh.y);
                    mma_bf16(acc[0][2 * tt + 0], al0, bh.x, bh.y);
                    mma_bf16(acc[0][2 * tt + 0], ah0, bl.x, bl.y);
                    mma_bf16(acc[0][2 * tt + 1], ah0, bh.z, bh.w);
                    mma_bf16(acc[0][2 * tt + 1], al0, bh.z, bh.w);
                    mma_bf16(acc[0][2 * tt + 1], ah0, bl.z, bl.w);
                    mma_bf16(acc[1][2 * tt + 0], ah1, bh.x, bh.y);
                    mma_bf16(acc[1][2 * tt + 0], al1, bh.x, bh.y);
                    mma_bf16(acc[1][2 * tt + 0], ah1, bl.x, bl.y);
                    mma_bf16(acc[1][2 * tt + 1], ah1, bh.z, bh.w);
                    mma_bf16(acc[1][2 * tt + 1], al1, bh.z, bh.w);
                    mma_bf16(acc[1][2 * tt + 1], ah1, bl.z, bl.w);
                }
            }

            #pragma unroll
            for (int nt = 0; nt < 8; nt++) {
                int gcol = cc * 128 + p * 64 + nt * 8 + 2 * (lane & 3);
                float2 x0, x1, x2, x3;
                if (cc < 2) {
                    x0 = *(const float2*)(d_h + (size_t)s0 * HH + gcol);
                    x1 = *(const float2*)(d_h + (size_t)s1 * HH + gcol);
                    x2 = *(const float2*)(d_h + (size_t)s2 * HH + gcol);
                    x3 = *(const float2*)(d_h + (size_t)s3 * HH + gcol);
                } else {
                    float2 tv = *(const float2*)&stp[gcol - HH];
                    x0 = tv; x1 = tv; x2 = tv; x3 = tv;
                }
                float sA = mk0 * fmaxf(acc[0][nt][0] + x0.x, 0.f);
                sA = fmaf(mk1, fmaxf(acc[0][nt][2] + x1.x, 0.f), sA);
                sA = fmaf(mk2, fmaxf(acc[1][nt][0] + x2.x, 0.f), sA);
                sA = fmaf(mk3, fmaxf(acc[1][nt][2] + x3.x, 0.f), sA);
                float sB = mk0 * fmaxf(acc[0][nt][1] + x0.y, 0.f);
                sB = fmaf(mk1, fmaxf(acc[0][nt][3] + x1.y, 0.f), sB);
                sB = fmaf(mk2, fmaxf(acc[1][nt][1] + x2.y, 0.f), sB);
                sB = fmaf(mk3, fmaxf(acc[1][nt][3] + x3.y, 0.f), sB);
                #pragma unroll
                for (int off = 16; off >= 4; off >>= 1) {
                    sA += __shfl_down_sync(0xffffffffu, sA, off);
                    sB += __shfl_down_sync(0xffffffffu, sB, off);
                }
                if (lane < 4) {
                    int gc = cc * 128 + p * 64 + nt * 8 + 2 * lane;
                    *(float2*)(d_aggr + (size_t)(i0 + node) * X2H + gc) = make_float2(sA, sB);
                }
            }
        }
        // no trailing sync: next chunk stages the OTHER B buffer; the sync
        // after that staging orders all reads of this buffer before reuse.
    }
}

// ---------------- tensor-core MLP GEMM (wide: 64 rows x 128 cols) ---------
// grid (2, 64); 8 warps = 4 m-tiles x 2 col-64-halves (8 n-tiles each).
// MODE0: z1 = silu(((1+eps)*[h|tproj] + aggr) @ W1 + b1)   K=512
// MODE1: z  = z1 @ W2 + b2 (+ GraphNorm col partials)       K=256
#define SMEM_G_WORDS 12544

template <int MODE>
__global__ void __launch_bounds__(256) k_mgemm(const float* __restrict__ bias,
                                               const float* __restrict__ epsp, int l) {
    const int KS = (MODE == 0) ? 32 : 16;
    const int NKSC = KS / 4;
    extern __shared__ float sm[];
    unsigned* Af = (unsigned*)sm;          // hi 0..2048, lo 2048..4096
    unsigned* Bf = (unsigned*)sm + 4096;   // hi 0..4096, lo 4096..8192
    float* stp = sm + 12288;               // 256
    int t = threadIdx.x;
    int w = t >> 5, lane = t & 31;
    int bx = blockIdx.x, mb = blockIdx.y;  // bx in {0,1}: 128-col half
    int m0 = mb * 64;
    int g = m0 >> 9;
    float ep = (MODE == 0) ? (1.f + epsp[l]) : 0.f;
    if (MODE == 0 && t < HH) stp[t] = d_tproj[(l * BB + g) * HH + t];
    const unsigned* wl = ((MODE == 0) ? d_w1frag : d_w2frag) + (size_t)l * KS * 4096;
    int mt = w & 3, half = w >> 2;

    float acc[8][4];
    #pragma unroll
    for (int q = 0; q < 8; q++) {
        acc[q][0] = 0.f; acc[q][1] = 0.f; acc[q][2] = 0.f; acc[q][3] = 0.f;
    }

    for (int ksc = 0; ksc < NKSC; ksc++) {
        __syncthreads();
        // stage A: bf16 hi/lo fragments with fused input epilogue
        for (int idx = t; idx < 2048; idx += 256) {
            int mtl = idx >> 9;
            int rem = idx & 511;
            int ksl = rem >> 7;
            int ln = (rem >> 2) & 31;
            int r = idx & 3;
            int row = m0 + 16 * mtl + 8 * (r & 1) + (ln >> 2);
            int kb = ksc * 64 + ksl * 16 + 8 * (r >> 1) + 2 * (ln & 3);
            float v0, v1;
            if (MODE == 0) {
                float2 ag = *(const float2*)(d_aggr + (size_t)row * X2H + kb);
                float2 hx;
                if (kb < HH) hx = *(const float2*)(d_h + (size_t)row * HH + kb);
                else         hx = *(const float2*)&stp[kb - HH];
                v0 = fmaf(ep, hx.x, ag.x);
                v1 = fmaf(ep, hx.y, ag.y);
            } else {
                float2 zz = *(const float2*)(d_z1 + (size_t)row * HH + kb);
                v0 = zz.x; v1 = zz.y;
            }
            float h0 = __bfloat162float(__float2bfloat16_rn(v0));
            float h1 = __bfloat162float(__float2bfloat16_rn(v1));
            Af[idx]        = pack_bf16x2(h0, h1);
            Af[idx + 2048] = pack_bf16x2(v0 - h0, v1 - h1);
        }
        // stage B: 128-col slice of precomputed weight fragments (1 uint4/thr/region)
        #pragma unroll
        for (int ks4 = 0; ks4 < 4; ks4++) {
            int ksg = ksc * 4 + ks4;
            const uint4* sh = (const uint4*)(wl + (size_t)ksg * 2048 + bx * 1024);
            const uint4* sl = (const uint4*)(wl + (size_t)KS * 2048 +
                                             (size_t)ksg * 2048 + bx * 1024);
            ((uint4*)(Bf + ks4 * 1024))[t] = sh[t];
            ((uint4*)(Bf + 4096 + ks4 * 1024))[t] = sl[t];
        }
        __syncthreads();
        #pragma unroll
        for (int ks = 0; ks < 4; ks++) {
            uint4 ah = *(const uint4*)&Af[((mt * 4 + ks) * 32 + lane) * 4];
            uint4 al = *(const uint4*)&Af[2048 + ((mt * 4 + ks) * 32 + lane) * 4];
            #pragma unroll
            for (int j = 0; j < 8; j++) {
                int ntl = half * 8 + j;
                uint2 bh = *(const uint2*)&Bf[ks * 1024 + ntl * 64 + lane * 2];
                uint2 bl = *(const uint2*)&Bf[4096 + ks * 1024 + ntl * 64 + lane * 2];
                mma_bf16(acc[j], ah, bh.x, bh.y);
                mma_bf16(acc[j], al, bh.x, bh.y);
                mma_bf16(acc[j], ah, bl.x, bl.y);
            }
        }
    }
    __syncthreads();

    int r0 = m0 + mt * 16 + (lane >> 2);
    if (MODE == 0) {
        #pragma unroll
        for (int j = 0; j < 8; j++) {
            int col = bx * 128 + (half * 8 + j) * 8 + 2 * (lane & 3);
            float b0v = bias[col], b1v = bias[col + 1];
            *(float2*)(d_z1 + (size_t)r0 * HH + col) =
                make_float2(silu_f(acc[j][0] + b0v), silu_f(acc[j][1] + b1v));
            *(float2*)(d_z1 + (size_t)(r0 + 8) * HH + col) =
                make_float2(silu_f(acc[j][2] + b0v), silu_f(acc[j][3] + b1v));
        }
    } else {
        float* sps = sm;          // reuse Af region: 4*128 + 4*128 floats
        float* spq = sm + 512;
        #pragma unroll
        for (int j = 0; j < 8; j++) {
            int cl = (half * 8 + j) * 8 + 2 * (lane & 3);
            int col = bx * 128 + cl;
            float b0v = bias[col], b1v = bias[col + 1];
            float v00 = acc[j][0] + b0v, v01 = acc[j][1] + b1v;
            float v10 = acc[j][2] + b0v, v11 = acc[j][3] + b1v;
            *(float2*)(d_z + (size_t)r0 * HH + col) = make_float2(v00, v01);
            *(float2*)(d_z + (size_t)(r0 + 8) * HH + col) = make_float2(v10, v11);
            float s0 = v00 + v10, s1 = v01 + v11;
            float q0 = v00 * v00 + v10 * v10, q1 = v01 * v01 + v11 * v11;
            #pragma unroll
            for (int off = 16; off >= 4; off >>= 1) {
                s0 += __shfl_down_sync(0xffffffffu, s0, off);
                s1 += __shfl_down_sync(0xffffffffu, s1, off);
                q0 += __shfl_down_sync(0xffffffffu, q0, off);
                q1 += __shfl_down_sync(0xffffffffu, q1, off);
            }
            if (lane < 4) {
                int c2 = (half * 8 + j) * 8 + 2 * lane;
                sps[mt * 128 + c2] = s0; sps[mt * 128 + c2 + 1] = s1;
                spq[mt * 128 + c2] = q0; spq[mt * 128 + c2 + 1] = q1;
            }
        }
        __syncthreads();
        if (t < 128) {
            float S = 0.f, Q = 0.f;
            #pragma unroll
            for (int p = 0; p < 4; p++) { S += sps[p * 128 + t]; Q += spq[p * 128 + t]; }
            d_psum[mb * HH + bx * 128 + t] = S;
            d_psumq[mb * HH + bx * 128 + t] = Q;
        }
    }
}

// ---------------- GraphNorm finalize (folds gemm1 partials) ---------------
// grid 128 blocks x 32 rows
__global__ void k_gfin(const float* __restrict__ gw, const float* __restrict__ gb,
                       const float* __restrict__ gms) {
    int nb = blockIdx.x * 32;
    int g = nb >> 9;
    int c = threadIdx.x;
    float s = 0.f, q = 0.f;
    #pragma unroll
    for (int p = 0; p < 8; p++) {
        s += d_psum[(g * 8 + p) * HH + c];
        q += d_psumq[(g * 8 + p) * HH + c];
    }
    float mean = s * (1.f / 512.f);
    float ez2  = q * (1.f / 512.f);
    float mm = mean * gms[c];
    float var = ez2 - 2.f * mm * mean + mm * mm;
    float inv = 1.f / sqrtf(var + 1e-5f);
    float w = gw[c], b = gb[c];
    for (int n = 0; n < 32; n++) {
        size_t id = (size_t)(nb + n) * HH + c;
        float cc = d_z[id] - mm;
        float zn = fmaf(w * cc, inv, b);
        float hv = zn + d_h[id];
        d_h[id] = silu_f(hv);
    }
}

// ---------------- output head ----------------
__global__ void k_out(const float* __restrict__ Wout, const float* __restrict__ bout,
                      float* __restrict__ out) {
    __shared__ float sw[HH * 3];
    int t = threadIdx.x;
    for (int idx = t; idx < HH * 3; idx += 256) sw[idx] = Wout[idx];
    __syncthreads();
    int w = t >> 5, lane = t & 31;
    int i = blockIdx.x * 8 + w;
    float a0 = 0.f, a1 = 0.f, a2 = 0.f;
    for (int c = lane; c < HH; c += 32) {
        float hv = d_h[(size_t)i * HH + c];
        a0 = fmaf(hv, sw[c * 3 + 0], a0);
        a1 = fmaf(hv, sw[c * 3 + 1], a1);
        a2 = fmaf(hv, sw[c * 3 + 2], a2);
    }
    #pragma unroll
    for (int off = 16; off; off >>= 1) {
        a0 += __shfl_down_sync(0xffffffffu, a0, off);
        a1 += __shfl_down_sync(0xffffffffu, a1, off);
        a2 += __shfl_down_sync(0xffffffffu, a2, off);
    }
    if (lane == 0) {
        out[i * 3 + 0] = a0 + bout[0];
        out[i * 3 + 1] = a1 + bout[1];
        out[i * 3 + 2] = a2 + bout[2];
    }
}

// -------------------------------------------------------------------------
extern "C" void kernel_launch(void* const* d_in, const int* in_sizes, int n_in,
                              void* d_out, int out_size) {
    const float* coords = (const float*)d_in[0];
    const float* tin  = (const float*)d_in[2];
    const float* Wgfp = (const float*)d_in[3];
    const float* Wt_  = (const float*)d_in[4];
    const float* bt_  = (const float*)d_in[5];
    const float* Win  = (const float*)d_in[6];
    const float* bin  = (const float*)d_in[7];
    const float* W1   = (const float*)d_in[8];
    const float* b1   = (const float*)d_in[9];
    const float* W2   = (const float*)d_in[10];
    const float* b2   = (const float*)d_in[11];
    const float* We   = (const float*)d_in[12];
    const float* be   = (const float*)d_in[13];
    const float* eps  = (const float*)d_in[14];
    const float* gnw  = (const float*)d_in[15];
    const float* gnb  = (const float*)d_in[16];
    const float* gnms = (const float*)d_in[17];
    const float* Wtl  = (const float*)d_in[18];
    const float* btl  = (const float*)d_in[19];
    const float* Wout = (const float*)d_in[20];
    const float* bout = (const float*)d_in[21];
    float* out = (float*)d_out;

    const int smem_edge = SMEM_EDGE_WORDS * 4;   // 99328 B
    const int smem_g = SMEM_G_WORDS * 4;         // 50176 B
    cudaFuncSetAttribute(k_edge, cudaFuncAttributeMaxDynamicSharedMemorySize, smem_edge);
    cudaFuncSetAttribute(k_mgemm<0>, cudaFuncAttributeMaxDynamicSharedMemorySize, smem_g);
    cudaFuncSetAttribute(k_mgemm<1>, cudaFuncAttributeMaxDynamicSharedMemorySize, smem_g);

    k_temb<<<1, 128>>>(tin, Wgfp, Wt_, bt_);
    k_tproj<<<LL * BB, 256>>>(Wtl, btl);
    k_hin<<<NN, 256>>>(coords, Win, bin);
    k_nbr<<<NN / 4, 128>>>(coords);
    k_afrag<<<NN / 8, 256>>>(coords);
    k_befrag<<<dim3(4, LL), 256>>>(We, be);
    k_wfrag<32><<<dim3(32, LL), 256>>>(W1);
    k_wfrag<16><<<dim3(16, LL), 256>>>(W2);

    for (int l = 0; l < LL; l++) {
        k_edge<<<NN / 8, 256, smem_edge>>>(l);
        k_mgemm<0><<<dim3(2, 64), 256, smem_g>>>(b1 + l * HH, eps, l);
        k_mgemm<1><<<dim3(2, 64), 256, smem_g>>>(b2 + l * HH, eps, l);
        k_gfin<<<128, 256>>>(gnw + l * HH, gnb + l * HH, gnms + l * HH);
    }
    k_out<<<NN / 8, 256>>>(Wout, bout, out);
}